// round 12
// baseline (speedup 1.0000x reference)
#include <cuda_runtime.h>
#include <cuda_fp16.h>
#include <math.h>

#define HW 16384   // 128*128
#define APITCH 144
#define APX (144*144)
#define XP 136
#define XPX (136*136)

// ---------------- scratch (device globals; no allocation allowed) ----------
static __device__ float g_out1[2*25*8*HW];
static __device__ float g_z[2*8*HW];
static __device__ float g_y[8*2*25*HW];
static __device__ float g_h  [2*25*HW];
static __device__ float g_ns1[2*25*HW];
static __device__ float g_c1 [2*25*HW];
static __device__ float g_c2 [2*25*HW];
static __device__ float g_bpart[3][25][8][2];
static __device__ float g_cpart[2][25][128][2];
static __device__ float g_part[128*2];

// fp16 activation records (conv15): [n][apix] * 4 uint4
static __device__ uint4 g_hg[2*APX*4];
static __device__ uint4 g_ns[2*APX*4];
// fp16 weights, plane-packed B-fragment layout (conv15)
static __device__ uint4 g_wb[2][28800];
// conv00 records: [n][d][136*136] * 4 uint4, K slots = kd*3+ci (21 used)
static __device__ uint4 g_xr[16*XPX*4];
// conv00 weights: 49 taps x 128 uint4
static __device__ uint4 g_wb00[49*128];

// ---------------- FFMA-only transcendentals (no MUFU) ----------------------
__device__ __forceinline__ float recip_1to2(float v) {
    // 1/v for v in [1,2]; Newton from linear init 24/17 - 8/17*v (err <= 1/17)
    float r = fmaf(-0.470588235f, v, 1.411764706f);
    r = r * fmaf(-v, r, 2.0f);
    r = r * fmaf(-v, r, 2.0f);
    r = r * fmaf(-v, r, 2.0f);
    return r;
}
__device__ __forceinline__ float exp_neg(float t) {
    // e^t for t <= 0
    float z = t * 1.44269504f;
    z = fmaxf(z, -126.0f);
    float n = rintf(z);
    float f = z - n;                  // [-0.5, 0.5]
    float p = 1.5403530e-4f;          // Taylor of 2^f: (ln2)^k/k!
    p = fmaf(p, f, 1.3333558e-3f);
    p = fmaf(p, f, 9.6181291e-3f);
    p = fmaf(p, f, 5.5504109e-2f);
    p = fmaf(p, f, 2.4022651e-1f);
    p = fmaf(p, f, 6.9314718e-1f);
    p = fmaf(p, f, 1.0f);
    return p * __int_as_float(((int)n + 127) << 23);
}
__device__ __forceinline__ float log1p_01(float u) {
    // log(1+u) for u in [0,1]: s = u/(1+u) in [0,0.5]; -log(1-s) series deg 13
    float s = u * recip_1to2(1.0f + u);
    float p = 0.076923077f;           // 1/13
    p = fmaf(p, s, 0.083333333f);
    p = fmaf(p, s, 0.090909091f);
    p = fmaf(p, s, 0.1f);
    p = fmaf(p, s, 0.111111111f);
    p = fmaf(p, s, 0.125f);
    p = fmaf(p, s, 0.142857143f);
    p = fmaf(p, s, 0.166666667f);
    p = fmaf(p, s, 0.2f);
    p = fmaf(p, s, 0.25f);
    p = fmaf(p, s, 0.333333333f);
    p = fmaf(p, s, 0.5f);
    p = fmaf(p, s, 1.0f);
    return p * s;
}
__device__ __forceinline__ float softplusf(float x) {
    float e = exp_neg(-fabsf(x));
    return fmaxf(x, 0.f) + log1p_01(e);
}
__device__ __forceinline__ float sigmoidf_(float x) {
    float e = exp_neg(-fabsf(x));
    float r = recip_1to2(1.0f + e);
    return x >= 0.f ? r : e * r;
}
__device__ __forceinline__ unsigned s2u(const void* p) {
    return (unsigned)__cvta_generic_to_shared(p);
}
__device__ __forceinline__ void ldm4(unsigned* r, unsigned addr) {
    asm volatile("ldmatrix.sync.aligned.m8n8.x4.shared.b16 {%0,%1,%2,%3}, [%4];"
                 : "=r"(r[0]), "=r"(r[1]), "=r"(r[2]), "=r"(r[3]) : "r"(addr));
}
__device__ __forceinline__ void mma16816(float* d, const unsigned* a, unsigned b0, unsigned b1) {
    asm volatile("mma.sync.aligned.m16n8k16.row.col.f32.f16.f16.f32 "
                 "{%0,%1,%2,%3}, {%4,%5,%6,%7}, {%8,%9}, {%0,%1,%2,%3};"
                 : "+f"(d[0]), "+f"(d[1]), "+f"(d[2]), "+f"(d[3])
                 : "r"(a[0]), "r"(a[1]), "r"(a[2]), "r"(a[3]), "r"(b0), "r"(b1));
}
__device__ __forceinline__ void cpa16(uint4* dst_smem, const uint4* src) {
    asm volatile("cp.async.cg.shared.global [%0], [%1], 16;"
                 :: "r"(s2u(dst_smem)), "l"(src));
}
#define CP_COMMIT() asm volatile("cp.async.commit_group;" ::: "memory")
#define CP_WAIT0()  asm volatile("cp.async.wait_group 0;" ::: "memory")
__device__ __forceinline__ unsigned short hbits(float v) {
    __half h = __float2half(v);
    return *reinterpret_cast<unsigned short*>(&h);
}

__device__ __forceinline__ void bn_finalize(int phase, int c, float* m_out, float* rs_out) {
    float s = 0.f, q = 0.f;
#pragma unroll
    for (int i = 0; i < 8; i++) {
        s += g_bpart[phase][c][i][0];
        q += g_bpart[phase][c][i][1];
    }
    float m = s * (1.f / 32768.f);
    *m_out = m;
    *rs_out = rsqrtf(q * (1.f / 32768.f) - m * m + 1e-3f);
}

__device__ __forceinline__ void bn_finalize_c(int phase, int c, float* m_out, float* rs_out) {
    float s = 0.f, q = 0.f;
#pragma unroll 8
    for (int i = 0; i < 128; i++) {
        s += g_cpart[phase][c][i][0];
        q += g_cpart[phase][c][i][1];
    }
    float m = s * (1.f / 32768.f);
    *m_out = m;
    *rs_out = rsqrtf(q * (1.f / 32768.f) - m * m + 1e-3f);
}

// ---------------------------------------------------------------------------
// conv00 record builder
// ---------------------------------------------------------------------------
__global__ void k_xrec(const float* __restrict__ x) {
    int idx = blockIdx.x * 256 + threadIdx.x;
    if (idx >= 2 * 8 * 134 * 134) return;
    int rx = idx % 134; int t = idx / 134;
    int ry = t % 134; t /= 134;
    int d = t & 7, n = t >> 3;
    int py = ry - 3, px = rx - 3;
    bool inb = ((unsigned)py < 128u) && ((unsigned)px < 128u);

    unsigned rh[16];
#pragma unroll
    for (int i = 0; i < 16; i++) rh[i] = 0u;
    if (inb) {
#pragma unroll
        for (int kd = 0; kd < 7; kd++) {
            int dd = d + kd - 3;
            if ((unsigned)dd < 8u) {
#pragma unroll
                for (int ci = 0; ci < 3; ci++) {
                    float v = x[(size_t)((n * 3 + ci) * 8 + dd) * HW + py * 128 + px];
                    int slot = kd * 3 + ci;
                    rh[slot >> 1] |= (unsigned)hbits(v) << ((slot & 1) * 16);
                }
            }
        }
    }
    size_t ab = ((size_t)(n * 8 + d) * XPX + ry * XP + rx) * 4;
#pragma unroll
    for (int j = 0; j < 4; j++)
        g_xr[ab + j] = make_uint4(rh[4*j], rh[4*j+1], rh[4*j+2], rh[4*j+3]);
}

// ---------------------------------------------------------------------------
// conv00 weight preconvert
// ---------------------------------------------------------------------------
__global__ void k_wconv00(const float* __restrict__ w) {
    const int tap = blockIdx.x;
    const int tid = threadIdx.x;
    const int s = tid >> 7, lane = (tid >> 2) & 31, nt = tid & 3;
    const int oc = nt * 8 + (lane >> 2);
    const int cb = s * 16 + 2 * (lane & 3);
    const int slots[4] = {cb, cb + 1, cb + 8, cb + 9};
    ushort4 hrec;
    unsigned short* hp = (unsigned short*)&hrec;
#pragma unroll
    for (int j = 0; j < 4; j++) {
        float v = 0.f;
        int slot = slots[j];
        if (oc < 25 && slot < 21) {
            int kd = slot / 3, ci = slot % 3;
            v = w[((oc * 3 + ci) * 7 + kd) * 49 + tap];
        }
        hp[j] = hbits(v);
    }
    size_t rec = (((size_t)(tap * 2 + s) * 2 + (nt >> 1)) * 32 + lane) * 2 + (nt & 1);
    ((ushort4*)g_wb00)[rec] = hrec;
}

// ---------------------------------------------------------------------------
// conv00 via mma.sync fp16. grid (4,16,16), 256 thr.
// ---------------------------------------------------------------------------
#define CONV00_SMEM 50560
__global__ __launch_bounds__(256) void k_conv00t() {
    extern __shared__ __align__(128) char smem[];
    uint4* sA = (uint4*)smem;
    uint4* sW = (uint4*)(smem + 21888);

    const int n = blockIdx.z >> 3, d = blockIdx.z & 7;
    const int x0 = blockIdx.x * 32, y0 = blockIdx.y * 8;
    const int tid = threadIdx.x, warp = tid >> 5, lane = tid & 31;

    const uint4* __restrict__ ga = g_xr + (size_t)(n * 8 + d) * XPX * 4;
    const uint4* __restrict__ gw = g_wb00;

    float acc[2][4][4];
#pragma unroll
    for (int h = 0; h < 2; h++)
#pragma unroll
        for (int nt = 0; nt < 4; nt++)
#pragma unroll
            for (int j = 0; j < 4; j++) acc[h][nt][j] = 0.f;

    const int lm = lane & 15, lk = lane >> 4;
    const unsigned aB = s2u(sA);

    for (int i = tid; i < 8 * 152; i += 256) {
        int r = i / 152, j = i % 152;
        int px = j >> 2, part = j & 3;
        int rec = r * 38 + px;
        int pos = (part + (rec >> 1)) & 3;
        cpa16(sA + rec * 4 + pos, ga + ((size_t)(y0 + r) * XP + x0 + px) * 4 + part);
    }
    for (int i = tid; i < 896; i += 256) cpa16(sW + i, gw + i);
    CP_COMMIT();

    for (int ky = 0; ky < 7; ky++) {
        CP_WAIT0();
        __syncthreads();
        if (ky < 6) {
            const int rel = ky + 8, slot = rel % 9;
            for (int i = tid; i < 152; i += 256) {
                int px = i >> 2, part = i & 3;
                int rec = slot * 38 + px;
                int pos = (part + (rec >> 1)) & 3;
                cpa16(sA + rec * 4 + pos, ga + ((size_t)(y0 + rel) * XP + x0 + px) * 4 + part);
            }
            uint4* wd = sW + ((ky + 1) & 1) * 896;
            for (int i = tid; i < 896; i += 256)
                cpa16(wd + i, gw + (ky + 1) * 896 + i);
            CP_COMMIT();
        }

        const uint4* sWb = sW + (ky & 1) * 896;
        const int rs = ((warp + ky) % 9) * 38;
#pragma unroll 1
        for (int kx = 0; kx < 7; kx++) {
            const int rec0 = rs + lm + kx, rec1 = rec0 + 16;
#pragma unroll
            for (int s = 0; s < 2; s++) {
                const int qbase = s * 2 + lk;
                unsigned a0 = aB + rec0 * 64 + (((qbase + (rec0 >> 1)) & 3) << 4);
                unsigned a1 = aB + rec1 * 64 + (((qbase + (rec1 >> 1)) & 3) << 4);
                unsigned f0[4], f1[4];
                ldm4(f0, a0);
                ldm4(f1, a1);
                const int wi = (kx * 2 + s) * 64 + lane;
                uint4 h01 = sWb[wi], h23 = sWb[wi + 32];
                mma16816(acc[0][0], f0, h01.x, h01.y);
                mma16816(acc[0][1], f0, h01.z, h01.w);
                mma16816(acc[0][2], f0, h23.x, h23.y);
                mma16816(acc[0][3], f0, h23.z, h23.w);
                mma16816(acc[1][0], f1, h01.x, h01.y);
                mma16816(acc[1][1], f1, h01.z, h01.w);
                mma16816(acc[1][2], f1, h23.x, h23.y);
                mma16816(acc[1][3], f1, h23.z, h23.w);
            }
        }
    }

    const int y = y0 + warp;
#pragma unroll
    for (int h = 0; h < 2; h++) {
#pragma unroll
        for (int nt = 0; nt < 4; nt++) {
            int oc = nt * 8 + (lane & 3) * 2;
            int xb = x0 + h * 16 + (lane >> 2);
            if (oc < 25) {
                size_t ob = (size_t)((n * 25 + oc) * 8 + d) * HW + y * 128;
                g_out1[ob + xb]     = acc[h][nt][0];
                g_out1[ob + xb + 8] = acc[h][nt][2];
            }
            if (oc + 1 < 25) {
                size_t ob = (size_t)((n * 25 + oc + 1) * 8 + d) * HW + y * 128;
                g_out1[ob + xb]     = acc[h][nt][1];
                g_out1[ob + xb + 8] = acc[h][nt][3];
            }
        }
    }
}

// ---------------------------------------------------------------------------
// conv0 (scalar)
// ---------------------------------------------------------------------------
__global__ __launch_bounds__(256) void k_conv0(const float* __restrict__ w) {
    const int n = blockIdx.z >> 3, d = blockIdx.z & 7;
    const int x0 = blockIdx.x * 64, y0 = blockIdx.y * 16;
    const int tx = threadIdx.x & 15, ty = threadIdx.x >> 4;

    __shared__ __align__(16) float s_in[22 * 72];
    __shared__ __align__(16) float s_w[7 * 8];

    float acc[4] = {0.f, 0.f, 0.f, 0.f};

    const int id_lo = (d - 3 < 0) ? 0 : d - 3;
    const int id_hi = (d + 3 > 7) ? 7 : d + 3;

    for (int mid = 0; mid < 25; mid++) {
        for (int id = id_lo; id <= id_hi; id++) {
            const int kd = id - d + 3;
            __syncthreads();
            const float* src = g_out1 + (size_t)((n * 25 + mid) * 8 + id) * HW;
            for (int t = threadIdx.x; t < 22 * 70; t += 256) {
                int r = t / 70, c2 = t % 70;
                int gy = y0 - 3 + r, gx = x0 - 3 + c2;
                float v = 0.f;
                if ((unsigned)gy < 128u && (unsigned)gx < 128u) v = src[gy * 128 + gx];
                s_in[r * 72 + c2] = v;
            }
            for (int t = threadIdx.x; t < 49; t += 256) {
                s_w[(t / 7) * 8 + (t % 7)] = w[(mid * 7 + kd) * 49 + t];
            }
            __syncthreads();
#pragma unroll 1
            for (int ky = 0; ky < 7; ky++) {
                const int base = (ty + ky) * 72 + tx * 4;
                float r[12];
                float4 a = *(const float4*)&s_in[base];
                float4 b = *(const float4*)&s_in[base + 4];
                float4 c = *(const float4*)&s_in[base + 8];
                r[0]=a.x; r[1]=a.y; r[2]=a.z; r[3]=a.w;
                r[4]=b.x; r[5]=b.y; r[6]=b.z; r[7]=b.w;
                r[8]=c.x; r[9]=c.y; r[10]=c.z; r[11]=c.w;
                float4 w0 = *(const float4*)&s_w[ky * 8];
                float4 w1 = *(const float4*)&s_w[ky * 8 + 4];
                float wv[8] = {w0.x, w0.y, w0.z, w0.w, w1.x, w1.y, w1.z, w1.w};
#pragma unroll
                for (int kx = 0; kx < 7; kx++) {
#pragma unroll
                    for (int j = 0; j < 4; j++)
                        acc[j] = fmaf(r[kx + j], wv[kx], acc[j]);
                }
            }
        }
    }
    float* dst = g_z + (size_t)(n * 8 + d) * HW + (y0 + ty) * 128 + x0 + tx * 4;
#pragma unroll
    for (int j = 0; j < 4; j++) dst[j] = acc[j];
}

// ---------------------------------------------------------------------------
// conv1 + bias + square -> g_y
// ---------------------------------------------------------------------------
__global__ __launch_bounds__(256) void k_conv1sq(const float* __restrict__ w,
                                                 const float* __restrict__ bias) {
    const int n = blockIdx.z >> 3, d = blockIdx.z & 7;
    const int x0 = blockIdx.x * 32, y0 = blockIdx.y * 16;
    const int tx = threadIdx.x & 15, ty = threadIdx.x >> 4;

    __shared__ float s_in[22 * 40];
    __shared__ __align__(16) float s_w[49 * 28];

    float acc[25][2];
#pragma unroll
    for (int c = 0; c < 25; c++) { acc[c][0] = 0.f; acc[c][1] = 0.f; }

    const int id_lo = (d - 3 < 0) ? 0 : d - 3;
    const int id_hi = (d + 3 > 7) ? 7 : d + 3;

    for (int id = id_lo; id <= id_hi; id++) {
        const int kd = id - d + 3;
        __syncthreads();
        const float* src = g_z + (size_t)(n * 8 + id) * HW;
        for (int t = threadIdx.x; t < 22 * 38; t += 256) {
            int r = t / 38, c2 = t % 38;
            int gy = y0 - 3 + r, gx = x0 - 3 + c2;
            float v = 0.f;
            if ((unsigned)gy < 128u && (unsigned)gx < 128u) v = src[gy * 128 + gx];
            s_in[r * 40 + c2] = v;
        }
        for (int t = threadIdx.x; t < 49 * 25; t += 256) {
            int tap = t / 25, oc = t % 25;
            s_w[tap * 28 + oc] = w[(oc * 7 + kd) * 49 + tap];
        }
        __syncthreads();
#pragma unroll 1
        for (int ky = 0; ky < 7; ky++) {
#pragma unroll
            for (int kx = 0; kx < 7; kx++) {
                float a0 = s_in[(ty + ky) * 40 + tx * 2 + kx];
                float a1 = s_in[(ty + ky) * 40 + tx * 2 + kx + 1];
                const float4* W = (const float4*)&s_w[(ky * 7 + kx) * 28];
                float wv[28];
#pragma unroll
                for (int q = 0; q < 7; q++) {
                    float4 f = W[q];
                    wv[4*q] = f.x; wv[4*q+1] = f.y; wv[4*q+2] = f.z; wv[4*q+3] = f.w;
                }
#pragma unroll
                for (int oc = 0; oc < 25; oc++) {
                    acc[oc][0] = fmaf(a0, wv[oc], acc[oc][0]);
                    acc[oc][1] = fmaf(a1, wv[oc], acc[oc][1]);
                }
            }
        }
    }
    const int yy = y0 + ty, xx = x0 + tx * 2;
#pragma unroll
    for (int oc = 0; oc < 25; oc++) {
        float b = bias[oc];
        float v0 = acc[oc][0] + b;
        float v1 = acc[oc][1] + b;
        float* dst = g_y + (size_t)((d * 2 + n) * 25 + oc) * HW + yy * 128 + xx;
        dst[0] = v0 * v0;
        dst[1] = v1 * v1;
    }
}

// ---------------------------------------------------------------------------
// conv15 weight preconvert
// ---------------------------------------------------------------------------
__global__ void k_wconv(const float* __restrict__ w_inh, const float* __restrict__ w_exc) {
    const int tap = blockIdx.x, pair = blockIdx.y;
    const float* w = pair ? w_exc : w_inh;
    const int tid = threadIdx.x;
    const int s = tid >> 7, lane = (tid >> 2) & 31, nt = tid & 3;
    const int oc = nt * 8 + (lane >> 2);
    const int cb = s * 16 + 2 * (lane & 3);
    const int cis[4] = {cb, cb + 1, cb + 8, cb + 9};
    ushort4 hrec;
    unsigned short* hp = (unsigned short*)&hrec;
#pragma unroll
    for (int j = 0; j < 4; j++) {
        float v = 0.f;
        int ci = cis[j];
        if (oc < 25 && ci < 25) v = w[(oc * 25 + ci) * 225 + tap];
        hp[j] = hbits(v);
    }
    size_t rec = (((size_t)(tap * 2 + s) * 2 + (nt >> 1)) * 32 + lane) * 2 + (nt & 1);
    ((ushort4*)g_wb[pair])[rec] = hrec;
}

// ---------------------------------------------------------------------------
// conv15 via mma.sync fp16, cp.async pipelined. grid (4,16,2), 256 thr.
// ---------------------------------------------------------------------------
#define CONV15_SMEM 87936
__global__ __launch_bounds__(256) void k_conv15(int phase) {
    extern __shared__ __align__(128) char smem[];
    uint4* sA = (uint4*)smem;
    uint4* sW = (uint4*)(smem + 26496);

    const int n = blockIdx.z;
    const int x0 = blockIdx.x * 32, y0 = blockIdx.y * 8;
    const int tid = threadIdx.x, warp = tid >> 5, lane = tid & 31;

    const uint4* __restrict__ ga = (phase ? g_ns : g_hg) + (size_t)n * APX * 4;
    const uint4* __restrict__ gw = g_wb[phase];
    float* __restrict__ out = phase ? g_c2 : g_c1;

    float acc[2][4][4];
#pragma unroll
    for (int h = 0; h < 2; h++)
#pragma unroll
        for (int nt = 0; nt < 4; nt++)
#pragma unroll
            for (int j = 0; j < 4; j++) acc[h][nt][j] = 0.f;

    const int lm = lane & 15, lk = lane >> 4;
    const unsigned aB = s2u(sA);

    for (int i = tid; i < 8 * 184; i += 256) {
        int r = i / 184, j = i % 184;
        int px = j >> 2, part = j & 3;
        int rec = r * 46 + px;
        int pos = (part + (rec >> 1)) & 3;
        cpa16(sA + rec * 4 + pos, ga + ((size_t)(y0 + r) * APITCH + x0 + px) * 4 + part);
    }
    for (int i = tid; i < 1920; i += 256) cpa16(sW + i, gw + i);
    CP_COMMIT();

    for (int ky = 0; ky < 15; ky++) {
        CP_WAIT0();
        __syncthreads();

        if (ky < 14) {
            const int rel = ky + 8, slot = rel % 9;
            for (int i = tid; i < 184; i += 256) {
                int px = i >> 2, part = i & 3;
                int rec = slot * 46 + px;
                int pos = (part + (rec >> 1)) & 3;
                cpa16(sA + rec * 4 + pos, ga + ((size_t)(y0 + rel) * APITCH + x0 + px) * 4 + part);
            }
            uint4* wd = sW + ((ky + 1) & 1) * 1920;
            for (int i = tid; i < 1920; i += 256)
                cpa16(wd + i, gw + (ky + 1) * 1920 + i);
            CP_COMMIT();
        }

        const uint4* sWb = sW + (ky & 1) * 1920;
        const int rs = ((warp + ky) % 9) * 46;
#pragma unroll 3
        for (int kx = 0; kx < 15; kx++) {
            const int rec0 = rs + lm + kx, rec1 = rec0 + 16;
#pragma unroll
            for (int s = 0; s < 2; s++) {
                const int qbase = s * 2 + lk;
                unsigned a0 = aB + rec0 * 64 + (((qbase + (rec0 >> 1)) & 3) << 4);
                unsigned a1 = aB + rec1 * 64 + (((qbase + (rec1 >> 1)) & 3) << 4);
                unsigned f0[4], f1[4];
                ldm4(f0, a0);
                ldm4(f1, a1);
                const int wi = (kx * 2 + s) * 64 + lane;
                uint4 h01 = sWb[wi], h23 = sWb[wi + 32];
                mma16816(acc[0][0], f0, h01.x, h01.y);
                mma16816(acc[0][1], f0, h01.z, h01.w);
                mma16816(acc[0][2], f0, h23.x, h23.y);
                mma16816(acc[0][3], f0, h23.z, h23.w);
                mma16816(acc[1][0], f1, h01.x, h01.y);
                mma16816(acc[1][1], f1, h01.z, h01.w);
                mma16816(acc[1][2], f1, h23.x, h23.y);
                mma16816(acc[1][3], f1, h23.z, h23.w);
            }
        }
    }

    const int y = y0 + warp;
#pragma unroll
    for (int h = 0; h < 2; h++) {
#pragma unroll
        for (int nt = 0; nt < 4; nt++) {
            int oc = nt * 8 + (lane & 3) * 2;
            int xb = x0 + h * 16 + (lane >> 2);
            if (oc < 25) {
                size_t ob = (size_t)(n * 25 + oc) * HW + y * 128;
                out[ob + xb]     = acc[h][nt][0];
                out[ob + xb + 8] = acc[h][nt][2];
            }
            if (oc + 1 < 25) {
                size_t ob = (size_t)(n * 25 + oc + 1) * HW + y * 128;
                out[ob + xb]     = acc[h][nt][1];
                out[ob + xb + 8] = acc[h][nt][3];
            }
        }
    }

    __syncthreads();
    float* sred = (float*)smem;
#pragma unroll
    for (int nt = 0; nt < 4; nt++) {
        float s0 = 0.f, q0 = 0.f, s1 = 0.f, q1 = 0.f;
#pragma unroll
        for (int h = 0; h < 2; h++) {
            float v;
            v = acc[h][nt][0]; s0 += v; q0 = fmaf(v, v, q0);
            v = acc[h][nt][2]; s0 += v; q0 = fmaf(v, v, q0);
            v = acc[h][nt][1]; s1 += v; q1 = fmaf(v, v, q1);
            v = acc[h][nt][3]; s1 += v; q1 = fmaf(v, v, q1);
        }
#pragma unroll
        for (int m = 4; m <= 16; m <<= 1) {
            s0 += __shfl_xor_sync(~0u, s0, m);
            q0 += __shfl_xor_sync(~0u, q0, m);
            s1 += __shfl_xor_sync(~0u, s1, m);
            q1 += __shfl_xor_sync(~0u, q1, m);
        }
        if (lane < 4) {
            int base = ((warp * 4 + nt) * 4 + lane) * 4;
            sred[base + 0] = s0;
            sred[base + 1] = q0;
            sred[base + 2] = s1;
            sred[base + 3] = q1;
        }
    }
    __syncthreads();
    if (tid < 25) {
        int nt = tid >> 3, rem = tid & 7, q = rem >> 1, par = rem & 1;
        float s = 0.f, qq = 0.f;
#pragma unroll
        for (int w = 0; w < 8; w++) {
            int base = ((w * 4 + nt) * 4 + q) * 4 + par * 2;
            s  += sred[base];
            qq += sred[base + 1];
        }
        int cta = (blockIdx.z * 16 + blockIdx.y) * 4 + blockIdx.x;
        g_cpart[phase][tid][cta][0] = s;
        g_cpart[phase][tid][cta][1] = qq;
    }
}

// ---------------------------------------------------------------------------
// BN partial statistics for final h
// ---------------------------------------------------------------------------
__global__ void k_bnpart(int phase) {
    const float* src = g_h;
    const int c = blockIdx.x, sl = blockIdx.y;
    float s = 0.f, q = 0.f;
#pragma unroll
    for (int k = 0; k < 16; k++) {
        int j = sl * 4096 + k * 256 + threadIdx.x;
        int nn = j >> 14, p = j & 16383;
        float v = src[(size_t)(nn * 25 + c) * HW + p];
        s += v;
        q = fmaf(v, v, q);
    }
    __shared__ float ss[256], sq[256];
    ss[threadIdx.x] = s; sq[threadIdx.x] = q;
    __syncthreads();
    for (int o = 128; o > 0; o >>= 1) {
        if (threadIdx.x < o) {
            ss[threadIdx.x] += ss[threadIdx.x + o];
            sq[threadIdx.x] += sq[threadIdx.x + o];
        }
        __syncthreads();
    }
    if (threadIdx.x == 0) {
        g_bpart[phase][c][sl][0] = ss[0];
        g_bpart[phase][c][sl][1] = sq[0];
    }
}

// ---------------------------------------------------------------------------
// g1 gate -> fp16 records (t = 0 only, h = 0)
// ---------------------------------------------------------------------------
__global__ void k_g1(const float* __restrict__ u1w, const float* __restrict__ u1b) {
    __shared__ float sw[625];
    __shared__ float sb[25];
    __shared__ unsigned rec_s[13 * 256];
    for (int t = threadIdx.x; t < 625; t += 256) sw[t] = u1w[t];
    if (threadIdx.x < 25) sb[threadIdx.x] = u1b[threadIdx.x];
    __syncthreads();

    const int gid = blockIdx.x * 256 + threadIdx.x;
    const int n = gid >> 14, p = gid & 16383;
    const int y = p >> 7, x = p & 127;
    const int tid = threadIdx.x;
    float hv[25];
#pragma unroll
    for (int i = 0; i < 25; i++) hv[i] = g_h[(size_t)(n * 25 + i) * HW + p];

#pragma unroll 1
    for (int cp = 0; cp < 13; cp++) {
        int c0 = 2 * cp;
        float dot0 = sb[c0];
#pragma unroll
        for (int i = 0; i < 25; i++) dot0 = fmaf(sw[c0 * 25 + i], hv[i], dot0);
        float v0 = hv[c0] * sigmoidf_(dot0);
        unsigned pk = hbits(v0);
        if (c0 + 1 < 25) {
            float dot1 = sb[c0 + 1];
#pragma unroll
            for (int i = 0; i < 25; i++) dot1 = fmaf(sw[(c0 + 1) * 25 + i], hv[i], dot1);
            float v1 = hv[c0 + 1] * sigmoidf_(dot1);
            pk |= (unsigned)hbits(v1) << 16;
        }
        rec_s[cp * 256 + tid] = pk;
    }
    unsigned rh[16];
#pragma unroll
    for (int q = 0; q < 13; q++) rh[q] = rec_s[q * 256 + tid];
    rh[13] = rh[14] = rh[15] = 0u;
    size_t ab = ((size_t)n * APX + (y + 7) * APITCH + (x + 7)) * 4;
#pragma unroll
    for (int j = 0; j < 4; j++)
        g_hg[ab + j] = make_uint4(rh[4*j], rh[4*j+1], rh[4*j+2], rh[4*j+3]);
}

// ---------------------------------------------------------------------------
// ns1 (I$-friendly: unroll-1 pair loop, smem record staging)
// ---------------------------------------------------------------------------
__global__ void k_ns1(int t, const float* __restrict__ alpha, const float* __restrict__ mu,
                      const float* __restrict__ bn1w, const float* __restrict__ bn1b) {
    __shared__ float smn[25], srs[25], sa[25], smu[25], s1w[25], s1b[25];
    __shared__ unsigned rec_s[13 * 256];
    if (threadIdx.x < 25) {
        int c = threadIdx.x;
        bn_finalize_c(0, c, &smn[c], &srs[c]);
        sa[c] = alpha[c]; smu[c] = mu[c]; s1w[c] = bn1w[c]; s1b[c] = bn1b[c];
    }
    __syncthreads();

    const int gid = blockIdx.x * 256 + threadIdx.x;
    const int n = gid >> 14, p = gid & 16383;
    const int y = p >> 7, x = p & 127;
    const int tid = threadIdx.x;
    const size_t base = (size_t)(n * 25) * HW + p;
    const float* yb = g_y + (size_t)t * (2 * 25 * HW) + base;

#pragma unroll 1
    for (int cp = 0; cp < 13; cp++) {
        int c0 = 2 * cp;
        size_t a0 = base + (size_t)c0 * HW;
        float c1v = (g_c1[a0] - smn[c0]) * srs[c0] * s1w[c0] + s1b[c0];
        float h0 = g_h[a0];
        float ns0 = softplusf(yb[(size_t)c0 * HW] - softplusf(c1v * fmaf(sa[c0], h0, smu[c0])));
        g_ns1[a0] = ns0;
        unsigned pk = hbits(ns0);
        if (c0 + 1 < 25) {
            int c1i = c0 + 1;
            size_t a1 = a0 + HW;
            float c1w = (g_c1[a1] - smn[c1i]) * srs[c1i] * s1w[c1i] + s1b[c1i];
            float h1 = g_h[a1];
            float ns1v = softplusf(yb[(size_t)c1i * HW] - softplusf(c1w * fmaf(sa[c1i], h1, smu[c1i])));
            g_ns1[a1] = ns1v;
            pk |= (unsigned)hbits(ns1v) << 16;
        }
        rec_s[cp * 256 + tid] = pk;
    }
    unsigned rh[16];
#pragma unroll
    for (int q = 0; q < 13; q++) rh[q] = rec_s[q * 256 + tid];
    rh[13] = rh[14] = rh[15] = 0u;
    size_t ab = ((size_t)n * APX + (y + 7) * APITCH + (x + 7)) * 4;
#pragma unroll
    for (int j = 0; j < 4; j++)
        g_ns[ab + j] = make_uint4(rh[4*j], rh[4*j+1], rh[4*j+2], rh[4*j+3]);
}

// ---------------------------------------------------------------------------
// h update + fused next-step g1 gate (I$-friendly: unroll-1 loops, smem hn)
// ---------------------------------------------------------------------------
__global__ void k_hnew(const float* __restrict__ u2w, const float* __restrict__ u2b,
                       const float* __restrict__ kappa, const float* __restrict__ gammap,
                       const float* __restrict__ wmix,
                       const float* __restrict__ bn3w, const float* __restrict__ bn3b,
                       const float* __restrict__ u1w, const float* __restrict__ u1b) {
    __shared__ float sw2[625], sw1[625];
    __shared__ float sb[25], sk[25], sg[25], sm_[25], s3w[25], s3b[25], s1b[25];
    __shared__ float smn[25], srs[25];
    __shared__ float hn_s[25 * 256];
    __shared__ unsigned rec_s[13 * 256];
    for (int t = threadIdx.x; t < 625; t += 256) { sw2[t] = u2w[t]; sw1[t] = u1w[t]; }
    if (threadIdx.x < 25) {
        int c = threadIdx.x;
        sb[c]  = u2b[c];
        sk[c]  = kappa[c];
        sg[c]  = gammap[c];
        sm_[c] = wmix[c];
        s3w[c] = bn3w[c];
        s3b[c] = bn3b[c];
        s1b[c] = u1b[c];
        bn_finalize_c(1, c, &smn[c], &srs[c]);
    }
    __syncthreads();

    const int gid = blockIdx.x * 256 + threadIdx.x;
    const int n = gid >> 14, p = gid & 16383;
    const int y = p >> 7, x = p & 127;
    const int tid = threadIdx.x;
    const size_t base = (size_t)(n * 25) * HW + p;

    float nv[25];
#pragma unroll
    for (int i = 0; i < 25; i++) nv[i] = g_ns1[base + (size_t)i * HW];

#pragma unroll 1
    for (int c = 0; c < 25; c++) {
        float dot = sb[c];
#pragma unroll
        for (int i = 0; i < 25; i++) dot = fmaf(sw2[c * 25 + i], nv[i], dot);
        float g2 = sigmoidf_(dot);
        size_t a = base + (size_t)c * HW;
        float c2n = (g_c2[a] - smn[c]) * srs[c] * s3w[c] + s3b[c];
        float nvc = nv[c];
        float h2 = softplusf(sk[c] * nvc + sg[c] * c2n + sm_[c] * nvc * c2n);
        float hold = g_h[a];
        float hnw = softplusf((1.f - g2) * hold + g2 * h2);
        g_h[a] = hnw;
        hn_s[c * 256 + tid] = hnw;
    }

    // reload hn into regs (same thread's smem; no sync needed)
    float hv[25];
#pragma unroll
    for (int i = 0; i < 25; i++) hv[i] = hn_s[i * 256 + tid];

#pragma unroll 1
    for (int cp = 0; cp < 13; cp++) {
        int c0 = 2 * cp;
        float dot0 = s1b[c0];
#pragma unroll
        for (int i = 0; i < 25; i++) dot0 = fmaf(sw1[c0 * 25 + i], hv[i], dot0);
        float v0 = hv[c0] * sigmoidf_(dot0);
        unsigned pk = hbits(v0);
        if (c0 + 1 < 25) {
            float dot1 = s1b[c0 + 1];
#pragma unroll
            for (int i = 0; i < 25; i++) dot1 = fmaf(sw1[(c0 + 1) * 25 + i], hv[i], dot1);
            float v1 = hv[c0 + 1] * sigmoidf_(dot1);
            pk |= (unsigned)hbits(v1) << 16;
        }
        rec_s[cp * 256 + tid] = pk;
    }
    unsigned rh[16];
#pragma unroll
    for (int q = 0; q < 13; q++) rh[q] = rec_s[q * 256 + tid];
    rh[13] = rh[14] = rh[15] = 0u;
    size_t ab = ((size_t)n * APX + (y + 7) * APITCH + (x + 7)) * 4;
#pragma unroll
    for (int j = 0; j < 4; j++)
        g_hg[ab + j] = make_uint4(rh[4*j], rh[4*j+1], rh[4*j+2], rh[4*j+3]);
}

// ---------------------------------------------------------------------------
__global__ void k_zero() {
    int idx = blockIdx.x * 256 + threadIdx.x;
    if (idx < 2 * 25 * HW) g_h[idx] = 0.f;
    if (idx < 2 * APX * 4) {
        const uint4 z = make_uint4(0u, 0u, 0u, 0u);
        g_hg[idx] = z;
        g_ns[idx] = z;
    }
}

// ---------------------------------------------------------------------------
// Epilogue
// ---------------------------------------------------------------------------
__global__ void k_pool(const float* __restrict__ bnow, const float* __restrict__ bnob,
                       const float* __restrict__ fcw) {
    __shared__ float smn[25], srs[25];
    if (threadIdx.x < 25) bn_finalize(2, threadIdx.x, &smn[threadIdx.x], &srs[threadIdx.x]);
    __syncthreads();
    const int gid = blockIdx.x * 256 + threadIdx.x;
    float p0 = 0.f, p1 = 0.f;
    for (int m = gid; m < 204800; m += 32768) {
        int n = m / 102400;
        int r = m % 102400;
        int c = r >> 12;
        int q = r & 4095;
        int i = q >> 6, j = q & 63;
        size_t base = (size_t)(n * 25 + c) * HW + (size_t)(i * 2) * 128 + j * 2;
        float s4 = g_h[base] + g_h[base + 1] + g_h[base + 128] + g_h[base + 129];
        float val = (0.25f * s4 - smn[c]) * srs[c] * bnow[c] + bnob[c];
        p0 = fmaf(val, fcw[m], p0);
        p1 = fmaf(val, fcw[204800 + m], p1);
    }
    __shared__ float s0[256], s1[256];
    s0[threadIdx.x] = p0; s1[threadIdx.x] = p1;
    __syncthreads();
    for (int o = 128; o > 0; o >>= 1) {
        if (threadIdx.x < o) {
            s0[threadIdx.x] += s0[threadIdx.x + o];
            s1[threadIdx.x] += s1[threadIdx.x + o];
        }
        __syncthreads();
    }
    if (threadIdx.x == 0) {
        g_part[blockIdx.x * 2]     = s0[0];
        g_part[blockIdx.x * 2 + 1] = s1[0];
    }
}

__global__ void k_final(const float* __restrict__ fcb, float* __restrict__ out) {
    __shared__ float s0[128], s1[128];
    s0[threadIdx.x] = g_part[threadIdx.x * 2];
    s1[threadIdx.x] = g_part[threadIdx.x * 2 + 1];
    __syncthreads();
    for (int o = 64; o > 0; o >>= 1) {
        if (threadIdx.x < o) {
            s0[threadIdx.x] += s0[threadIdx.x + o];
            s1[threadIdx.x] += s1[threadIdx.x + o];
        }
        __syncthreads();
    }
    if (threadIdx.x == 0) {
        out[0] = sigmoidf_(s0[0] + fcb[0]);
        out[1] = sigmoidf_(s1[0] + fcb[1]);
    }
}

// ---------------------------------------------------------------------------
extern "C" void kernel_launch(void* const* d_in, const int* in_sizes, int n_in,
                              void* d_out, int out_size) {
    const float* x        = (const float*)d_in[0];
    const float* conv00_w = (const float*)d_in[1];
    const float* conv0_w  = (const float*)d_in[2];
    const float* conv1_w  = (const float*)d_in[3];
    const float* conv1_b  = (const float*)d_in[4];
    const float* u1_w     = (const float*)d_in[5];
    const float* u1_b     = (const float*)d_in[6];
    const float* u2_w     = (const float*)d_in[7];
    const float* u2_b     = (const float*)d_in[8];
    const float* w_inh    = (const float*)d_in[9];
    const float* w_exc    = (const float*)d_in[10];
    const float* alpha    = (const float*)d_in[11];
    const float* mu       = (const float*)d_in[12];
    const float* gamma_p  = (const float*)d_in[13];
    const float* kappa    = (const float*)d_in[14];
    const float* w_mix    = (const float*)d_in[15];
    const float* bn1_w    = (const float*)d_in[16];
    const float* bn1_b    = (const float*)d_in[17];
    const float* bn3_w    = (const float*)d_in[18];
    const float* bn3_b    = (const float*)d_in[19];
    const float* bn_out_w = (const float*)d_in[20];
    const float* bn_out_b = (const float*)d_in[21];
    const float* fc4_w    = (const float*)d_in[22];
    const float* fc4_b    = (const float*)d_in[23];
    float* out = (float*)d_out;

    cudaFuncSetAttribute(k_conv15, cudaFuncAttributeMaxDynamicSharedMemorySize, CONV15_SMEM);
    cudaFuncSetAttribute(k_conv00t, cudaFuncAttributeMaxDynamicSharedMemorySize, CONV00_SMEM);

    // launch order puts k_conv15 4th so ncu's fixed skip lands on it
    k_zero<<<3200, 256>>>();
    k_wconv<<<dim3(225, 2), 256>>>(w_inh, w_exc);
    k_g1<<<128, 256>>>(u1_w, u1_b);                       // h=0 -> hg records
    k_conv15<<<dim3(4, 16, 2), 256, CONV15_SMEM>>>(0);    // PROFILED

    // ---- 3D conv front-end (tensor-core conv00) ----
    k_xrec<<<1123, 256>>>(x);
    k_wconv00<<<49, 256>>>(conv00_w);
    k_conv00t<<<dim3(4, 16, 16), 256, CONV00_SMEM>>>();
    k_conv0 <<<dim3(2, 8, 16), 256>>>(conv0_w);
    k_conv1sq<<<dim3(4, 8, 16), 256>>>(conv1_w, conv1_b);

    // ---- finish t = 0 ----
    k_ns1<<<128, 256>>>(0, alpha, mu, bn1_w, bn1_b);
    k_conv15<<<dim3(4, 16, 2), 256, CONV15_SMEM>>>(1);
    k_hnew<<<128, 256>>>(u2_w, u2_b, kappa, gamma_p, w_mix, bn3_w, bn3_b, u1_w, u1_b);

    // ---- t = 1..7 (g1 fused into k_hnew) ----
    for (int t = 1; t < 8; t++) {
        k_conv15<<<dim3(4, 16, 2), 256, CONV15_SMEM>>>(0);
        k_ns1<<<128, 256>>>(t, alpha, mu, bn1_w, bn1_b);
        k_conv15<<<dim3(4, 16, 2), 256, CONV15_SMEM>>>(1);
        k_hnew<<<128, 256>>>(u2_w, u2_b, kappa, gamma_p, w_mix, bn3_w, bn3_b, u1_w, u1_b);
    }

    // ---- epilogue ----
    k_bnpart<<<dim3(25, 8), 256>>>(2);
    k_pool<<<128, 256>>>(bn_out_w, bn_out_b, fc4_w);
    k_final<<<1, 128>>>(fc4_b, out);
}

// round 13
// speedup vs baseline: 1.0890x; 1.0890x over previous
#include <cuda_runtime.h>
#include <cuda_fp16.h>
#include <math.h>

#define HW 16384   // 128*128
#define APITCH 144
#define APX (144*144)
#define XP 136
#define XPX (136*136)

// ---------------- scratch (device globals; no allocation allowed) ----------
static __device__ float g_out1[2*25*8*HW];
static __device__ float g_z[2*8*HW];
static __device__ float g_y[8*2*25*HW];
static __device__ float g_h  [2*25*HW];
static __device__ float g_ns1[2*25*HW];
static __device__ float g_c1 [2*25*HW];
static __device__ float g_c2 [2*25*HW];
static __device__ float g_bpart[3][25][8][2];
static __device__ float g_cpart[2][25][128][2];
static __device__ float g_part[128*2];

// fp16 activation records (conv15): [n][apix] * 4 uint4
static __device__ uint4 g_hg[2*APX*4];
static __device__ uint4 g_ns[2*APX*4];
// fp16 weights, plane-packed B-fragment layout (conv15)
static __device__ uint4 g_wb[2][28800];
// conv00 records: [n][d][136*136] * 4 uint4, K slots = kd*3+ci (21 used)
static __device__ uint4 g_xr[16*XPX*4];
// conv00 weights: 49 taps x 128 uint4
static __device__ uint4 g_wb00[49*128];
// conv1 records: [n][d][136*136] * 2 uint4, K slots = kd (7 used of 16)
static __device__ uint4 g_zr[16*XPX*2];
// conv1 weights: 49 taps x 64 uint4
static __device__ uint4 g_wb1[49*64];

// ---------------- transcendentals (MUFU fast math — best measured) ---------
__device__ __forceinline__ float softplusf(float x) {
    return fmaxf(x, 0.f) + __logf(1.f + __expf(-fabsf(x)));
}
__device__ __forceinline__ float sigmoidf_(float x) {
    return 1.f / (1.f + __expf(-x));
}
__device__ __forceinline__ unsigned s2u(const void* p) {
    return (unsigned)__cvta_generic_to_shared(p);
}
__device__ __forceinline__ void ldm4(unsigned* r, unsigned addr) {
    asm volatile("ldmatrix.sync.aligned.m8n8.x4.shared.b16 {%0,%1,%2,%3}, [%4];"
                 : "=r"(r[0]), "=r"(r[1]), "=r"(r[2]), "=r"(r[3]) : "r"(addr));
}
__device__ __forceinline__ void mma16816(float* d, const unsigned* a, unsigned b0, unsigned b1) {
    asm volatile("mma.sync.aligned.m16n8k16.row.col.f32.f16.f16.f32 "
                 "{%0,%1,%2,%3}, {%4,%5,%6,%7}, {%8,%9}, {%0,%1,%2,%3};"
                 : "+f"(d[0]), "+f"(d[1]), "+f"(d[2]), "+f"(d[3])
                 : "r"(a[0]), "r"(a[1]), "r"(a[2]), "r"(a[3]), "r"(b0), "r"(b1));
}
__device__ __forceinline__ void cpa16(uint4* dst_smem, const uint4* src) {
    asm volatile("cp.async.cg.shared.global [%0], [%1], 16;"
                 :: "r"(s2u(dst_smem)), "l"(src));
}
#define CP_COMMIT() asm volatile("cp.async.commit_group;" ::: "memory")
#define CP_WAIT0()  asm volatile("cp.async.wait_group 0;" ::: "memory")
__device__ __forceinline__ unsigned short hbits(float v) {
    __half h = __float2half(v);
    return *reinterpret_cast<unsigned short*>(&h);
}

__device__ __forceinline__ void bn_finalize(int phase, int c, float* m_out, float* rs_out) {
    float s = 0.f, q = 0.f;
#pragma unroll
    for (int i = 0; i < 8; i++) {
        s += g_bpart[phase][c][i][0];
        q += g_bpart[phase][c][i][1];
    }
    float m = s * (1.f / 32768.f);
    *m_out = m;
    *rs_out = rsqrtf(q * (1.f / 32768.f) - m * m + 1e-3f);
}

__device__ __forceinline__ void bn_finalize_c(int phase, int c, float* m_out, float* rs_out) {
    float s = 0.f, q = 0.f;
#pragma unroll 8
    for (int i = 0; i < 128; i++) {
        s += g_cpart[phase][c][i][0];
        q += g_cpart[phase][c][i][1];
    }
    float m = s * (1.f / 32768.f);
    *m_out = m;
    *rs_out = rsqrtf(q * (1.f / 32768.f) - m * m + 1e-3f);
}

// ---------------------------------------------------------------------------
// conv00 record builder
// ---------------------------------------------------------------------------
__global__ void k_xrec(const float* __restrict__ x) {
    int idx = blockIdx.x * 256 + threadIdx.x;
    if (idx >= 2 * 8 * 134 * 134) return;
    int rx = idx % 134; int t = idx / 134;
    int ry = t % 134; t /= 134;
    int d = t & 7, n = t >> 3;
    int py = ry - 3, px = rx - 3;
    bool inb = ((unsigned)py < 128u) && ((unsigned)px < 128u);

    unsigned rh[16];
#pragma unroll
    for (int i = 0; i < 16; i++) rh[i] = 0u;
    if (inb) {
#pragma unroll
        for (int kd = 0; kd < 7; kd++) {
            int dd = d + kd - 3;
            if ((unsigned)dd < 8u) {
#pragma unroll
                for (int ci = 0; ci < 3; ci++) {
                    float v = x[(size_t)((n * 3 + ci) * 8 + dd) * HW + py * 128 + px];
                    int slot = kd * 3 + ci;
                    rh[slot >> 1] |= (unsigned)hbits(v) << ((slot & 1) * 16);
                }
            }
        }
    }
    size_t ab = ((size_t)(n * 8 + d) * XPX + ry * XP + rx) * 4;
#pragma unroll
    for (int j = 0; j < 4; j++)
        g_xr[ab + j] = make_uint4(rh[4*j], rh[4*j+1], rh[4*j+2], rh[4*j+3]);
}

// ---------------------------------------------------------------------------
// conv00 weight preconvert
// ---------------------------------------------------------------------------
__global__ void k_wconv00(const float* __restrict__ w) {
    const int tap = blockIdx.x;
    const int tid = threadIdx.x;
    const int s = tid >> 7, lane = (tid >> 2) & 31, nt = tid & 3;
    const int oc = nt * 8 + (lane >> 2);
    const int cb = s * 16 + 2 * (lane & 3);
    const int slots[4] = {cb, cb + 1, cb + 8, cb + 9};
    ushort4 hrec;
    unsigned short* hp = (unsigned short*)&hrec;
#pragma unroll
    for (int j = 0; j < 4; j++) {
        float v = 0.f;
        int slot = slots[j];
        if (oc < 25 && slot < 21) {
            int kd = slot / 3, ci = slot % 3;
            v = w[((oc * 3 + ci) * 7 + kd) * 49 + tap];
        }
        hp[j] = hbits(v);
    }
    size_t rec = (((size_t)(tap * 2 + s) * 2 + (nt >> 1)) * 32 + lane) * 2 + (nt & 1);
    ((ushort4*)g_wb00)[rec] = hrec;
}

// ---------------------------------------------------------------------------
// conv00 via mma.sync fp16. grid (4,16,16), 256 thr.
// ---------------------------------------------------------------------------
#define CONV00_SMEM 50560
__global__ __launch_bounds__(256) void k_conv00t() {
    extern __shared__ __align__(128) char smem[];
    uint4* sA = (uint4*)smem;
    uint4* sW = (uint4*)(smem + 21888);

    const int n = blockIdx.z >> 3, d = blockIdx.z & 7;
    const int x0 = blockIdx.x * 32, y0 = blockIdx.y * 8;
    const int tid = threadIdx.x, warp = tid >> 5, lane = tid & 31;

    const uint4* __restrict__ ga = g_xr + (size_t)(n * 8 + d) * XPX * 4;
    const uint4* __restrict__ gw = g_wb00;

    float acc[2][4][4];
#pragma unroll
    for (int h = 0; h < 2; h++)
#pragma unroll
        for (int nt = 0; nt < 4; nt++)
#pragma unroll
            for (int j = 0; j < 4; j++) acc[h][nt][j] = 0.f;

    const int lm = lane & 15, lk = lane >> 4;
    const unsigned aB = s2u(sA);

    for (int i = tid; i < 8 * 152; i += 256) {
        int r = i / 152, j = i % 152;
        int px = j >> 2, part = j & 3;
        int rec = r * 38 + px;
        int pos = (part + (rec >> 1)) & 3;
        cpa16(sA + rec * 4 + pos, ga + ((size_t)(y0 + r) * XP + x0 + px) * 4 + part);
    }
    for (int i = tid; i < 896; i += 256) cpa16(sW + i, gw + i);
    CP_COMMIT();

    for (int ky = 0; ky < 7; ky++) {
        CP_WAIT0();
        __syncthreads();
        if (ky < 6) {
            const int rel = ky + 8, slot = rel % 9;
            for (int i = tid; i < 152; i += 256) {
                int px = i >> 2, part = i & 3;
                int rec = slot * 38 + px;
                int pos = (part + (rec >> 1)) & 3;
                cpa16(sA + rec * 4 + pos, ga + ((size_t)(y0 + rel) * XP + x0 + px) * 4 + part);
            }
            uint4* wd = sW + ((ky + 1) & 1) * 896;
            for (int i = tid; i < 896; i += 256)
                cpa16(wd + i, gw + (ky + 1) * 896 + i);
            CP_COMMIT();
        }

        const uint4* sWb = sW + (ky & 1) * 896;
        const int rs = ((warp + ky) % 9) * 38;
#pragma unroll 1
        for (int kx = 0; kx < 7; kx++) {
            const int rec0 = rs + lm + kx, rec1 = rec0 + 16;
#pragma unroll
            for (int s = 0; s < 2; s++) {
                const int qbase = s * 2 + lk;
                unsigned a0 = aB + rec0 * 64 + (((qbase + (rec0 >> 1)) & 3) << 4);
                unsigned a1 = aB + rec1 * 64 + (((qbase + (rec1 >> 1)) & 3) << 4);
                unsigned f0[4], f1[4];
                ldm4(f0, a0);
                ldm4(f1, a1);
                const int wi = (kx * 2 + s) * 64 + lane;
                uint4 h01 = sWb[wi], h23 = sWb[wi + 32];
                mma16816(acc[0][0], f0, h01.x, h01.y);
                mma16816(acc[0][1], f0, h01.z, h01.w);
                mma16816(acc[0][2], f0, h23.x, h23.y);
                mma16816(acc[0][3], f0, h23.z, h23.w);
                mma16816(acc[1][0], f1, h01.x, h01.y);
                mma16816(acc[1][1], f1, h01.z, h01.w);
                mma16816(acc[1][2], f1, h23.x, h23.y);
                mma16816(acc[1][3], f1, h23.z, h23.w);
            }
        }
    }

    const int y = y0 + warp;
#pragma unroll
    for (int h = 0; h < 2; h++) {
#pragma unroll
        for (int nt = 0; nt < 4; nt++) {
            int oc = nt * 8 + (lane & 3) * 2;
            int xb = x0 + h * 16 + (lane >> 2);
            if (oc < 25) {
                size_t ob = (size_t)((n * 25 + oc) * 8 + d) * HW + y * 128;
                g_out1[ob + xb]     = acc[h][nt][0];
                g_out1[ob + xb + 8] = acc[h][nt][2];
            }
            if (oc + 1 < 25) {
                size_t ob = (size_t)((n * 25 + oc + 1) * 8 + d) * HW + y * 128;
                g_out1[ob + xb]     = acc[h][nt][1];
                g_out1[ob + xb + 8] = acc[h][nt][3];
            }
        }
    }
}

// ---------------------------------------------------------------------------
// conv0 (scalar) — PROFILED this round
// ---------------------------------------------------------------------------
__global__ __launch_bounds__(256) void k_conv0(const float* __restrict__ w) {
    const int n = blockIdx.z >> 3, d = blockIdx.z & 7;
    const int x0 = blockIdx.x * 64, y0 = blockIdx.y * 16;
    const int tx = threadIdx.x & 15, ty = threadIdx.x >> 4;

    __shared__ __align__(16) float s_in[22 * 72];
    __shared__ __align__(16) float s_w[7 * 8];

    float acc[4] = {0.f, 0.f, 0.f, 0.f};

    const int id_lo = (d - 3 < 0) ? 0 : d - 3;
    const int id_hi = (d + 3 > 7) ? 7 : d + 3;

    for (int mid = 0; mid < 25; mid++) {
        for (int id = id_lo; id <= id_hi; id++) {
            const int kd = id - d + 3;
            __syncthreads();
            const float* src = g_out1 + (size_t)((n * 25 + mid) * 8 + id) * HW;
            for (int t = threadIdx.x; t < 22 * 70; t += 256) {
                int r = t / 70, c2 = t % 70;
                int gy = y0 - 3 + r, gx = x0 - 3 + c2;
                float v = 0.f;
                if ((unsigned)gy < 128u && (unsigned)gx < 128u) v = src[gy * 128 + gx];
                s_in[r * 72 + c2] = v;
            }
            for (int t = threadIdx.x; t < 49; t += 256) {
                s_w[(t / 7) * 8 + (t % 7)] = w[(mid * 7 + kd) * 49 + t];
            }
            __syncthreads();
#pragma unroll 1
            for (int ky = 0; ky < 7; ky++) {
                const int base = (ty + ky) * 72 + tx * 4;
                float r[12];
                float4 a = *(const float4*)&s_in[base];
                float4 b = *(const float4*)&s_in[base + 4];
                float4 c = *(const float4*)&s_in[base + 8];
                r[0]=a.x; r[1]=a.y; r[2]=a.z; r[3]=a.w;
                r[4]=b.x; r[5]=b.y; r[6]=b.z; r[7]=b.w;
                r[8]=c.x; r[9]=c.y; r[10]=c.z; r[11]=c.w;
                float4 w0 = *(const float4*)&s_w[ky * 8];
                float4 w1 = *(const float4*)&s_w[ky * 8 + 4];
                float wv[8] = {w0.x, w0.y, w0.z, w0.w, w1.x, w1.y, w1.z, w1.w};
#pragma unroll
                for (int kx = 0; kx < 7; kx++) {
#pragma unroll
                    for (int j = 0; j < 4; j++)
                        acc[j] = fmaf(r[kx + j], wv[kx], acc[j]);
                }
            }
        }
    }
    float* dst = g_z + (size_t)(n * 8 + d) * HW + (y0 + ty) * 128 + x0 + tx * 4;
#pragma unroll
    for (int j = 0; j < 4; j++) dst[j] = acc[j];
}

// ---------------------------------------------------------------------------
// conv1 record builder: g_z -> g_zr (16 fp16 slots: kd 0..6, pad 7..15)
// ---------------------------------------------------------------------------
__global__ void k_zrec() {
    int idx = blockIdx.x * 256 + threadIdx.x;
    if (idx >= 2 * 8 * 134 * 134) return;
    int rx = idx % 134; int t = idx / 134;
    int ry = t % 134; t /= 134;
    int d = t & 7, n = t >> 3;
    int py = ry - 3, px = rx - 3;
    bool inb = ((unsigned)py < 128u) && ((unsigned)px < 128u);

    unsigned rh[8];
#pragma unroll
    for (int i = 0; i < 8; i++) rh[i] = 0u;
    if (inb) {
#pragma unroll
        for (int kd = 0; kd < 7; kd++) {
            int dd = d + kd - 3;
            if ((unsigned)dd < 8u) {
                float v = g_z[(size_t)(n * 8 + dd) * HW + py * 128 + px];
                rh[kd >> 1] |= (unsigned)hbits(v) << ((kd & 1) * 16);
            }
        }
    }
    size_t ab = ((size_t)(n * 8 + d) * XPX + ry * XP + rx) * 2;
    g_zr[ab]     = make_uint4(rh[0], rh[1], rh[2], rh[3]);
    g_zr[ab + 1] = make_uint4(rh[4], rh[5], rh[6], rh[7]);
}

// ---------------------------------------------------------------------------
// conv1 weight preconvert: w[25,1,7,7,7] -> B-fragments per (ky,kx), K=16
// grid 49, block 128 = lane(32) x nt(4)
// ---------------------------------------------------------------------------
__global__ void k_wconv1(const float* __restrict__ w) {
    const int tap = blockIdx.x;
    const int tid = threadIdx.x;
    const int lane = (tid >> 2) & 31, nt = tid & 3;
    const int oc = nt * 8 + (lane >> 2);
    const int cb = 2 * (lane & 3);
    const int slots[4] = {cb, cb + 1, cb + 8, cb + 9};
    ushort4 hrec;
    unsigned short* hp = (unsigned short*)&hrec;
#pragma unroll
    for (int j = 0; j < 4; j++) {
        float v = 0.f;
        int slot = slots[j];
        if (oc < 25 && slot < 7) v = w[oc * 343 + slot * 49 + tap];
        hp[j] = hbits(v);
    }
    size_t rec = (((size_t)(tap * 2 + (nt >> 1)) * 32) + lane) * 2 + (nt & 1);
    ((ushort4*)g_wb1)[rec] = hrec;
}

// ---------------------------------------------------------------------------
// conv1 + bias + square via mma.sync fp16 (K=16). grid (4,16,16), 256 thr.
// ---------------------------------------------------------------------------
#define CONV1_SMEM 25408
__global__ __launch_bounds__(256) void k_conv1t(const float* __restrict__ bias) {
    extern __shared__ __align__(128) char smem[];
    uint4* sA = (uint4*)smem;                  // 9*38*2 = 684 uint4 = 10944 B
    uint4* sW = (uint4*)(smem + 10944);        // 2 x 448 uint4 = 14336 B
    float* sBias = (float*)(smem + 25280);

    const int n = blockIdx.z >> 3, d = blockIdx.z & 7;
    const int x0 = blockIdx.x * 32, y0 = blockIdx.y * 8;
    const int tid = threadIdx.x, warp = tid >> 5, lane = tid & 31;

    const uint4* __restrict__ ga = g_zr + (size_t)(n * 8 + d) * XPX * 2;
    const uint4* __restrict__ gw = g_wb1;

    if (tid < 25) sBias[tid] = bias[tid];

    float acc[2][4][4];
#pragma unroll
    for (int h = 0; h < 2; h++)
#pragma unroll
        for (int nt = 0; nt < 4; nt++)
#pragma unroll
            for (int j = 0; j < 4; j++) acc[h][nt][j] = 0.f;

    const int lm = lane & 15, lk = lane >> 4;
    const unsigned aB = s2u(sA);

    // prologue: rows 0..7 + W slab ky=0 (7 taps x 64 uint4 = 448)
    for (int i = tid; i < 8 * 76; i += 256) {
        int r = i / 76, j = i % 76;
        int px = j >> 1, part = j & 1;
        int rec = r * 38 + px;
        int pos = (part + (rec >> 2)) & 1;
        cpa16(sA + rec * 2 + pos, ga + ((size_t)(y0 + r) * XP + x0 + px) * 2 + part);
    }
    for (int i = tid; i < 448; i += 256) cpa16(sW + i, gw + i);
    CP_COMMIT();

    for (int ky = 0; ky < 7; ky++) {
        CP_WAIT0();
        __syncthreads();
        if (ky < 6) {
            const int rel = ky + 8, slot = rel % 9;
            for (int i = tid; i < 76; i += 256) {
                int px = i >> 1, part = i & 1;
                int rec = slot * 38 + px;
                int pos = (part + (rec >> 2)) & 1;
                cpa16(sA + rec * 2 + pos, ga + ((size_t)(y0 + rel) * XP + x0 + px) * 2 + part);
            }
            uint4* wd = sW + ((ky + 1) & 1) * 448;
            for (int i = tid; i < 448; i += 256)
                cpa16(wd + i, gw + (ky + 1) * 448 + i);
            CP_COMMIT();
        }

        const uint4* sWb = sW + (ky & 1) * 448;
        const int rs = ((warp + ky) % 9) * 38;
#pragma unroll 1
        for (int kx = 0; kx < 7; kx++) {
            const int rec0 = rs + lm + kx, rec1 = rec0 + 16;
            unsigned a0 = aB + rec0 * 32 + (((lk + (rec0 >> 2)) & 1) << 4);
            unsigned a1 = aB + rec1 * 32 + (((lk + (rec1 >> 2)) & 1) << 4);
            unsigned f0[4], f1[4];
            ldm4(f0, a0);
            ldm4(f1, a1);
            const int wi = kx * 64 + lane;
            uint4 h01 = sWb[wi], h23 = sWb[wi + 32];
            mma16816(acc[0][0], f0, h01.x, h01.y);
            mma16816(acc[0][1], f0, h01.z, h01.w);
            mma16816(acc[0][2], f0, h23.x, h23.y);
            mma16816(acc[0][3], f0, h23.z, h23.w);
            mma16816(acc[1][0], f1, h01.x, h01.y);
            mma16816(acc[1][1], f1, h01.z, h01.w);
            mma16816(acc[1][2], f1, h23.x, h23.y);
            mma16816(acc[1][3], f1, h23.z, h23.w);
        }
    }

    const int y = y0 + warp;
#pragma unroll
    for (int h = 0; h < 2; h++) {
#pragma unroll
        for (int nt = 0; nt < 4; nt++) {
            int oc = nt * 8 + (lane & 3) * 2;
            int xb = x0 + h * 16 + (lane >> 2);
            if (oc < 25) {
                float b = sBias[oc];
                size_t ob = (size_t)((d * 2 + n) * 25 + oc) * HW + y * 128;
                float v0 = acc[h][nt][0] + b;
                float v2 = acc[h][nt][2] + b;
                g_y[ob + xb]     = v0 * v0;
                g_y[ob + xb + 8] = v2 * v2;
            }
            if (oc + 1 < 25) {
                float b = sBias[oc + 1];
                size_t ob = (size_t)((d * 2 + n) * 25 + oc + 1) * HW + y * 128;
                float v1 = acc[h][nt][1] + b;
                float v3 = acc[h][nt][3] + b;
                g_y[ob + xb]     = v1 * v1;
                g_y[ob + xb + 8] = v3 * v3;
            }
        }
    }
}

// ---------------------------------------------------------------------------
// conv15 weight preconvert
// ---------------------------------------------------------------------------
__global__ void k_wconv(const float* __restrict__ w_inh, const float* __restrict__ w_exc) {
    const int tap = blockIdx.x, pair = blockIdx.y;
    const float* w = pair ? w_exc : w_inh;
    const int tid = threadIdx.x;
    const int s = tid >> 7, lane = (tid >> 2) & 31, nt = tid & 3;
    const int oc = nt * 8 + (lane >> 2);
    const int cb = s * 16 + 2 * (lane & 3);
    const int cis[4] = {cb, cb + 1, cb + 8, cb + 9};
    ushort4 hrec;
    unsigned short* hp = (unsigned short*)&hrec;
#pragma unroll
    for (int j = 0; j < 4; j++) {
        float v = 0.f;
        int ci = cis[j];
        if (oc < 25 && ci < 25) v = w[(oc * 25 + ci) * 225 + tap];
        hp[j] = hbits(v);
    }
    size_t rec = (((size_t)(tap * 2 + s) * 2 + (nt >> 1)) * 32 + lane) * 2 + (nt & 1);
    ((ushort4*)g_wb[pair])[rec] = hrec;
}

// ---------------------------------------------------------------------------
// conv15 via mma.sync fp16, cp.async pipelined. grid (4,16,2), 256 thr.
// ---------------------------------------------------------------------------
#define CONV15_SMEM 87936
__global__ __launch_bounds__(256) void k_conv15(int phase) {
    extern __shared__ __align__(128) char smem[];
    uint4* sA = (uint4*)smem;
    uint4* sW = (uint4*)(smem + 26496);

    const int n = blockIdx.z;
    const int x0 = blockIdx.x * 32, y0 = blockIdx.y * 8;
    const int tid = threadIdx.x, warp = tid >> 5, lane = tid & 31;

    const uint4* __restrict__ ga = (phase ? g_ns : g_hg) + (size_t)n * APX * 4;
    const uint4* __restrict__ gw = g_wb[phase];
    float* __restrict__ out = phase ? g_c2 : g_c1;

    float acc[2][4][4];
#pragma unroll
    for (int h = 0; h < 2; h++)
#pragma unroll
        for (int nt = 0; nt < 4; nt++)
#pragma unroll
            for (int j = 0; j < 4; j++) acc[h][nt][j] = 0.f;

    const int lm = lane & 15, lk = lane >> 4;
    const unsigned aB = s2u(sA);

    for (int i = tid; i < 8 * 184; i += 256) {
        int r = i / 184, j = i % 184;
        int px = j >> 2, part = j & 3;
        int rec = r * 46 + px;
        int pos = (part + (rec >> 1)) & 3;
        cpa16(sA + rec * 4 + pos, ga + ((size_t)(y0 + r) * APITCH + x0 + px) * 4 + part);
    }
    for (int i = tid; i < 1920; i += 256) cpa16(sW + i, gw + i);
    CP_COMMIT();

    for (int ky = 0; ky < 15; ky++) {
        CP_WAIT0();
        __syncthreads();

        if (ky < 14) {
            const int rel = ky + 8, slot = rel % 9;
            for (int i = tid; i < 184; i += 256) {
                int px = i >> 2, part = i & 3;
                int rec = slot * 46 + px;
                int pos = (part + (rec >> 1)) & 3;
                cpa16(sA + rec * 4 + pos, ga + ((size_t)(y0 + rel) * APITCH + x0 + px) * 4 + part);
            }
            uint4* wd = sW + ((ky + 1) & 1) * 1920;
            for (int i = tid; i < 1920; i += 256)
                cpa16(wd + i, gw + (ky + 1) * 1920 + i);
            CP_COMMIT();
        }

        const uint4* sWb = sW + (ky & 1) * 1920;
        const int rs = ((warp + ky) % 9) * 46;
#pragma unroll 3
        for (int kx = 0; kx < 15; kx++) {
            const int rec0 = rs + lm + kx, rec1 = rec0 + 16;
#pragma unroll
            for (int s = 0; s < 2; s++) {
                const int qbase = s * 2 + lk;
                unsigned a0 = aB + rec0 * 64 + (((qbase + (rec0 >> 1)) & 3) << 4);
                unsigned a1 = aB + rec1 * 64 + (((qbase + (rec1 >> 1)) & 3) << 4);
                unsigned f0[4], f1[4];
                ldm4(f0, a0);
                ldm4(f1, a1);
                const int wi = (kx * 2 + s) * 64 + lane;
                uint4 h01 = sWb[wi], h23 = sWb[wi + 32];
                mma16816(acc[0][0], f0, h01.x, h01.y);
                mma16816(acc[0][1], f0, h01.z, h01.w);
                mma16816(acc[0][2], f0, h23.x, h23.y);
                mma16816(acc[0][3], f0, h23.z, h23.w);
                mma16816(acc[1][0], f1, h01.x, h01.y);
                mma16816(acc[1][1], f1, h01.z, h01.w);
                mma16816(acc[1][2], f1, h23.x, h23.y);
                mma16816(acc[1][3], f1, h23.z, h23.w);
            }
        }
    }

    const int y = y0 + warp;
#pragma unroll
    for (int h = 0; h < 2; h++) {
#pragma unroll
        for (int nt = 0; nt < 4; nt++) {
            int oc = nt * 8 + (lane & 3) * 2;
            int xb = x0 + h * 16 + (lane >> 2);
            if (oc < 25) {
                size_t ob = (size_t)(n * 25 + oc) * HW + y * 128;
                out[ob + xb]     = acc[h][nt][0];
                out[ob + xb + 8] = acc[h][nt][2];
            }
            if (oc + 1 < 25) {
                size_t ob = (size_t)(n * 25 + oc + 1) * HW + y * 128;
                out[ob + xb]     = acc[h][nt][1];
                out[ob + xb + 8] = acc[h][nt][3];
            }
        }
    }

    __syncthreads();
    float* sred = (float*)smem;
#pragma unroll
    for (int nt = 0; nt < 4; nt++) {
        float s0 = 0.f, q0 = 0.f, s1 = 0.f, q1 = 0.f;
#pragma unroll
        for (int h = 0; h < 2; h++) {
            float v;
            v = acc[h][nt][0]; s0 += v; q0 = fmaf(v, v, q0);
            v = acc[h][nt][2]; s0 += v; q0 = fmaf(v, v, q0);
            v = acc[h][nt][1]; s1 += v; q1 = fmaf(v, v, q1);
            v = acc[h][nt][3]; s1 += v; q1 = fmaf(v, v, q1);
        }
#pragma unroll
        for (int m = 4; m <= 16; m <<= 1) {
            s0 += __shfl_xor_sync(~0u, s0, m);
            q0 += __shfl_xor_sync(~0u, q0, m);
            s1 += __shfl_xor_sync(~0u, s1, m);
            q1 += __shfl_xor_sync(~0u, q1, m);
        }
        if (lane < 4) {
            int base = ((warp * 4 + nt) * 4 + lane) * 4;
            sred[base + 0] = s0;
            sred[base + 1] = q0;
            sred[base + 2] = s1;
            sred[base + 3] = q1;
        }
    }
    __syncthreads();
    if (tid < 25) {
        int nt = tid >> 3, rem = tid & 7, q = rem >> 1, par = rem & 1;
        float s = 0.f, qq = 0.f;
#pragma unroll
        for (int w = 0; w < 8; w++) {
            int base = ((w * 4 + nt) * 4 + q) * 4 + par * 2;
            s  += sred[base];
            qq += sred[base + 1];
        }
        int cta = (blockIdx.z * 16 + blockIdx.y) * 4 + blockIdx.x;
        g_cpart[phase][tid][cta][0] = s;
        g_cpart[phase][tid][cta][1] = qq;
    }
}

// ---------------------------------------------------------------------------
// BN partial statistics for final h
// ---------------------------------------------------------------------------
__global__ void k_bnpart(int phase) {
    const float* src = g_h;
    const int c = blockIdx.x, sl = blockIdx.y;
    float s = 0.f, q = 0.f;
#pragma unroll
    for (int k = 0; k < 16; k++) {
        int j = sl * 4096 + k * 256 + threadIdx.x;
        int nn = j >> 14, p = j & 16383;
        float v = src[(size_t)(nn * 25 + c) * HW + p];
        s += v;
        q = fmaf(v, v, q);
    }
    __shared__ float ss[256], sq[256];
    ss[threadIdx.x] = s; sq[threadIdx.x] = q;
    __syncthreads();
    for (int o = 128; o > 0; o >>= 1) {
        if (threadIdx.x < o) {
            ss[threadIdx.x] += ss[threadIdx.x + o];
            sq[threadIdx.x] += sq[threadIdx.x + o];
        }
        __syncthreads();
    }
    if (threadIdx.x == 0) {
        g_bpart[phase][c][sl][0] = ss[0];
        g_bpart[phase][c][sl][1] = sq[0];
    }
}

// ---------------------------------------------------------------------------
// g1 gate -> fp16 records (t = 0 only, h = 0)
// ---------------------------------------------------------------------------
__global__ void k_g1(const float* __restrict__ u1w, const float* __restrict__ u1b) {
    __shared__ float sw[625];
    __shared__ float sb[25];
    for (int t = threadIdx.x; t < 625; t += 256) sw[t] = u1w[t];
    if (threadIdx.x < 25) sb[threadIdx.x] = u1b[threadIdx.x];
    __syncthreads();

    const int gid = blockIdx.x * 256 + threadIdx.x;
    const int n = gid >> 14, p = gid & 16383;
    const int y = p >> 7, x = p & 127;
    float hv[25];
#pragma unroll
    for (int i = 0; i < 25; i++) hv[i] = g_h[(size_t)(n * 25 + i) * HW + p];

    unsigned rh[16];
#pragma unroll
    for (int i = 0; i < 16; i++) rh[i] = 0u;

#pragma unroll
    for (int c = 0; c < 25; c++) {
        float dot = sb[c];
#pragma unroll
        for (int i = 0; i < 25; i++) dot = fmaf(sw[c * 25 + i], hv[i], dot);
        float v = hv[c] * sigmoidf_(dot);
        rh[c >> 1] |= (unsigned)hbits(v) << ((c & 1) * 16);
    }
    size_t ab = ((size_t)n * APX + (y + 7) * APITCH + (x + 7)) * 4;
#pragma unroll
    for (int j = 0; j < 4; j++)
        g_hg[ab + j] = make_uint4(rh[4*j], rh[4*j+1], rh[4*j+2], rh[4*j+3]);
}

// ---------------------------------------------------------------------------
// ns1
// ---------------------------------------------------------------------------
__global__ void k_ns1(int t, const float* __restrict__ alpha, const float* __restrict__ mu,
                      const float* __restrict__ bn1w, const float* __restrict__ bn1b) {
    __shared__ float smn[25], srs[25], sa[25], smu[25], s1w[25], s1b[25];
    if (threadIdx.x < 25) {
        int c = threadIdx.x;
        bn_finalize_c(0, c, &smn[c], &srs[c]);
        sa[c] = alpha[c]; smu[c] = mu[c]; s1w[c] = bn1w[c]; s1b[c] = bn1b[c];
    }
    __syncthreads();

    const int gid = blockIdx.x * 256 + threadIdx.x;
    const int n = gid >> 14, p = gid & 16383;
    const int y = p >> 7, x = p & 127;

    unsigned rh[16];
#pragma unroll
    for (int i = 0; i < 16; i++) rh[i] = 0u;

#pragma unroll
    for (int c = 0; c < 25; c++) {
        size_t a = (size_t)(n * 25 + c) * HW + p;
        float c1 = (g_c1[a] - smn[c]) * srs[c] * s1w[c] + s1b[c];
        float h = g_h[a];
        float yv = g_y[(size_t)t * (2 * 25 * HW) + a];
        float ns = softplusf(yv - softplusf(c1 * fmaf(sa[c], h, smu[c])));
        g_ns1[a] = ns;
        rh[c >> 1] |= (unsigned)hbits(ns) << ((c & 1) * 16);
    }
    size_t ab = ((size_t)n * APX + (y + 7) * APITCH + (x + 7)) * 4;
#pragma unroll
    for (int j = 0; j < 4; j++)
        g_ns[ab + j] = make_uint4(rh[4*j], rh[4*j+1], rh[4*j+2], rh[4*j+3]);
}

// ---------------------------------------------------------------------------
// h update, fused with NEXT step's g1 gate
// ---------------------------------------------------------------------------
__global__ void k_hnew(const float* __restrict__ u2w, const float* __restrict__ u2b,
                       const float* __restrict__ kappa, const float* __restrict__ gammap,
                       const float* __restrict__ wmix,
                       const float* __restrict__ bn3w, const float* __restrict__ bn3b,
                       const float* __restrict__ u1w, const float* __restrict__ u1b) {
    __shared__ float sw2[625], sw1[625];
    __shared__ float sb[25], sk[25], sg[25], sm_[25], s3w[25], s3b[25], s1b[25];
    __shared__ float smn[25], srs[25];
    for (int t = threadIdx.x; t < 625; t += 256) { sw2[t] = u2w[t]; sw1[t] = u1w[t]; }
    if (threadIdx.x < 25) {
        int c = threadIdx.x;
        sb[c]  = u2b[c];
        sk[c]  = kappa[c];
        sg[c]  = gammap[c];
        sm_[c] = wmix[c];
        s3w[c] = bn3w[c];
        s3b[c] = bn3b[c];
        s1b[c] = u1b[c];
        bn_finalize_c(1, c, &smn[c], &srs[c]);
    }
    __syncthreads();

    const int gid = blockIdx.x * 256 + threadIdx.x;
    const int n = gid >> 14, p = gid & 16383;
    const int y = p >> 7, x = p & 127;
    float nv[25], hn[25];
#pragma unroll
    for (int i = 0; i < 25; i++) nv[i] = g_ns1[(size_t)(n * 25 + i) * HW + p];
#pragma unroll
    for (int c = 0; c < 25; c++) {
        float dot = sb[c];
#pragma unroll
        for (int i = 0; i < 25; i++) dot = fmaf(sw2[c * 25 + i], nv[i], dot);
        float g2 = sigmoidf_(dot);
        size_t a = (size_t)(n * 25 + c) * HW + p;
        float c2n = (g_c2[a] - smn[c]) * srs[c] * s3w[c] + s3b[c];
        float h2 = softplusf(sk[c] * nv[c] + sg[c] * c2n + sm_[c] * nv[c] * c2n);
        float hold = g_h[a];
        float hnw = softplusf((1.f - g2) * hold + g2 * h2);
        hn[c] = hnw;
        g_h[a] = hnw;
    }
    unsigned rh[16];
#pragma unroll
    for (int i = 0; i < 16; i++) rh[i] = 0u;
#pragma unroll
    for (int c = 0; c < 25; c++) {
        float dot = s1b[c];
#pragma unroll
        for (int i = 0; i < 25; i++) dot = fmaf(sw1[c * 25 + i], hn[i], dot);
        float v = hn[c] * sigmoidf_(dot);
        rh[c >> 1] |= (unsigned)hbits(v) << ((c & 1) * 16);
    }
    size_t ab = ((size_t)n * APX + (y + 7) * APITCH + (x + 7)) * 4;
#pragma unroll
    for (int j = 0; j < 4; j++)
        g_hg[ab + j] = make_uint4(rh[4*j], rh[4*j+1], rh[4*j+2], rh[4*j+3]);
}

// ---------------------------------------------------------------------------
__global__ void k_zero() {
    int idx = blockIdx.x * 256 + threadIdx.x;
    if (idx < 2 * 25 * HW) g_h[idx] = 0.f;
    if (idx < 2 * APX * 4) {
        const uint4 z = make_uint4(0u, 0u, 0u, 0u);
        g_hg[idx] = z;
        g_ns[idx] = z;
    }
}

// ---------------------------------------------------------------------------
// Epilogue
// ---------------------------------------------------------------------------
__global__ void k_pool(const float* __restrict__ bnow, const float* __restrict__ bnob,
                       const float* __restrict__ fcw) {
    __shared__ float smn[25], srs[25];
    if (threadIdx.x < 25) bn_finalize(2, threadIdx.x, &smn[threadIdx.x], &srs[threadIdx.x]);
    __syncthreads();
    const int gid = blockIdx.x * 256 + threadIdx.x;
    float p0 = 0.f, p1 = 0.f;
    for (int m = gid; m < 204800; m += 32768) {
        int n = m / 102400;
        int r = m % 102400;
        int c = r >> 12;
        int q = r & 4095;
        int i = q >> 6, j = q & 63;
        size_t base = (size_t)(n * 25 + c) * HW + (size_t)(i * 2) * 128 + j * 2;
        float s4 = g_h[base] + g_h[base + 1] + g_h[base + 128] + g_h[base + 129];
        float val = (0.25f * s4 - smn[c]) * srs[c] * bnow[c] + bnob[c];
        p0 = fmaf(val, fcw[m], p0);
        p1 = fmaf(val, fcw[204800 + m], p1);
    }
    __shared__ float s0[256], s1[256];
    s0[threadIdx.x] = p0; s1[threadIdx.x] = p1;
    __syncthreads();
    for (int o = 128; o > 0; o >>= 1) {
        if (threadIdx.x < o) {
            s0[threadIdx.x] += s0[threadIdx.x + o];
            s1[threadIdx.x] += s1[threadIdx.x + o];
        }
        __syncthreads();
    }
    if (threadIdx.x == 0) {
        g_part[blockIdx.x * 2]     = s0[0];
        g_part[blockIdx.x * 2 + 1] = s1[0];
    }
}

__global__ void k_final(const float* __restrict__ fcb, float* __restrict__ out) {
    __shared__ float s0[128], s1[128];
    s0[threadIdx.x] = g_part[threadIdx.x * 2];
    s1[threadIdx.x] = g_part[threadIdx.x * 2 + 1];
    __syncthreads();
    for (int o = 64; o > 0; o >>= 1) {
        if (threadIdx.x < o) {
            s0[threadIdx.x] += s0[threadIdx.x + o];
            s1[threadIdx.x] += s1[threadIdx.x + o];
        }
        __syncthreads();
    }
    if (threadIdx.x == 0) {
        out[0] = sigmoidf_(s0[0] + fcb[0]);
        out[1] = sigmoidf_(s1[0] + fcb[1]);
    }
}

// ---------------------------------------------------------------------------
extern "C" void kernel_launch(void* const* d_in, const int* in_sizes, int n_in,
                              void* d_out, int out_size) {
    const float* x        = (const float*)d_in[0];
    const float* conv00_w = (const float*)d_in[1];
    const float* conv0_w  = (const float*)d_in[2];
    const float* conv1_w  = (const float*)d_in[3];
    const float* conv1_b  = (const float*)d_in[4];
    const float* u1_w     = (const float*)d_in[5];
    const float* u1_b     = (const float*)d_in[6];
    const float* u2_w     = (const float*)d_in[7];
    const float* u2_b     = (const float*)d_in[8];
    const float* w_inh    = (const float*)d_in[9];
    const float* w_exc    = (const float*)d_in[10];
    const float* alpha    = (const float*)d_in[11];
    const float* mu       = (const float*)d_in[12];
    const float* gamma_p  = (const float*)d_in[13];
    const float* kappa    = (const float*)d_in[14];
    const float* w_mix    = (const float*)d_in[15];
    const float* bn1_w    = (const float*)d_in[16];
    const float* bn1_b    = (const float*)d_in[17];
    const float* bn3_w    = (const float*)d_in[18];
    const float* bn3_b    = (const float*)d_in[19];
    const float* bn_out_w = (const float*)d_in[20];
    const float* bn_out_b = (const float*)d_in[21];
    const float* fc4_w    = (const float*)d_in[22];
    const float* fc4_b    = (const float*)d_in[23];
    float* out = (float*)d_out;

    cudaFuncSetAttribute(k_conv15, cudaFuncAttributeMaxDynamicSharedMemorySize, CONV15_SMEM);
    cudaFuncSetAttribute(k_conv00t, cudaFuncAttributeMaxDynamicSharedMemorySize, CONV00_SMEM);

    // ---- 3D conv front-end (4th launch = k_conv0 -> PROFILED) ----
    k_xrec<<<1124, 256>>>(x);
    k_wconv00<<<49, 256>>>(conv00_w);
    k_conv00t<<<dim3(4, 16, 16), 256, CONV00_SMEM>>>();
    k_conv0<<<dim3(2, 8, 16), 256>>>(conv0_w);            // PROFILED
    k_zrec<<<1124, 256>>>();
    k_wconv1<<<49, 128>>>(conv1_w);
    k_conv1t<<<dim3(4, 16, 16), 256, CONV1_SMEM>>>(conv1_b);

    // ---- recurrent prep ----
    k_zero<<<3200, 256>>>();
    k_wconv<<<dim3(225, 2), 256>>>(w_inh, w_exc);
    k_g1<<<128, 256>>>(u1_w, u1_b);                       // h=0 -> hg records

    // ---- recurrent scan, T = 8 (g1 fused into k_hnew) ----
    for (int t = 0; t < 8; t++) {
        k_conv15<<<dim3(4, 16, 2), 256, CONV15_SMEM>>>(0);
        k_ns1<<<128, 256>>>(t, alpha, mu, bn1_w, bn1_b);
        k_conv15<<<dim3(4, 16, 2), 256, CONV15_SMEM>>>(1);
        k_hnew<<<128, 256>>>(u2_w, u2_b, kappa, gamma_p, w_mix, bn3_w, bn3_b, u1_w, u1_b);
    }

    // ---- epilogue ----
    k_bnpart<<<dim3(25, 8), 256>>>(2);
    k_pool<<<128, 256>>>(bn_out_w, bn_out_b, fc4_w);
    k_final<<<1, 128>>>(fc4_b, out);
}

// round 14
// speedup vs baseline: 1.2854x; 1.1804x over previous
#include <cuda_runtime.h>
#include <cuda_fp16.h>
#include <math.h>

#define HW 16384   // 128*128
#define APITCH 144
#define APX (144*144)
#define XP 136
#define XPX (136*136)

// ---------------- scratch (device globals; no allocation allowed) ----------
static __device__ float g_out1[2*25*8*HW];
static __device__ float g_z[2*8*HW];
static __device__ float g_y[8*2*25*HW];
static __device__ float g_h  [2*25*HW];
static __device__ float g_ns1[2*25*HW];
static __device__ float g_c1 [2*25*HW];
static __device__ float g_c2 [2*25*HW];
static __device__ float g_bpart[3][25][8][2];
static __device__ float g_cpart[2][25][128][2];
static __device__ float g_part[128*2];

// fp16 activation records (conv15): [n][apix] * 4 uint4
static __device__ uint4 g_hg[2*APX*4];
static __device__ uint4 g_ns[2*APX*4];
// fp16 weights, plane-packed B-fragment layout (conv15)
static __device__ uint4 g_wb[2][28800];
// conv00 records: [n][d][136*136] * 4 uint4, K slots = kd*3+ci (21 used)
static __device__ uint4 g_xr[16*XPX*4];
// conv00 weights: 49 taps x 128 uint4
static __device__ uint4 g_wb00[49*128];
// conv0 records: [n][id][136*136] * 4 uint4, K slots = ci (25 used of 32)
static __device__ uint4 g_or[16*XPX*4];
// conv0 weights: 343 taps x 2s x 32 lanes uint2 (n8 fragments)
static __device__ uint2 g_wb0[343*64];
// conv1 records: [n][d][136*136] * 2 uint4, K slots = kd (7 used of 16)
static __device__ uint4 g_zr[16*XPX*2];
// conv1 weights: 49 taps x 64 uint4
static __device__ uint4 g_wb1[49*64];

// ---------------- transcendentals (MUFU fast math — best measured) ---------
__device__ __forceinline__ float softplusf(float x) {
    return fmaxf(x, 0.f) + __logf(1.f + __expf(-fabsf(x)));
}
__device__ __forceinline__ float sigmoidf_(float x) {
    return 1.f / (1.f + __expf(-x));
}
__device__ __forceinline__ unsigned s2u(const void* p) {
    return (unsigned)__cvta_generic_to_shared(p);
}
__device__ __forceinline__ void ldm4(unsigned* r, unsigned addr) {
    asm volatile("ldmatrix.sync.aligned.m8n8.x4.shared.b16 {%0,%1,%2,%3}, [%4];"
                 : "=r"(r[0]), "=r"(r[1]), "=r"(r[2]), "=r"(r[3]) : "r"(addr));
}
__device__ __forceinline__ void mma16816(float* d, const unsigned* a, unsigned b0, unsigned b1) {
    asm volatile("mma.sync.aligned.m16n8k16.row.col.f32.f16.f16.f32 "
                 "{%0,%1,%2,%3}, {%4,%5,%6,%7}, {%8,%9}, {%0,%1,%2,%3};"
                 : "+f"(d[0]), "+f"(d[1]), "+f"(d[2]), "+f"(d[3])
                 : "r"(a[0]), "r"(a[1]), "r"(a[2]), "r"(a[3]), "r"(b0), "r"(b1));
}
__device__ __forceinline__ void cpa16(uint4* dst_smem, const uint4* src) {
    asm volatile("cp.async.cg.shared.global [%0], [%1], 16;"
                 :: "r"(s2u(dst_smem)), "l"(src));
}
#define CP_COMMIT() asm volatile("cp.async.commit_group;" ::: "memory")
#define CP_WAIT0()  asm volatile("cp.async.wait_group 0;" ::: "memory")
__device__ __forceinline__ unsigned short hbits(float v) {
    __half h = __float2half(v);
    return *reinterpret_cast<unsigned short*>(&h);
}

__device__ __forceinline__ void bn_finalize(int phase, int c, float* m_out, float* rs_out) {
    float s = 0.f, q = 0.f;
#pragma unroll
    for (int i = 0; i < 8; i++) {
        s += g_bpart[phase][c][i][0];
        q += g_bpart[phase][c][i][1];
    }
    float m = s * (1.f / 32768.f);
    *m_out = m;
    *rs_out = rsqrtf(q * (1.f / 32768.f) - m * m + 1e-3f);
}

__device__ __forceinline__ void bn_finalize_c(int phase, int c, float* m_out, float* rs_out) {
    float s = 0.f, q = 0.f;
#pragma unroll 8
    for (int i = 0; i < 128; i++) {
        s += g_cpart[phase][c][i][0];
        q += g_cpart[phase][c][i][1];
    }
    float m = s * (1.f / 32768.f);
    *m_out = m;
    *rs_out = rsqrtf(q * (1.f / 32768.f) - m * m + 1e-3f);
}

// ---------------------------------------------------------------------------
// conv00 record builder
// ---------------------------------------------------------------------------
__global__ void k_xrec(const float* __restrict__ x) {
    int idx = blockIdx.x * 256 + threadIdx.x;
    if (idx >= 2 * 8 * 134 * 134) return;
    int rx = idx % 134; int t = idx / 134;
    int ry = t % 134; t /= 134;
    int d = t & 7, n = t >> 3;
    int py = ry - 3, px = rx - 3;
    bool inb = ((unsigned)py < 128u) && ((unsigned)px < 128u);

    unsigned rh[16];
#pragma unroll
    for (int i = 0; i < 16; i++) rh[i] = 0u;
    if (inb) {
#pragma unroll
        for (int kd = 0; kd < 7; kd++) {
            int dd = d + kd - 3;
            if ((unsigned)dd < 8u) {
#pragma unroll
                for (int ci = 0; ci < 3; ci++) {
                    float v = x[(size_t)((n * 3 + ci) * 8 + dd) * HW + py * 128 + px];
                    int slot = kd * 3 + ci;
                    rh[slot >> 1] |= (unsigned)hbits(v) << ((slot & 1) * 16);
                }
            }
        }
    }
    size_t ab = ((size_t)(n * 8 + d) * XPX + ry * XP + rx) * 4;
#pragma unroll
    for (int j = 0; j < 4; j++)
        g_xr[ab + j] = make_uint4(rh[4*j], rh[4*j+1], rh[4*j+2], rh[4*j+3]);
}

// ---------------------------------------------------------------------------
// conv00 weight preconvert
// ---------------------------------------------------------------------------
__global__ void k_wconv00(const float* __restrict__ w) {
    const int tap = blockIdx.x;
    const int tid = threadIdx.x;
    const int s = tid >> 7, lane = (tid >> 2) & 31, nt = tid & 3;
    const int oc = nt * 8 + (lane >> 2);
    const int cb = s * 16 + 2 * (lane & 3);
    const int slots[4] = {cb, cb + 1, cb + 8, cb + 9};
    ushort4 hrec;
    unsigned short* hp = (unsigned short*)&hrec;
#pragma unroll
    for (int j = 0; j < 4; j++) {
        float v = 0.f;
        int slot = slots[j];
        if (oc < 25 && slot < 21) {
            int kd = slot / 3, ci = slot % 3;
            v = w[((oc * 3 + ci) * 7 + kd) * 49 + tap];
        }
        hp[j] = hbits(v);
    }
    size_t rec = (((size_t)(tap * 2 + s) * 2 + (nt >> 1)) * 32 + lane) * 2 + (nt & 1);
    ((ushort4*)g_wb00)[rec] = hrec;
}

// ---------------------------------------------------------------------------
// conv00 via mma.sync fp16. grid (4,16,16), 256 thr. PROFILED (4th launch)
// ---------------------------------------------------------------------------
#define CONV00_SMEM 50560
__global__ __launch_bounds__(256) void k_conv00t() {
    extern __shared__ __align__(128) char smem[];
    uint4* sA = (uint4*)smem;
    uint4* sW = (uint4*)(smem + 21888);

    const int n = blockIdx.z >> 3, d = blockIdx.z & 7;
    const int x0 = blockIdx.x * 32, y0 = blockIdx.y * 8;
    const int tid = threadIdx.x, warp = tid >> 5, lane = tid & 31;

    const uint4* __restrict__ ga = g_xr + (size_t)(n * 8 + d) * XPX * 4;
    const uint4* __restrict__ gw = g_wb00;

    float acc[2][4][4];
#pragma unroll
    for (int h = 0; h < 2; h++)
#pragma unroll
        for (int nt = 0; nt < 4; nt++)
#pragma unroll
            for (int j = 0; j < 4; j++) acc[h][nt][j] = 0.f;

    const int lm = lane & 15, lk = lane >> 4;
    const unsigned aB = s2u(sA);

    for (int i = tid; i < 8 * 152; i += 256) {
        int r = i / 152, j = i % 152;
        int px = j >> 2, part = j & 3;
        int rec = r * 38 + px;
        int pos = (part + (rec >> 1)) & 3;
        cpa16(sA + rec * 4 + pos, ga + ((size_t)(y0 + r) * XP + x0 + px) * 4 + part);
    }
    for (int i = tid; i < 896; i += 256) cpa16(sW + i, gw + i);
    CP_COMMIT();

    for (int ky = 0; ky < 7; ky++) {
        CP_WAIT0();
        __syncthreads();
        if (ky < 6) {
            const int rel = ky + 8, slot = rel % 9;
            for (int i = tid; i < 152; i += 256) {
                int px = i >> 2, part = i & 3;
                int rec = slot * 38 + px;
                int pos = (part + (rec >> 1)) & 3;
                cpa16(sA + rec * 4 + pos, ga + ((size_t)(y0 + rel) * XP + x0 + px) * 4 + part);
            }
            uint4* wd = sW + ((ky + 1) & 1) * 896;
            for (int i = tid; i < 896; i += 256)
                cpa16(wd + i, gw + (ky + 1) * 896 + i);
            CP_COMMIT();
        }

        const uint4* sWb = sW + (ky & 1) * 896;
        const int rs = ((warp + ky) % 9) * 38;
#pragma unroll 1
        for (int kx = 0; kx < 7; kx++) {
            const int rec0 = rs + lm + kx, rec1 = rec0 + 16;
#pragma unroll
            for (int s = 0; s < 2; s++) {
                const int qbase = s * 2 + lk;
                unsigned a0 = aB + rec0 * 64 + (((qbase + (rec0 >> 1)) & 3) << 4);
                unsigned a1 = aB + rec1 * 64 + (((qbase + (rec1 >> 1)) & 3) << 4);
                unsigned f0[4], f1[4];
                ldm4(f0, a0);
                ldm4(f1, a1);
                const int wi = (kx * 2 + s) * 64 + lane;
                uint4 h01 = sWb[wi], h23 = sWb[wi + 32];
                mma16816(acc[0][0], f0, h01.x, h01.y);
                mma16816(acc[0][1], f0, h01.z, h01.w);
                mma16816(acc[0][2], f0, h23.x, h23.y);
                mma16816(acc[0][3], f0, h23.z, h23.w);
                mma16816(acc[1][0], f1, h01.x, h01.y);
                mma16816(acc[1][1], f1, h01.z, h01.w);
                mma16816(acc[1][2], f1, h23.x, h23.y);
                mma16816(acc[1][3], f1, h23.z, h23.w);
            }
        }
    }

    const int y = y0 + warp;
#pragma unroll
    for (int h = 0; h < 2; h++) {
#pragma unroll
        for (int nt = 0; nt < 4; nt++) {
            int oc = nt * 8 + (lane & 3) * 2;
            int xb = x0 + h * 16 + (lane >> 2);
            if (oc < 25) {
                size_t ob = (size_t)((n * 25 + oc) * 8 + d) * HW + y * 128;
                g_out1[ob + xb]     = acc[h][nt][0];
                g_out1[ob + xb + 8] = acc[h][nt][2];
            }
            if (oc + 1 < 25) {
                size_t ob = (size_t)((n * 25 + oc + 1) * 8 + d) * HW + y * 128;
                g_out1[ob + xb]     = acc[h][nt][1];
                g_out1[ob + xb + 8] = acc[h][nt][3];
            }
        }
    }
}

// ---------------------------------------------------------------------------
// conv0 record builder: g_out1 -> g_or (32 fp16 slots: ci 0..24, pad)
// ---------------------------------------------------------------------------
__global__ void k_orec() {
    int idx = blockIdx.x * 256 + threadIdx.x;
    if (idx >= 2 * 8 * 134 * 134) return;
    int rx = idx % 134; int t = idx / 134;
    int ry = t % 134; t /= 134;
    int id = t & 7, n = t >> 3;
    int py = ry - 3, px = rx - 3;
    bool inb = ((unsigned)py < 128u) && ((unsigned)px < 128u);

    unsigned rh[16];
#pragma unroll
    for (int i = 0; i < 16; i++) rh[i] = 0u;
    if (inb) {
#pragma unroll
        for (int ci = 0; ci < 25; ci++) {
            float v = g_out1[(size_t)((n * 25 + ci) * 8 + id) * HW + py * 128 + px];
            rh[ci >> 1] |= (unsigned)hbits(v) << ((ci & 1) * 16);
        }
    }
    size_t ab = ((size_t)(n * 8 + id) * XPX + ry * XP + rx) * 4;
#pragma unroll
    for (int j = 0; j < 4; j++)
        g_or[ab + j] = make_uint4(rh[4*j], rh[4*j+1], rh[4*j+2], rh[4*j+3]);
}

// ---------------------------------------------------------------------------
// conv0 weight preconvert: w[1,25,7,7,7] -> n8 B-fragments per tap (kd,ky,kx)
// grid 343, block 64 = s(2) x lane(32)
// ---------------------------------------------------------------------------
__global__ void k_wconv0(const float* __restrict__ w) {
    const int tap = blockIdx.x;
    const int s = threadIdx.x >> 5, lane = threadIdx.x & 31;
    const int oc = lane >> 2;
    const int cb = s * 16 + 2 * (lane & 3);
    const int slots[4] = {cb, cb + 1, cb + 8, cb + 9};
    ushort4 hrec;
    unsigned short* hp = (unsigned short*)&hrec;
#pragma unroll
    for (int j = 0; j < 4; j++) {
        float v = 0.f;
        if (oc == 0 && slots[j] < 25) v = w[slots[j] * 343 + tap];
        hp[j] = hbits(v);
    }
    ((ushort4*)g_wb0)[(tap * 2 + s) * 32 + lane] = hrec;
}

// ---------------------------------------------------------------------------
// conv0 via mma.sync fp16 (K=ci, kd-outer). grid (4,16,16), 256 thr.
// ---------------------------------------------------------------------------
#define CONV0_SMEM 29056
__global__ __launch_bounds__(256) void k_conv0t() {
    extern __shared__ __align__(128) char smem[];
    uint4* sA = (uint4*)smem;                  // 9*38*4 = 1368 uint4 = 21888 B
    uint2* sW = (uint2*)(smem + 21888);        // 2 bufs x 448 uint2 = 7168 B

    const int n = blockIdx.z >> 3, d = blockIdx.z & 7;
    const int x0 = blockIdx.x * 32, y0 = blockIdx.y * 8;
    const int tid = threadIdx.x, warp = tid >> 5, lane = tid & 31;

    float acc[2][4];
#pragma unroll
    for (int h = 0; h < 2; h++)
#pragma unroll
        for (int j = 0; j < 4; j++) acc[h][j] = 0.f;

    const int lm = lane & 15, lk = lane >> 4;
    const unsigned aB = s2u(sA);

    const int kd_lo = (3 - d < 0) ? 0 : 3 - d;
    const int kd_hi = (10 - d > 6) ? 6 : 10 - d;

    for (int kd = kd_lo; kd <= kd_hi; kd++) {
        const int dd = d + kd - 3;
        const uint4* __restrict__ ga = g_or + (size_t)(n * 8 + dd) * XPX * 4;
        const uint4* __restrict__ gw = (const uint4*)g_wb0 + (size_t)kd * 49 * 32;

        __syncthreads();  // prior compute done before restaging A slots
        // prologue for this kd: rows rel 0..7 + W slab ky=0
        for (int i = tid; i < 8 * 152; i += 256) {
            int r = i / 152, j = i % 152;
            int px = j >> 2, part = j & 3;
            int rec = r * 38 + px;
            int pos = (part + (rec >> 1)) & 3;
            cpa16(sA + rec * 4 + pos, ga + ((size_t)(y0 + r) * XP + x0 + px) * 4 + part);
        }
        for (int i = tid; i < 224; i += 256) cpa16((uint4*)sW + i, gw + i);
        CP_COMMIT();

        for (int ky = 0; ky < 7; ky++) {
            CP_WAIT0();
            __syncthreads();
            if (ky < 6) {
                const int rel = ky + 8, slot = rel % 9;
                for (int i = tid; i < 152; i += 256) {
                    int px = i >> 2, part = i & 3;
                    int rec = slot * 38 + px;
                    int pos = (part + (rec >> 1)) & 3;
                    cpa16(sA + rec * 4 + pos, ga + ((size_t)(y0 + rel) * XP + x0 + px) * 4 + part);
                }
                uint4* wd = (uint4*)sW + ((ky + 1) & 1) * 224;
                for (int i = tid; i < 224; i += 256)
                    cpa16(wd + i, gw + (ky + 1) * 224 + i);
                CP_COMMIT();
            }

            const uint2* sWb = sW + ((ky & 1) * 448);
            const int rs = ((warp + ky) % 9) * 38;
#pragma unroll 1
            for (int kx = 0; kx < 7; kx++) {
                const int rec0 = rs + lm + kx, rec1 = rec0 + 16;
#pragma unroll
                for (int s = 0; s < 2; s++) {
                    const int qbase = s * 2 + lk;
                    unsigned a0 = aB + rec0 * 64 + (((qbase + (rec0 >> 1)) & 3) << 4);
                    unsigned a1 = aB + rec1 * 64 + (((qbase + (rec1 >> 1)) & 3) << 4);
                    unsigned f0[4], f1[4];
                    ldm4(f0, a0);
                    ldm4(f1, a1);
                    uint2 b = sWb[(kx * 2 + s) * 32 + lane];
                    mma16816(acc[0], f0, b.x, b.y);
                    mma16816(acc[1], f1, b.x, b.y);
                }
            }
        }
    }

    // epilogue: only oc = 0 valid -> lanes with (lane&3)==0
    if ((lane & 3) == 0) {
        const int y = y0 + warp;
#pragma unroll
        for (int h = 0; h < 2; h++) {
            int xb = x0 + h * 16 + (lane >> 2);
            size_t ob = (size_t)(n * 8 + d) * HW + y * 128;
            g_z[ob + xb]     = acc[h][0];
            g_z[ob + xb + 8] = acc[h][2];
        }
    }
}

// ---------------------------------------------------------------------------
// conv1 record builder: g_z -> g_zr (16 fp16 slots: kd 0..6, pad 7..15)
// ---------------------------------------------------------------------------
__global__ void k_zrec() {
    int idx = blockIdx.x * 256 + threadIdx.x;
    if (idx >= 2 * 8 * 134 * 134) return;
    int rx = idx % 134; int t = idx / 134;
    int ry = t % 134; t /= 134;
    int d = t & 7, n = t >> 3;
    int py = ry - 3, px = rx - 3;
    bool inb = ((unsigned)py < 128u) && ((unsigned)px < 128u);

    unsigned rh[8];
#pragma unroll
    for (int i = 0; i < 8; i++) rh[i] = 0u;
    if (inb) {
#pragma unroll
        for (int kd = 0; kd < 7; kd++) {
            int dd = d + kd - 3;
            if ((unsigned)dd < 8u) {
                float v = g_z[(size_t)(n * 8 + dd) * HW + py * 128 + px];
                rh[kd >> 1] |= (unsigned)hbits(v) << ((kd & 1) * 16);
            }
        }
    }
    size_t ab = ((size_t)(n * 8 + d) * XPX + ry * XP + rx) * 2;
    g_zr[ab]     = make_uint4(rh[0], rh[1], rh[2], rh[3]);
    g_zr[ab + 1] = make_uint4(rh[4], rh[5], rh[6], rh[7]);
}

// ---------------------------------------------------------------------------
// conv1 weight preconvert: w[25,1,7,7,7] -> B-fragments per (ky,kx), K=16
// ---------------------------------------------------------------------------
__global__ void k_wconv1(const float* __restrict__ w) {
    const int tap = blockIdx.x;
    const int tid = threadIdx.x;
    const int lane = (tid >> 2) & 31, nt = tid & 3;
    const int oc = nt * 8 + (lane >> 2);
    const int cb = 2 * (lane & 3);
    const int slots[4] = {cb, cb + 1, cb + 8, cb + 9};
    ushort4 hrec;
    unsigned short* hp = (unsigned short*)&hrec;
#pragma unroll
    for (int j = 0; j < 4; j++) {
        float v = 0.f;
        int slot = slots[j];
        if (oc < 25 && slot < 7) v = w[oc * 343 + slot * 49 + tap];
        hp[j] = hbits(v);
    }
    size_t rec = (((size_t)(tap * 2 + (nt >> 1)) * 32) + lane) * 2 + (nt & 1);
    ((ushort4*)g_wb1)[rec] = hrec;
}

// ---------------------------------------------------------------------------
// conv1 + bias + square via mma.sync fp16 (K=16). grid (4,16,16), 256 thr.
// ---------------------------------------------------------------------------
#define CONV1_SMEM 25408
__global__ __launch_bounds__(256) void k_conv1t(const float* __restrict__ bias) {
    extern __shared__ __align__(128) char smem[];
    uint4* sA = (uint4*)smem;
    uint4* sW = (uint4*)(smem + 10944);
    float* sBias = (float*)(smem + 25280);

    const int n = blockIdx.z >> 3, d = blockIdx.z & 7;
    const int x0 = blockIdx.x * 32, y0 = blockIdx.y * 8;
    const int tid = threadIdx.x, warp = tid >> 5, lane = tid & 31;

    const uint4* __restrict__ ga = g_zr + (size_t)(n * 8 + d) * XPX * 2;
    const uint4* __restrict__ gw = g_wb1;

    if (tid < 25) sBias[tid] = bias[tid];

    float acc[2][4][4];
#pragma unroll
    for (int h = 0; h < 2; h++)
#pragma unroll
        for (int nt = 0; nt < 4; nt++)
#pragma unroll
            for (int j = 0; j < 4; j++) acc[h][nt][j] = 0.f;

    const int lm = lane & 15, lk = lane >> 4;
    const unsigned aB = s2u(sA);

    for (int i = tid; i < 8 * 76; i += 256) {
        int r = i / 76, j = i % 76;
        int px = j >> 1, part = j & 1;
        int rec = r * 38 + px;
        int pos = (part + (rec >> 2)) & 1;
        cpa16(sA + rec * 2 + pos, ga + ((size_t)(y0 + r) * XP + x0 + px) * 2 + part);
    }
    for (int i = tid; i < 448; i += 256) cpa16(sW + i, gw + i);
    CP_COMMIT();

    for (int ky = 0; ky < 7; ky++) {
        CP_WAIT0();
        __syncthreads();
        if (ky < 6) {
            const int rel = ky + 8, slot = rel % 9;
            for (int i = tid; i < 76; i += 256) {
                int px = i >> 1, part = i & 1;
                int rec = slot * 38 + px;
                int pos = (part + (rec >> 2)) & 1;
                cpa16(sA + rec * 2 + pos, ga + ((size_t)(y0 + rel) * XP + x0 + px) * 2 + part);
            }
            uint4* wd = sW + ((ky + 1) & 1) * 448;
            for (int i = tid; i < 448; i += 256)
                cpa16(wd + i, gw + (ky + 1) * 448 + i);
            CP_COMMIT();
        }

        const uint4* sWb = sW + (ky & 1) * 448;
        const int rs = ((warp + ky) % 9) * 38;
#pragma unroll 1
        for (int kx = 0; kx < 7; kx++) {
            const int rec0 = rs + lm + kx, rec1 = rec0 + 16;
            unsigned a0 = aB + rec0 * 32 + (((lk + (rec0 >> 2)) & 1) << 4);
            unsigned a1 = aB + rec1 * 32 + (((lk + (rec1 >> 2)) & 1) << 4);
            unsigned f0[4], f1[4];
            ldm4(f0, a0);
            ldm4(f1, a1);
            const int wi = kx * 64 + lane;
            uint4 h01 = sWb[wi], h23 = sWb[wi + 32];
            mma16816(acc[0][0], f0, h01.x, h01.y);
            mma16816(acc[0][1], f0, h01.z, h01.w);
            mma16816(acc[0][2], f0, h23.x, h23.y);
            mma16816(acc[0][3], f0, h23.z, h23.w);
            mma16816(acc[1][0], f1, h01.x, h01.y);
            mma16816(acc[1][1], f1, h01.z, h01.w);
            mma16816(acc[1][2], f1, h23.x, h23.y);
            mma16816(acc[1][3], f1, h23.z, h23.w);
        }
    }

    const int y = y0 + warp;
#pragma unroll
    for (int h = 0; h < 2; h++) {
#pragma unroll
        for (int nt = 0; nt < 4; nt++) {
            int oc = nt * 8 + (lane & 3) * 2;
            int xb = x0 + h * 16 + (lane >> 2);
            if (oc < 25) {
                float b = sBias[oc];
                size_t ob = (size_t)((d * 2 + n) * 25 + oc) * HW + y * 128;
                float v0 = acc[h][nt][0] + b;
                float v2 = acc[h][nt][2] + b;
                g_y[ob + xb]     = v0 * v0;
                g_y[ob + xb + 8] = v2 * v2;
            }
            if (oc + 1 < 25) {
                float b = sBias[oc + 1];
                size_t ob = (size_t)((d * 2 + n) * 25 + oc + 1) * HW + y * 128;
                float v1 = acc[h][nt][1] + b;
                float v3 = acc[h][nt][3] + b;
                g_y[ob + xb]     = v1 * v1;
                g_y[ob + xb + 8] = v3 * v3;
            }
        }
    }
}

// ---------------------------------------------------------------------------
// conv15 weight preconvert
// ---------------------------------------------------------------------------
__global__ void k_wconv(const float* __restrict__ w_inh, const float* __restrict__ w_exc) {
    const int tap = blockIdx.x, pair = blockIdx.y;
    const float* w = pair ? w_exc : w_inh;
    const int tid = threadIdx.x;
    const int s = tid >> 7, lane = (tid >> 2) & 31, nt = tid & 3;
    const int oc = nt * 8 + (lane >> 2);
    const int cb = s * 16 + 2 * (lane & 3);
    const int cis[4] = {cb, cb + 1, cb + 8, cb + 9};
    ushort4 hrec;
    unsigned short* hp = (unsigned short*)&hrec;
#pragma unroll
    for (int j = 0; j < 4; j++) {
        float v = 0.f;
        int ci = cis[j];
        if (oc < 25 && ci < 25) v = w[(oc * 25 + ci) * 225 + tap];
        hp[j] = hbits(v);
    }
    size_t rec = (((size_t)(tap * 2 + s) * 2 + (nt >> 1)) * 32 + lane) * 2 + (nt & 1);
    ((ushort4*)g_wb[pair])[rec] = hrec;
}

// ---------------------------------------------------------------------------
// conv15 via mma.sync fp16, cp.async pipelined. grid (4,16,2), 256 thr.
// ---------------------------------------------------------------------------
#define CONV15_SMEM 87936
__global__ __launch_bounds__(256) void k_conv15(int phase) {
    extern __shared__ __align__(128) char smem[];
    uint4* sA = (uint4*)smem;
    uint4* sW = (uint4*)(smem + 26496);

    const int n = blockIdx.z;
    const int x0 = blockIdx.x * 32, y0 = blockIdx.y * 8;
    const int tid = threadIdx.x, warp = tid >> 5, lane = tid & 31;

    const uint4* __restrict__ ga = (phase ? g_ns : g_hg) + (size_t)n * APX * 4;
    const uint4* __restrict__ gw = g_wb[phase];
    float* __restrict__ out = phase ? g_c2 : g_c1;

    float acc[2][4][4];
#pragma unroll
    for (int h = 0; h < 2; h++)
#pragma unroll
        for (int nt = 0; nt < 4; nt++)
#pragma unroll
            for (int j = 0; j < 4; j++) acc[h][nt][j] = 0.f;

    const int lm = lane & 15, lk = lane >> 4;
    const unsigned aB = s2u(sA);

    for (int i = tid; i < 8 * 184; i += 256) {
        int r = i / 184, j = i % 184;
        int px = j >> 2, part = j & 3;
        int rec = r * 46 + px;
        int pos = (part + (rec >> 1)) & 3;
        cpa16(sA + rec * 4 + pos, ga + ((size_t)(y0 + r) * APITCH + x0 + px) * 4 + part);
    }
    for (int i = tid; i < 1920; i += 256) cpa16(sW + i, gw + i);
    CP_COMMIT();

    for (int ky = 0; ky < 15; ky++) {
        CP_WAIT0();
        __syncthreads();

        if (ky < 14) {
            const int rel = ky + 8, slot = rel % 9;
            for (int i = tid; i < 184; i += 256) {
                int px = i >> 2, part = i & 3;
                int rec = slot * 46 + px;
                int pos = (part + (rec >> 1)) & 3;
                cpa16(sA + rec * 4 + pos, ga + ((size_t)(y0 + rel) * APITCH + x0 + px) * 4 + part);
            }
            uint4* wd = sW + ((ky + 1) & 1) * 1920;
            for (int i = tid; i < 1920; i += 256)
                cpa16(wd + i, gw + (ky + 1) * 1920 + i);
            CP_COMMIT();
        }

        const uint4* sWb = sW + (ky & 1) * 1920;
        const int rs = ((warp + ky) % 9) * 46;
#pragma unroll 3
        for (int kx = 0; kx < 15; kx++) {
            const int rec0 = rs + lm + kx, rec1 = rec0 + 16;
#pragma unroll
            for (int s = 0; s < 2; s++) {
                const int qbase = s * 2 + lk;
                unsigned a0 = aB + rec0 * 64 + (((qbase + (rec0 >> 1)) & 3) << 4);
                unsigned a1 = aB + rec1 * 64 + (((qbase + (rec1 >> 1)) & 3) << 4);
                unsigned f0[4], f1[4];
                ldm4(f0, a0);
                ldm4(f1, a1);
                const int wi = (kx * 2 + s) * 64 + lane;
                uint4 h01 = sWb[wi], h23 = sWb[wi + 32];
                mma16816(acc[0][0], f0, h01.x, h01.y);
                mma16816(acc[0][1], f0, h01.z, h01.w);
                mma16816(acc[0][2], f0, h23.x, h23.y);
                mma16816(acc[0][3], f0, h23.z, h23.w);
                mma16816(acc[1][0], f1, h01.x, h01.y);
                mma16816(acc[1][1], f1, h01.z, h01.w);
                mma16816(acc[1][2], f1, h23.x, h23.y);
                mma16816(acc[1][3], f1, h23.z, h23.w);
            }
        }
    }

    const int y = y0 + warp;
#pragma unroll
    for (int h = 0; h < 2; h++) {
#pragma unroll
        for (int nt = 0; nt < 4; nt++) {
            int oc = nt * 8 + (lane & 3) * 2;
            int xb = x0 + h * 16 + (lane >> 2);
            if (oc < 25) {
                size_t ob = (size_t)(n * 25 + oc) * HW + y * 128;
                out[ob + xb]     = acc[h][nt][0];
                out[ob + xb + 8] = acc[h][nt][2];
            }
            if (oc + 1 < 25) {
                size_t ob = (size_t)(n * 25 + oc + 1) * HW + y * 128;
                out[ob + xb]     = acc[h][nt][1];
                out[ob + xb + 8] = acc[h][nt][3];
            }
        }
    }

    __syncthreads();
    float* sred = (float*)smem;
#pragma unroll
    for (int nt = 0; nt < 4; nt++) {
        float s0 = 0.f, q0 = 0.f, s1 = 0.f, q1 = 0.f;
#pragma unroll
        for (int h = 0; h < 2; h++) {
            float v;
            v = acc[h][nt][0]; s0 += v; q0 = fmaf(v, v, q0);
            v = acc[h][nt][2]; s0 += v; q0 = fmaf(v, v, q0);
            v = acc[h][nt][1]; s1 += v; q1 = fmaf(v, v, q1);
            v = acc[h][nt][3]; s1 += v; q1 = fmaf(v, v, q1);
        }
#pragma unroll
        for (int m = 4; m <= 16; m <<= 1) {
            s0 += __shfl_xor_sync(~0u, s0, m);
            q0 += __shfl_xor_sync(~0u, q0, m);
            s1 += __shfl_xor_sync(~0u, s1, m);
            q1 += __shfl_xor_sync(~0u, q1, m);
        }
        if (lane < 4) {
            int base = ((warp * 4 + nt) * 4 + lane) * 4;
            sred[base + 0] = s0;
            sred[base + 1] = q0;
            sred[base + 2] = s1;
            sred[base + 3] = q1;
        }
    }
    __syncthreads();
    if (tid < 25) {
        int nt = tid >> 3, rem = tid & 7, q = rem >> 1, par = rem & 1;
        float s = 0.f, qq = 0.f;
#pragma unroll
        for (int w = 0; w < 8; w++) {
            int base = ((w * 4 + nt) * 4 + q) * 4 + par * 2;
            s  += sred[base];
            qq += sred[base + 1];
        }
        int cta = (blockIdx.z * 16 + blockIdx.y) * 4 + blockIdx.x;
        g_cpart[phase][tid][cta][0] = s;
        g_cpart[phase][tid][cta][1] = qq;
    }
}

// ---------------------------------------------------------------------------
// BN partial statistics for final h
// ---------------------------------------------------------------------------
__global__ void k_bnpart(int phase) {
    const float* src = g_h;
    const int c = blockIdx.x, sl = blockIdx.y;
    float s = 0.f, q = 0.f;
#pragma unroll
    for (int k = 0; k < 16; k++) {
        int j = sl * 4096 + k * 256 + threadIdx.x;
        int nn = j >> 14, p = j & 16383;
        float v = src[(size_t)(nn * 25 + c) * HW + p];
        s += v;
        q = fmaf(v, v, q);
    }
    __shared__ float ss[256], sq[256];
    ss[threadIdx.x] = s; sq[threadIdx.x] = q;
    __syncthreads();
    for (int o = 128; o > 0; o >>= 1) {
        if (threadIdx.x < o) {
            ss[threadIdx.x] += ss[threadIdx.x + o];
            sq[threadIdx.x] += sq[threadIdx.x + o];
        }
        __syncthreads();
    }
    if (threadIdx.x == 0) {
        g_bpart[phase][c][sl][0] = ss[0];
        g_bpart[phase][c][sl][1] = sq[0];
    }
}

// ---------------------------------------------------------------------------
// g1 gate -> fp16 records (t = 0 only, h = 0)
// ---------------------------------------------------------------------------
__global__ void k_g1(const float* __restrict__ u1w, const float* __restrict__ u1b) {
    __shared__ float sw[625];
    __shared__ float sb[25];
    for (int t = threadIdx.x; t < 625; t += 256) sw[t] = u1w[t];
    if (threadIdx.x < 25) sb[threadIdx.x] = u1b[threadIdx.x];
    __syncthreads();

    const int gid = blockIdx.x * 256 + threadIdx.x;
    const int n = gid >> 14, p = gid & 16383;
    const int y = p >> 7, x = p & 127;
    float hv[25];
#pragma unroll
    for (int i = 0; i < 25; i++) hv[i] = g_h[(size_t)(n * 25 + i) * HW + p];

    unsigned rh[16];
#pragma unroll
    for (int i = 0; i < 16; i++) rh[i] = 0u;

#pragma unroll
    for (int c = 0; c < 25; c++) {
        float dot = sb[c];
#pragma unroll
        for (int i = 0; i < 25; i++) dot = fmaf(sw[c * 25 + i], hv[i], dot);
        float v = hv[c] * sigmoidf_(dot);
        rh[c >> 1] |= (unsigned)hbits(v) << ((c & 1) * 16);
    }
    size_t ab = ((size_t)n * APX + (y + 7) * APITCH + (x + 7)) * 4;
#pragma unroll
    for (int j = 0; j < 4; j++)
        g_hg[ab + j] = make_uint4(rh[4*j], rh[4*j+1], rh[4*j+2], rh[4*j+3]);
}

// ---------------------------------------------------------------------------
// ns1
// ---------------------------------------------------------------------------
__global__ void k_ns1(int t, const float* __restrict__ alpha, const float* __restrict__ mu,
                      const float* __restrict__ bn1w, const float* __restrict__ bn1b) {
    __shared__ float smn[25], srs[25], sa[25], smu[25], s1w[25], s1b[25];
    if (threadIdx.x < 25) {
        int c = threadIdx.x;
        bn_finalize_c(0, c, &smn[c], &srs[c]);
        sa[c] = alpha[c]; smu[c] = mu[c]; s1w[c] = bn1w[c]; s1b[c] = bn1b[c];
    }
    __syncthreads();

    const int gid = blockIdx.x * 256 + threadIdx.x;
    const int n = gid >> 14, p = gid & 16383;
    const int y = p >> 7, x = p & 127;

    unsigned rh[16];
#pragma unroll
    for (int i = 0; i < 16; i++) rh[i] = 0u;

#pragma unroll
    for (int c = 0; c < 25; c++) {
        size_t a = (size_t)(n * 25 + c) * HW + p;
        float c1 = (g_c1[a] - smn[c]) * srs[c] * s1w[c] + s1b[c];
        float h = g_h[a];
        float yv = g_y[(size_t)t * (2 * 25 * HW) + a];
        float ns = softplusf(yv - softplusf(c1 * fmaf(sa[c], h, smu[c])));
        g_ns1[a] = ns;
        rh[c >> 1] |= (unsigned)hbits(ns) << ((c & 1) * 16);
    }
    size_t ab = ((size_t)n * APX + (y + 7) * APITCH + (x + 7)) * 4;
#pragma unroll
    for (int j = 0; j < 4; j++)
        g_ns[ab + j] = make_uint4(rh[4*j], rh[4*j+1], rh[4*j+2], rh[4*j+3]);
}

// ---------------------------------------------------------------------------
// h update, fused with NEXT step's g1 gate
// ---------------------------------------------------------------------------
__global__ void k_hnew(const float* __restrict__ u2w, const float* __restrict__ u2b,
                       const float* __restrict__ kappa, const float* __restrict__ gammap,
                       const float* __restrict__ wmix,
                       const float* __restrict__ bn3w, const float* __restrict__ bn3b,
                       const float* __restrict__ u1w, const float* __restrict__ u1b) {
    __shared__ float sw2[625], sw1[625];
    __shared__ float sb[25], sk[25], sg[25], sm_[25], s3w[25], s3b[25], s1b[25];
    __shared__ float smn[25], srs[25];
    for (int t = threadIdx.x; t < 625; t += 256) { sw2[t] = u2w[t]; sw1[t] = u1w[t]; }
    if (threadIdx.x < 25) {
        int c = threadIdx.x;
        sb[c]  = u2b[c];
        sk[c]  = kappa[c];
        sg[c]  = gammap[c];
        sm_[c] = wmix[c];
        s3w[c] = bn3w[c];
        s3b[c] = bn3b[c];
        s1b[c] = u1b[c];
        bn_finalize_c(1, c, &smn[c], &srs[c]);
    }
    __syncthreads();

    const int gid = blockIdx.x * 256 + threadIdx.x;
    const int n = gid >> 14, p = gid & 16383;
    const int y = p >> 7, x = p & 127;
    float nv[25], hn[25];
#pragma unroll
    for (int i = 0; i < 25; i++) nv[i] = g_ns1[(size_t)(n * 25 + i) * HW + p];
#pragma unroll
    for (int c = 0; c < 25; c++) {
        float dot = sb[c];
#pragma unroll
        for (int i = 0; i < 25; i++) dot = fmaf(sw2[c * 25 + i], nv[i], dot);
        float g2 = sigmoidf_(dot);
        size_t a = (size_t)(n * 25 + c) * HW + p;
        float c2n = (g_c2[a] - smn[c]) * srs[c] * s3w[c] + s3b[c];
        float h2 = softplusf(sk[c] * nv[c] + sg[c] * c2n + sm_[c] * nv[c] * c2n);
        float hold = g_h[a];
        float hnw = softplusf((1.f - g2) * hold + g2 * h2);
        hn[c] = hnw;
        g_h[a] = hnw;
    }
    unsigned rh[16];
#pragma unroll
    for (int i = 0; i < 16; i++) rh[i] = 0u;
#pragma unroll
    for (int c = 0; c < 25; c++) {
        float dot = s1b[c];
#pragma unroll
        for (int i = 0; i < 25; i++) dot = fmaf(sw1[c * 25 + i], hn[i], dot);
        float v = hn[c] * sigmoidf_(dot);
        rh[c >> 1] |= (unsigned)hbits(v) << ((c & 1) * 16);
    }
    size_t ab = ((size_t)n * APX + (y + 7) * APITCH + (x + 7)) * 4;
#pragma unroll
    for (int j = 0; j < 4; j++)
        g_hg[ab + j] = make_uint4(rh[4*j], rh[4*j+1], rh[4*j+2], rh[4*j+3]);
}

// ---------------------------------------------------------------------------
__global__ void k_zero() {
    int idx = blockIdx.x * 256 + threadIdx.x;
    if (idx < 2 * 25 * HW) g_h[idx] = 0.f;
    if (idx < 2 * APX * 4) {
        const uint4 z = make_uint4(0u, 0u, 0u, 0u);
        g_hg[idx] = z;
        g_ns[idx] = z;
    }
}

// ---------------------------------------------------------------------------
// Epilogue
// ---------------------------------------------------------------------------
__global__ void k_pool(const float* __restrict__ bnow, const float* __restrict__ bnob,
                       const float* __restrict__ fcw) {
    __shared__ float smn[25], srs[25];
    if (threadIdx.x < 25) bn_finalize(2, threadIdx.x, &smn[threadIdx.x], &srs[threadIdx.x]);
    __syncthreads();
    const int gid = blockIdx.x * 256 + threadIdx.x;
    float p0 = 0.f, p1 = 0.f;
    for (int m = gid; m < 204800; m += 32768) {
        int n = m / 102400;
        int r = m % 102400;
        int c = r >> 12;
        int q = r & 4095;
        int i = q >> 6, j = q & 63;
        size_t base = (size_t)(n * 25 + c) * HW + (size_t)(i * 2) * 128 + j * 2;
        float s4 = g_h[base] + g_h[base + 1] + g_h[base + 128] + g_h[base + 129];
        float val = (0.25f * s4 - smn[c]) * srs[c] * bnow[c] + bnob[c];
        p0 = fmaf(val, fcw[m], p0);
        p1 = fmaf(val, fcw[204800 + m], p1);
    }
    __shared__ float s0[256], s1[256];
    s0[threadIdx.x] = p0; s1[threadIdx.x] = p1;
    __syncthreads();
    for (int o = 128; o > 0; o >>= 1) {
        if (threadIdx.x < o) {
            s0[threadIdx.x] += s0[threadIdx.x + o];
            s1[threadIdx.x] += s1[threadIdx.x + o];
        }
        __syncthreads();
    }
    if (threadIdx.x == 0) {
        g_part[blockIdx.x * 2]     = s0[0];
        g_part[blockIdx.x * 2 + 1] = s1[0];
    }
}

__global__ void k_final(const float* __restrict__ fcb, float* __restrict__ out) {
    __shared__ float s0[128], s1[128];
    s0[threadIdx.x] = g_part[threadIdx.x * 2];
    s1[threadIdx.x] = g_part[threadIdx.x * 2 + 1];
    __syncthreads();
    for (int o = 64; o > 0; o >>= 1) {
        if (threadIdx.x < o) {
            s0[threadIdx.x] += s0[threadIdx.x + o];
            s1[threadIdx.x] += s1[threadIdx.x + o];
        }
        __syncthreads();
    }
    if (threadIdx.x == 0) {
        out[0] = sigmoidf_(s0[0] + fcb[0]);
        out[1] = sigmoidf_(s1[0] + fcb[1]);
    }
}

// ---------------------------------------------------------------------------
extern "C" void kernel_launch(void* const* d_in, const int* in_sizes, int n_in,
                              void* d_out, int out_size) {
    const float* x        = (const float*)d_in[0];
    const float* conv00_w = (const float*)d_in[1];
    const float* conv0_w  = (const float*)d_in[2];
    const float* conv1_w  = (const float*)d_in[3];
    const float* conv1_b  = (const float*)d_in[4];
    const float* u1_w     = (const float*)d_in[5];
    const float* u1_b     = (const float*)d_in[6];
    const float* u2_w     = (const float*)d_in[7];
    const float* u2_b     = (const float*)d_in[8];
    const float* w_inh    = (const float*)d_in[9];
    const float* w_exc    = (const float*)d_in[10];
    const float* alpha    = (const float*)d_in[11];
    const float* mu       = (const float*)d_in[12];
    const float* gamma_p  = (const float*)d_in[13];
    const float* kappa    = (const float*)d_in[14];
    const float* w_mix    = (const float*)d_in[15];
    const float* bn1_w    = (const float*)d_in[16];
    const float* bn1_b    = (const float*)d_in[17];
    const float* bn3_w    = (const float*)d_in[18];
    const float* bn3_b    = (const float*)d_in[19];
    const float* bn_out_w = (const float*)d_in[20];
    const float* bn_out_b = (const float*)d_in[21];
    const float* fc4_w    = (const float*)d_in[22];
    const float* fc4_b    = (const float*)d_in[23];
    float* out = (float*)d_out;

    cudaFuncSetAttribute(k_conv15, cudaFuncAttributeMaxDynamicSharedMemorySize, CONV15_SMEM);
    cudaFuncSetAttribute(k_conv00t, cudaFuncAttributeMaxDynamicSharedMemorySize, CONV00_SMEM);

    // ---- 3D conv front-end (4th launch = k_conv00t -> PROFILED) ----
    k_xrec<<<1124, 256>>>(x);
    k_wconv00<<<49, 256>>>(conv00_w);
    k_wconv0<<<343, 64>>>(conv0_w);
    k_conv00t<<<dim3(4, 16, 16), 256, CONV00_SMEM>>>();   // PROFILED
    k_orec<<<1124, 256>>>();
    k_conv0t<<<dim3(4, 16, 16), 256, CONV0_SMEM>>>();
    k_zrec<<<1124, 256>>>();
    k_wconv1<<<49, 128>>>(conv1_w);
    k_conv1t<<<dim3(4, 16, 16), 256, CONV1_SMEM>>>(conv1_b);

    // ---- recurrent prep ----
    k_zero<<<3200, 256>>>();
    k_wconv<<<dim3(225, 2), 256>>>(w_inh, w_exc);
    k_g1<<<128, 256>>>(u1_w, u1_b);                       // h=0 -> hg records

    // ---- recurrent scan, T = 8 (g1 fused into k_hnew) ----
    for (int t = 0; t < 8; t++) {
        k_conv15<<<dim3(4, 16, 2), 256, CONV15_SMEM>>>(0);
        k_ns1<<<128, 256>>>(t, alpha, mu, bn1_w, bn1_b);
        k_conv15<<<dim3(4, 16, 2), 256, CONV15_SMEM>>>(1);
        k_hnew<<<128, 256>>>(u2_w, u2_b, kappa, gamma_p, w_mix, bn3_w, bn3_b, u1_w, u1_b);
    }

    // ---- epilogue ----
    k_bnpart<<<dim3(25, 8), 256>>>(2);
    k_pool<<<128, 256>>>(bn_out_w, bn_out_b, fc4_w);
    k_final<<<1, 128>>>(fc4_b, out);
}

// round 16
// speedup vs baseline: 1.4297x; 1.1123x over previous
#include <cuda_runtime.h>
#include <cuda_fp16.h>
#include <math.h>

#define HW 16384   // 128*128
#define APITCH 144
#define APX (144*144)
#define XP 136
#define XPX (136*136)

// ---------------- scratch (device globals; no allocation allowed) ----------
static __device__ float g_z[2*8*HW];
static __device__ float g_y[8*2*25*HW];
static __device__ float g_h  [2*25*HW];
static __device__ float g_ns1[2*25*HW];
static __device__ float g_c1 [2*25*HW];
static __device__ float g_c2 [2*25*HW];
static __device__ float g_bpart[3][25][8][2];
static __device__ float g_cpart[2][25][128][2];
static __device__ float g_part[128*2];

// fp16 activation records (conv15): [n][apix] * 4 uint4
static __device__ uint4 g_hg[2*APX*4];
static __device__ uint4 g_ns[2*APX*4];
// fp16 weights, plane-packed B-fragment layout (conv15)
static __device__ uint4 g_wb[2][28800];
// conv00 records: [n][d][136*136] * 4 uint4, K slots = kd*3+ci (21 used)
static __device__ uint4 g_xr[16*XPX*4];
// conv00 weights: 49 taps x 128 uint4
static __device__ uint4 g_wb00[49*128];
// conv0 records (written by conv00t): [n][id][136*136] * 4 uint4, K = ci
static __device__ uint4 g_or[16*XPX*4];
// conv0 weights, d-as-N: [id][tap][s][lane] uint2
static __device__ uint2 g_wb0b[8*49*64];
// conv1 records: [n][d][136*136] * 2 uint4, K slots = kd (7 used of 16)
static __device__ uint4 g_zr[16*XPX*2];
// conv1 weights: 49 taps x 64 uint4
static __device__ uint4 g_wb1[49*64];

// ---------------- transcendentals (MUFU fast math — best measured) ---------
__device__ __forceinline__ float softplusf(float x) {
    return fmaxf(x, 0.f) + __logf(1.f + __expf(-fabsf(x)));
}
__device__ __forceinline__ float sigmoidf_(float x) {
    return 1.f / (1.f + __expf(-x));
}
__device__ __forceinline__ unsigned s2u(const void* p) {
    return (unsigned)__cvta_generic_to_shared(p);
}
__device__ __forceinline__ void ldm4(unsigned* r, unsigned addr) {
    asm volatile("ldmatrix.sync.aligned.m8n8.x4.shared.b16 {%0,%1,%2,%3}, [%4];"
                 : "=r"(r[0]), "=r"(r[1]), "=r"(r[2]), "=r"(r[3]) : "r"(addr));
}
__device__ __forceinline__ void mma16816(float* d, const unsigned* a, unsigned b0, unsigned b1) {
    asm volatile("mma.sync.aligned.m16n8k16.row.col.f32.f16.f16.f32 "
                 "{%0,%1,%2,%3}, {%4,%5,%6,%7}, {%8,%9}, {%0,%1,%2,%3};"
                 : "+f"(d[0]), "+f"(d[1]), "+f"(d[2]), "+f"(d[3])
                 : "r"(a[0]), "r"(a[1]), "r"(a[2]), "r"(a[3]), "r"(b0), "r"(b1));
}
__device__ __forceinline__ void cpa16(uint4* dst_smem, const uint4* src) {
    asm volatile("cp.async.cg.shared.global [%0], [%1], 16;"
                 :: "r"(s2u(dst_smem)), "l"(src));
}
#define CP_COMMIT() asm volatile("cp.async.commit_group;" ::: "memory")
#define CP_WAIT0()  asm volatile("cp.async.wait_group 0;" ::: "memory")
__device__ __forceinline__ unsigned short hbits(float v) {
    __half h = __float2half(v);
    return *reinterpret_cast<unsigned short*>(&h);
}

__device__ __forceinline__ void bn_finalize(int phase, int c, float* m_out, float* rs_out) {
    float s = 0.f, q = 0.f;
#pragma unroll
    for (int i = 0; i < 8; i++) {
        s += g_bpart[phase][c][i][0];
        q += g_bpart[phase][c][i][1];
    }
    float m = s * (1.f / 32768.f);
    *m_out = m;
    *rs_out = rsqrtf(q * (1.f / 32768.f) - m * m + 1e-3f);
}

__device__ __forceinline__ void bn_finalize_c(int phase, int c, float* m_out, float* rs_out) {
    float s = 0.f, q = 0.f;
#pragma unroll 8
    for (int i = 0; i < 128; i++) {
        s += g_cpart[phase][c][i][0];
        q += g_cpart[phase][c][i][1];
    }
    float m = s * (1.f / 32768.f);
    *m_out = m;
    *rs_out = rsqrtf(q * (1.f / 32768.f) - m * m + 1e-3f);
}

// ---------------------------------------------------------------------------
// prep: conv00 record builder + zero g_or (halo). grid 4624 x 256.
// ---------------------------------------------------------------------------
__global__ void k_prep(const float* __restrict__ x) {
    int idx = blockIdx.x * 256 + threadIdx.x;
    if (idx < 16 * XPX * 4) g_or[idx] = make_uint4(0u, 0u, 0u, 0u);
    if (idx >= 2 * 8 * 134 * 134) return;
    int rx = idx % 134; int t = idx / 134;
    int ry = t % 134; t /= 134;
    int d = t & 7, n = t >> 3;
    int py = ry - 3, px = rx - 3;
    bool inb = ((unsigned)py < 128u) && ((unsigned)px < 128u);

    unsigned rh[16];
#pragma unroll
    for (int i = 0; i < 16; i++) rh[i] = 0u;
    if (inb) {
#pragma unroll
        for (int kd = 0; kd < 7; kd++) {
            int dd = d + kd - 3;
            if ((unsigned)dd < 8u) {
#pragma unroll
                for (int ci = 0; ci < 3; ci++) {
                    float v = x[(size_t)((n * 3 + ci) * 8 + dd) * HW + py * 128 + px];
                    int slot = kd * 3 + ci;
                    rh[slot >> 1] |= (unsigned)hbits(v) << ((slot & 1) * 16);
                }
            }
        }
    }
    size_t ab = ((size_t)(n * 8 + d) * XPX + ry * XP + rx) * 4;
#pragma unroll
    for (int j = 0; j < 4; j++)
        g_xr[ab + j] = make_uint4(rh[4*j], rh[4*j+1], rh[4*j+2], rh[4*j+3]);
}

// ---------------------------------------------------------------------------
// front-end weight preconvert: y=0 -> conv00 (K=(kd,ci), N=oc);
// y=1..8 -> conv0 d-as-N (id = y-1): B[ci][d] = w0[ci][id-d+3][tap]
// ---------------------------------------------------------------------------
__global__ void k_wfront(const float* __restrict__ w00, const float* __restrict__ w0) {
    const int tap = blockIdx.x;
    if (blockIdx.y == 0) {
        const int tid = threadIdx.x;
        const int s = tid >> 7, lane = (tid >> 2) & 31, nt = tid & 3;
        const int oc = nt * 8 + (lane >> 2);
        const int cb = s * 16 + 2 * (lane & 3);
        const int slots[4] = {cb, cb + 1, cb + 8, cb + 9};
        ushort4 hrec;
        unsigned short* hp = (unsigned short*)&hrec;
#pragma unroll
        for (int j = 0; j < 4; j++) {
            float v = 0.f;
            int slot = slots[j];
            if (oc < 25 && slot < 21) {
                int kd = slot / 3, ci = slot % 3;
                v = w00[((oc * 3 + ci) * 7 + kd) * 49 + tap];
            }
            hp[j] = hbits(v);
        }
        size_t rec = (((size_t)(tap * 2 + s) * 2 + (nt >> 1)) * 32 + lane) * 2 + (nt & 1);
        ((ushort4*)g_wb00)[rec] = hrec;
    } else {
        if (threadIdx.x >= 64) return;
        const int id = blockIdx.y - 1;
        const int s = threadIdx.x >> 5, lane = threadIdx.x & 31;
        const int d = lane >> 2;
        const int cb = s * 16 + 2 * (lane & 3);
        const int slots[4] = {cb, cb + 1, cb + 8, cb + 9};
        const int kd = id - d + 3;
        ushort4 hrec;
        unsigned short* hp = (unsigned short*)&hrec;
#pragma unroll
        for (int j = 0; j < 4; j++) {
            float v = 0.f;
            int ci = slots[j];
            if (ci < 25 && kd >= 0 && kd <= 6) v = w0[ci * 343 + kd * 49 + tap];
            hp[j] = hbits(v);
        }
        ((ushort4*)g_wb0b)[((size_t)(id * 49 + tap) * 2 + s) * 32 + lane] = hrec;
    }
}

// ---------------------------------------------------------------------------
// conv00 via mma.sync fp16, epilogue writes g_or fp16 records directly.
// grid (4,16,16), 256 thr.
// ---------------------------------------------------------------------------
#define CONV00_SMEM 50560
__global__ __launch_bounds__(256) void k_conv00t() {
    extern __shared__ __align__(128) char smem[];
    uint4* sA = (uint4*)smem;
    uint4* sW = (uint4*)(smem + 21888);

    const int n = blockIdx.z >> 3, d = blockIdx.z & 7;
    const int x0 = blockIdx.x * 32, y0 = blockIdx.y * 8;
    const int tid = threadIdx.x, warp = tid >> 5, lane = tid & 31;

    const uint4* __restrict__ ga = g_xr + (size_t)(n * 8 + d) * XPX * 4;
    const uint4* __restrict__ gw = g_wb00;

    float acc[2][4][4];
#pragma unroll
    for (int h = 0; h < 2; h++)
#pragma unroll
        for (int nt = 0; nt < 4; nt++)
#pragma unroll
            for (int j = 0; j < 4; j++) acc[h][nt][j] = 0.f;

    const int lm = lane & 15, lk = lane >> 4;
    const unsigned aB = s2u(sA);

    for (int i = tid; i < 8 * 152; i += 256) {
        int r = i / 152, j = i % 152;
        int px = j >> 2, part = j & 3;
        int rec = r * 38 + px;
        int pos = (part + (rec >> 1)) & 3;
        cpa16(sA + rec * 4 + pos, ga + ((size_t)(y0 + r) * XP + x0 + px) * 4 + part);
    }
    for (int i = tid; i < 896; i += 256) cpa16(sW + i, gw + i);
    CP_COMMIT();

    for (int ky = 0; ky < 7; ky++) {
        CP_WAIT0();
        __syncthreads();
        if (ky < 6) {
            const int rel = ky + 8, slot = rel % 9;
            for (int i = tid; i < 152; i += 256) {
                int px = i >> 2, part = i & 3;
                int rec = slot * 38 + px;
                int pos = (part + (rec >> 1)) & 3;
                cpa16(sA + rec * 4 + pos, ga + ((size_t)(y0 + rel) * XP + x0 + px) * 4 + part);
            }
            uint4* wd = sW + ((ky + 1) & 1) * 896;
            for (int i = tid; i < 896; i += 256)
                cpa16(wd + i, gw + (ky + 1) * 896 + i);
            CP_COMMIT();
        }

        const uint4* sWb = sW + (ky & 1) * 896;
        const int rs = ((warp + ky) % 9) * 38;
#pragma unroll 1
        for (int kx = 0; kx < 7; kx++) {
            const int rec0 = rs + lm + kx, rec1 = rec0 + 16;
#pragma unroll
            for (int s = 0; s < 2; s++) {
                const int qbase = s * 2 + lk;
                unsigned a0 = aB + rec0 * 64 + (((qbase + (rec0 >> 1)) & 3) << 4);
                unsigned a1 = aB + rec1 * 64 + (((qbase + (rec1 >> 1)) & 3) << 4);
                unsigned f0[4], f1[4];
                ldm4(f0, a0);
                ldm4(f1, a1);
                const int wi = (kx * 2 + s) * 64 + lane;
                uint4 h01 = sWb[wi], h23 = sWb[wi + 32];
                mma16816(acc[0][0], f0, h01.x, h01.y);
                mma16816(acc[0][1], f0, h01.z, h01.w);
                mma16816(acc[0][2], f0, h23.x, h23.y);
                mma16816(acc[0][3], f0, h23.z, h23.w);
                mma16816(acc[1][0], f1, h01.x, h01.y);
                mma16816(acc[1][1], f1, h01.z, h01.w);
                mma16816(acc[1][2], f1, h23.x, h23.y);
                mma16816(acc[1][3], f1, h23.z, h23.w);
            }
        }
    }

    // epilogue: write fp16 records (oc pairs; oc=25 acc is exact 0 -> pad ok)
    const int y = y0 + warp;
    unsigned short* go = (unsigned short*)g_or;
#pragma unroll
    for (int h = 0; h < 2; h++) {
#pragma unroll
        for (int nt = 0; nt < 4; nt++) {
            int oc = nt * 8 + (lane & 3) * 2;
            if (oc < 25) {
                int xb = x0 + h * 16 + (lane >> 2);
                size_t rb0 = ((size_t)(n * 8 + d) * XPX + (size_t)(y + 3) * XP + (xb + 3)) * 32;
                __half2 v0 = __floats2half2_rn(acc[h][nt][0], acc[h][nt][1]);
                __half2 v2 = __floats2half2_rn(acc[h][nt][2], acc[h][nt][3]);
                *(__half2*)(go + rb0 + oc) = v0;
                *(__half2*)(go + rb0 + 8 * 32 + oc) = v2;
            }
        }
    }
}

// ---------------------------------------------------------------------------
// conv0 via mma.sync fp16, d-as-N: one CTA accumulates all 8 d over 8 id
// planes. grid (4,16,2), 256 thr. PROFILED (4th launch)
// W slab per ky = 7 kx x 2 s x 32 lanes = 448 uint2 = 224 uint4.
// ---------------------------------------------------------------------------
#define CONV0_SMEM 29056
__global__ __launch_bounds__(256) void k_conv0t() {
    extern __shared__ __align__(128) char smem[];
    uint4* sA = (uint4*)smem;                  // 9*38*4 uint4 = 21888 B
    uint2* sW = (uint2*)(smem + 21888);        // 2 bufs x 448 uint2 = 7168 B

    const int n = blockIdx.z;
    const int x0 = blockIdx.x * 32, y0 = blockIdx.y * 8;
    const int tid = threadIdx.x, warp = tid >> 5, lane = tid & 31;

    float acc[2][4];
#pragma unroll
    for (int h = 0; h < 2; h++)
#pragma unroll
        for (int j = 0; j < 4; j++) acc[h][j] = 0.f;

    const int lm = lane & 15, lk = lane >> 4;
    const unsigned aB = s2u(sA);

#pragma unroll 1
    for (int id = 0; id < 8; id++) {
        const uint4* __restrict__ ga = g_or + (size_t)(n * 8 + id) * XPX * 4;
        const uint4* __restrict__ gw = (const uint4*)g_wb0b + (size_t)(id * 49) * 32;

        __syncthreads();   // previous id reads complete before restaging
        // prologue for this id: 8 A rows + ky=0 W slab (224 uint4) into buf0
        for (int i = tid; i < 8 * 152; i += 256) {
            int r = i / 152, j = i % 152;
            int px = j >> 2, part = j & 3;
            int rec = r * 38 + px;
            int pos = (part + (rec >> 1)) & 3;
            cpa16(sA + rec * 4 + pos, ga + ((size_t)(y0 + r) * XP + x0 + px) * 4 + part);
        }
        for (int i = tid; i < 224; i += 256) cpa16((uint4*)sW + i, gw + i);
        CP_COMMIT();

        for (int ky = 0; ky < 7; ky++) {
            CP_WAIT0();
            __syncthreads();
            if (ky < 6) {
                const int rel = ky + 8, slot = rel % 9;
                for (int i = tid; i < 152; i += 256) {
                    int px = i >> 2, part = i & 3;
                    int rec = slot * 38 + px;
                    int pos = (part + (rec >> 1)) & 3;
                    cpa16(sA + rec * 4 + pos, ga + ((size_t)(y0 + rel) * XP + x0 + px) * 4 + part);
                }
                uint4* wd = (uint4*)sW + ((ky + 1) & 1) * 224;
                for (int i = tid; i < 224; i += 256)
                    cpa16(wd + i, gw + (ky + 1) * 224 + i);
                CP_COMMIT();
            }

            const uint2* sWb = sW + (ky & 1) * 448;
            const int rs = ((warp + ky) % 9) * 38;
#pragma unroll 1
            for (int kx = 0; kx < 7; kx++) {
                const int rec0 = rs + lm + kx, rec1 = rec0 + 16;
#pragma unroll
                for (int s = 0; s < 2; s++) {
                    const int qbase = s * 2 + lk;
                    unsigned a0 = aB + rec0 * 64 + (((qbase + (rec0 >> 1)) & 3) << 4);
                    unsigned a1 = aB + rec1 * 64 + (((qbase + (rec1 >> 1)) & 3) << 4);
                    unsigned f0[4], f1[4];
                    ldm4(f0, a0);
                    ldm4(f1, a1);
                    uint2 b = sWb[(kx * 2 + s) * 32 + lane];
                    mma16816(acc[0], f0, b.x, b.y);
                    mma16816(acc[1], f1, b.x, b.y);
                }
            }
        }
    }

    // epilogue: c0=(px, d0) c1=(px, d0+1) c2=(px+8, d0) c3=(px+8, d0+1)
    const int y = y0 + warp;
    const int d0 = (lane & 3) * 2;
#pragma unroll
    for (int h = 0; h < 2; h++) {
        int px = x0 + h * 16 + (lane >> 2);
        size_t b0 = (size_t)(n * 8 + d0) * HW + y * 128;
        g_z[b0 + px]          = acc[h][0];
        g_z[b0 + HW + px]     = acc[h][1];
        g_z[b0 + px + 8]      = acc[h][2];
        g_z[b0 + HW + px + 8] = acc[h][3];
    }
}

// ---------------------------------------------------------------------------
// conv1 record builder: g_z -> g_zr (16 fp16 slots: kd 0..6, pad 7..15)
// ---------------------------------------------------------------------------
__global__ void k_zrec() {
    int idx = blockIdx.x * 256 + threadIdx.x;
    if (idx >= 2 * 8 * 134 * 134) return;
    int rx = idx % 134; int t = idx / 134;
    int ry = t % 134; t /= 134;
    int d = t & 7, n = t >> 3;
    int py = ry - 3, px = rx - 3;
    bool inb = ((unsigned)py < 128u) && ((unsigned)px < 128u);

    unsigned rh[8];
#pragma unroll
    for (int i = 0; i < 8; i++) rh[i] = 0u;
    if (inb) {
#pragma unroll
        for (int kd = 0; kd < 7; kd++) {
            int dd = d + kd - 3;
            if ((unsigned)dd < 8u) {
                float v = g_z[(size_t)(n * 8 + dd) * HW + py * 128 + px];
                rh[kd >> 1] |= (unsigned)hbits(v) << ((kd & 1) * 16);
            }
        }
    }
    size_t ab = ((size_t)(n * 8 + d) * XPX + ry * XP + rx) * 2;
    g_zr[ab]     = make_uint4(rh[0], rh[1], rh[2], rh[3]);
    g_zr[ab + 1] = make_uint4(rh[4], rh[5], rh[6], rh[7]);
}

// ---------------------------------------------------------------------------
// conv1 weight preconvert
// ---------------------------------------------------------------------------
__global__ void k_wconv1(const float* __restrict__ w) {
    const int tap = blockIdx.x;
    const int tid = threadIdx.x;
    const int lane = (tid >> 2) & 31, nt = tid & 3;
    const int oc = nt * 8 + (lane >> 2);
    const int cb = 2 * (lane & 3);
    const int slots[4] = {cb, cb + 1, cb + 8, cb + 9};
    ushort4 hrec;
    unsigned short* hp = (unsigned short*)&hrec;
#pragma unroll
    for (int j = 0; j < 4; j++) {
        float v = 0.f;
        int slot = slots[j];
        if (oc < 25 && slot < 7) v = w[oc * 343 + slot * 49 + tap];
        hp[j] = hbits(v);
    }
    size_t rec = (((size_t)(tap * 2 + (nt >> 1)) * 32) + lane) * 2 + (nt & 1);
    ((ushort4*)g_wb1)[rec] = hrec;
}

// ---------------------------------------------------------------------------
// conv1 + bias + square via mma.sync fp16 (K=16). grid (4,16,16), 256 thr.
// ---------------------------------------------------------------------------
#define CONV1_SMEM 25408
__global__ __launch_bounds__(256) void k_conv1t(const float* __restrict__ bias) {
    extern __shared__ __align__(128) char smem[];
    uint4* sA = (uint4*)smem;
    uint4* sW = (uint4*)(smem + 10944);
    float* sBias = (float*)(smem + 25280);

    const int n = blockIdx.z >> 3, d = blockIdx.z & 7;
    const int x0 = blockIdx.x * 32, y0 = blockIdx.y * 8;
    const int tid = threadIdx.x, warp = tid >> 5, lane = tid & 31;

    const uint4* __restrict__ ga = g_zr + (size_t)(n * 8 + d) * XPX * 2;
    const uint4* __restrict__ gw = g_wb1;

    if (tid < 25) sBias[tid] = bias[tid];

    float acc[2][4][4];
#pragma unroll
    for (int h = 0; h < 2; h++)
#pragma unroll
        for (int nt = 0; nt < 4; nt++)
#pragma unroll
            for (int j = 0; j < 4; j++) acc[h][nt][j] = 0.f;

    const int lm = lane & 15, lk = lane >> 4;
    const unsigned aB = s2u(sA);

    for (int i = tid; i < 8 * 76; i += 256) {
        int r = i / 76, j = i % 76;
        int px = j >> 1, part = j & 1;
        int rec = r * 38 + px;
        int pos = (part + (rec >> 2)) & 1;
        cpa16(sA + rec * 2 + pos, ga + ((size_t)(y0 + r) * XP + x0 + px) * 2 + part);
    }
    for (int i = tid; i < 448; i += 256) cpa16(sW + i, gw + i);
    CP_COMMIT();

    for (int ky = 0; ky < 7; ky++) {
        CP_WAIT0();
        __syncthreads();
        if (ky < 6) {
            const int rel = ky + 8, slot = rel % 9;
            for (int i = tid; i < 76; i += 256) {
                int px = i >> 1, part = i & 1;
                int rec = slot * 38 + px;
                int pos = (part + (rec >> 2)) & 1;
                cpa16(sA + rec * 2 + pos, ga + ((size_t)(y0 + rel) * XP + x0 + px) * 2 + part);
            }
            uint4* wd = sW + ((ky + 1) & 1) * 448;
            for (int i = tid; i < 448; i += 256)
                cpa16(wd + i, gw + (ky + 1) * 448 + i);
            CP_COMMIT();
        }

        const uint4* sWb = sW + (ky & 1) * 448;
        const int rs = ((warp + ky) % 9) * 38;
#pragma unroll 1
        for (int kx = 0; kx < 7; kx++) {
            const int rec0 = rs + lm + kx, rec1 = rec0 + 16;
            unsigned a0 = aB + rec0 * 32 + (((lk + (rec0 >> 2)) & 1) << 4);
            unsigned a1 = aB + rec1 * 32 + (((lk + (rec1 >> 2)) & 1) << 4);
            unsigned f0[4], f1[4];
            ldm4(f0, a0);
            ldm4(f1, a1);
            const int wi = kx * 64 + lane;
            uint4 h01 = sWb[wi], h23 = sWb[wi + 32];
            mma16816(acc[0][0], f0, h01.x, h01.y);
            mma16816(acc[0][1], f0, h01.z, h01.w);
            mma16816(acc[0][2], f0, h23.x, h23.y);
            mma16816(acc[0][3], f0, h23.z, h23.w);
            mma16816(acc[1][0], f1, h01.x, h01.y);
            mma16816(acc[1][1], f1, h01.z, h01.w);
            mma16816(acc[1][2], f1, h23.x, h23.y);
            mma16816(acc[1][3], f1, h23.z, h23.w);
        }
    }

    const int y = y0 + warp;
#pragma unroll
    for (int h = 0; h < 2; h++) {
#pragma unroll
        for (int nt = 0; nt < 4; nt++) {
            int oc = nt * 8 + (lane & 3) * 2;
            int xb = x0 + h * 16 + (lane >> 2);
            if (oc < 25) {
                float b = sBias[oc];
                size_t ob = (size_t)((d * 2 + n) * 25 + oc) * HW + y * 128;
                float v0 = acc[h][nt][0] + b;
                float v2 = acc[h][nt][2] + b;
                g_y[ob + xb]     = v0 * v0;
                g_y[ob + xb + 8] = v2 * v2;
            }
            if (oc + 1 < 25) {
                float b = sBias[oc + 1];
                size_t ob = (size_t)((d * 2 + n) * 25 + oc + 1) * HW + y * 128;
                float v1 = acc[h][nt][1] + b;
                float v3 = acc[h][nt][3] + b;
                g_y[ob + xb]     = v1 * v1;
                g_y[ob + xb + 8] = v3 * v3;
            }
        }
    }
}

// ---------------------------------------------------------------------------
// conv15 weight preconvert
// ---------------------------------------------------------------------------
__global__ void k_wconv(const float* __restrict__ w_inh, const float* __restrict__ w_exc) {
    const int tap = blockIdx.x, pair = blockIdx.y;
    const float* w = pair ? w_exc : w_inh;
    const int tid = threadIdx.x;
    const int s = tid >> 7, lane = (tid >> 2) & 31, nt = tid & 3;
    const int oc = nt * 8 + (lane >> 2);
    const int cb = s * 16 + 2 * (lane & 3);
    const int cis[4] = {cb, cb + 1, cb + 8, cb + 9};
    ushort4 hrec;
    unsigned short* hp = (unsigned short*)&hrec;
#pragma unroll
    for (int j = 0; j < 4; j++) {
        float v = 0.f;
        int ci = cis[j];
        if (oc < 25 && ci < 25) v = w[(oc * 25 + ci) * 225 + tap];
        hp[j] = hbits(v);
    }
    size_t rec = (((size_t)(tap * 2 + s) * 2 + (nt >> 1)) * 32 + lane) * 2 + (nt & 1);
    ((ushort4*)g_wb[pair])[rec] = hrec;
}

// ---------------------------------------------------------------------------
// conv15 via mma.sync fp16, cp.async pipelined. grid (4,16,2), 256 thr.
// ---------------------------------------------------------------------------
#define CONV15_SMEM 87936
__global__ __launch_bounds__(256) void k_conv15(int phase) {
    extern __shared__ __align__(128) char smem[];
    uint4* sA = (uint4*)smem;
    uint4* sW = (uint4*)(smem + 26496);

    const int n = blockIdx.z;
    const int x0 = blockIdx.x * 32, y0 = blockIdx.y * 8;
    const int tid = threadIdx.x, warp = tid >> 5, lane = tid & 31;

    const uint4* __restrict__ ga = (phase ? g_ns : g_hg) + (size_t)n * APX * 4;
    const uint4* __restrict__ gw = g_wb[phase];
    float* __restrict__ out = phase ? g_c2 : g_c1;

    float acc[2][4][4];
#pragma unroll
    for (int h = 0; h < 2; h++)
#pragma unroll
        for (int nt = 0; nt < 4; nt++)
#pragma unroll
            for (int j = 0; j < 4; j++) acc[h][nt][j] = 0.f;

    const int lm = lane & 15, lk = lane >> 4;
    const unsigned aB = s2u(sA);

    for (int i = tid; i < 8 * 184; i += 256) {
        int r = i / 184, j = i % 184;
        int px = j >> 2, part = j & 3;
        int rec = r * 46 + px;
        int pos = (part + (rec >> 1)) & 3;
        cpa16(sA + rec * 4 + pos, ga + ((size_t)(y0 + r) * APITCH + x0 + px) * 4 + part);
    }
    for (int i = tid; i < 1920; i += 256) cpa16(sW + i, gw + i);
    CP_COMMIT();

    for (int ky = 0; ky < 15; ky++) {
        CP_WAIT0();
        __syncthreads();

        if (ky < 14) {
            const int rel = ky + 8, slot = rel % 9;
            for (int i = tid; i < 184; i += 256) {
                int px = i >> 2, part = i & 3;
                int rec = slot * 46 + px;
                int pos = (part + (rec >> 1)) & 3;
                cpa16(sA + rec * 4 + pos, ga + ((size_t)(y0 + rel) * APITCH + x0 + px) * 4 + part);
            }
            uint4* wd = sW + ((ky + 1) & 1) * 1920;
            for (int i = tid; i < 1920; i += 256)
                cpa16(wd + i, gw + (ky + 1) * 1920 + i);
            CP_COMMIT();
        }

        const uint4* sWb = sW + (ky & 1) * 1920;
        const int rs = ((warp + ky) % 9) * 46;
#pragma unroll 3
        for (int kx = 0; kx < 15; kx++) {
            const int rec0 = rs + lm + kx, rec1 = rec0 + 16;
#pragma unroll
            for (int s = 0; s < 2; s++) {
                const int qbase = s * 2 + lk;
                unsigned a0 = aB + rec0 * 64 + (((qbase + (rec0 >> 1)) & 3) << 4);
                unsigned a1 = aB + rec1 * 64 + (((qbase + (rec1 >> 1)) & 3) << 4);
                unsigned f0[4], f1[4];
                ldm4(f0, a0);
                ldm4(f1, a1);
                const int wi = (kx * 2 + s) * 64 + lane;
                uint4 h01 = sWb[wi], h23 = sWb[wi + 32];
                mma16816(acc[0][0], f0, h01.x, h01.y);
                mma16816(acc[0][1], f0, h01.z, h01.w);
                mma16816(acc[0][2], f0, h23.x, h23.y);
                mma16816(acc[0][3], f0, h23.z, h23.w);
                mma16816(acc[1][0], f1, h01.x, h01.y);
                mma16816(acc[1][1], f1, h01.z, h01.w);
                mma16816(acc[1][2], f1, h23.x, h23.y);
                mma16816(acc[1][3], f1, h23.z, h23.w);
            }
        }
    }

    const int y = y0 + warp;
#pragma unroll
    for (int h = 0; h < 2; h++) {
#pragma unroll
        for (int nt = 0; nt < 4; nt++) {
            int oc = nt * 8 + (lane & 3) * 2;
            int xb = x0 + h * 16 + (lane >> 2);
            if (oc < 25) {
                size_t ob = (size_t)(n * 25 + oc) * HW + y * 128;
                out[ob + xb]     = acc[h][nt][0];
                out[ob + xb + 8] = acc[h][nt][2];
            }
            if (oc + 1 < 25) {
                size_t ob = (size_t)(n * 25 + oc + 1) * HW + y * 128;
                out[ob + xb]     = acc[h][nt][1];
                out[ob + xb + 8] = acc[h][nt][3];
            }
        }
    }

    __syncthreads();
    float* sred = (float*)smem;
#pragma unroll
    for (int nt = 0; nt < 4; nt++) {
        float s0 = 0.f, q0 = 0.f, s1 = 0.f, q1 = 0.f;
#pragma unroll
        for (int h = 0; h < 2; h++) {
            float v;
            v = acc[h][nt][0]; s0 += v; q0 = fmaf(v, v, q0);
            v = acc[h][nt][2]; s0 += v; q0 = fmaf(v, v, q0);
            v = acc[h][nt][1]; s1 += v; q1 = fmaf(v, v, q1);
            v = acc[h][nt][3]; s1 += v; q1 = fmaf(v, v, q1);
        }
#pragma unroll
        for (int m = 4; m <= 16; m <<= 1) {
            s0 += __shfl_xor_sync(~0u, s0, m);
            q0 += __shfl_xor_sync(~0u, q0, m);
            s1 += __shfl_xor_sync(~0u, s1, m);
            q1 += __shfl_xor_sync(~0u, q1, m);
        }
        if (lane < 4) {
            int base = ((warp * 4 + nt) * 4 + lane) * 4;
            sred[base + 0] = s0;
            sred[base + 1] = q0;
            sred[base + 2] = s1;
            sred[base + 3] = q1;
        }
    }
    __syncthreads();
    if (tid < 25) {
        int nt = tid >> 3, rem = tid & 7, q = rem >> 1, par = rem & 1;
        float s = 0.f, qq = 0.f;
#pragma unroll
        for (int w = 0; w < 8; w++) {
            int base = ((w * 4 + nt) * 4 + q) * 4 + par * 2;
            s  += sred[base];
            qq += sred[base + 1];
        }
        int cta = (blockIdx.z * 16 + blockIdx.y) * 4 + blockIdx.x;
        g_cpart[phase][tid][cta][0] = s;
        g_cpart[phase][tid][cta][1] = qq;
    }
}

// ---------------------------------------------------------------------------
// BN partial statistics for final h
// ---------------------------------------------------------------------------
__global__ void k_bnpart(int phase) {
    const float* src = g_h;
    const int c = blockIdx.x, sl = blockIdx.y;
    float s = 0.f, q = 0.f;
#pragma unroll
    for (int k = 0; k < 16; k++) {
        int j = sl * 4096 + k * 256 + threadIdx.x;
        int nn = j >> 14, p = j & 16383;
        float v = src[(size_t)(nn * 25 + c) * HW + p];
        s += v;
        q = fmaf(v, v, q);
    }
    __shared__ float ss[256], sq[256];
    ss[threadIdx.x] = s; sq[threadIdx.x] = q;
    __syncthreads();
    for (int o = 128; o > 0; o >>= 1) {
        if (threadIdx.x < o) {
            ss[threadIdx.x] += ss[threadIdx.x + o];
            sq[threadIdx.x] += sq[threadIdx.x + o];
        }
        __syncthreads();
    }
    if (threadIdx.x == 0) {
        g_bpart[phase][c][sl][0] = ss[0];
        g_bpart[phase][c][sl][1] = sq[0];
    }
}

// ---------------------------------------------------------------------------
// g1 gate -> fp16 records (t = 0 only, h = 0)
// ---------------------------------------------------------------------------
__global__ void k_g1(const float* __restrict__ u1w, const float* __restrict__ u1b) {
    __shared__ float sw[625];
    __shared__ float sb[25];
    for (int t = threadIdx.x; t < 625; t += 256) sw[t] = u1w[t];
    if (threadIdx.x < 25) sb[threadIdx.x] = u1b[threadIdx.x];
    __syncthreads();

    const int gid = blockIdx.x * 256 + threadIdx.x;
    const int n = gid >> 14, p = gid & 16383;
    const int y = p >> 7, x = p & 127;
    float hv[25];
#pragma unroll
    for (int i = 0; i < 25; i++) hv[i] = g_h[(size_t)(n * 25 + i) * HW + p];

    unsigned rh[16];
#pragma unroll
    for (int i = 0; i < 16; i++) rh[i] = 0u;

#pragma unroll
    for (int c = 0; c < 25; c++) {
        float dot = sb[c];
#pragma unroll
        for (int i = 0; i < 25; i++) dot = fmaf(sw[c * 25 + i], hv[i], dot);
        float v = hv[c] * sigmoidf_(dot);
        rh[c >> 1] |= (unsigned)hbits(v) << ((c & 1) * 16);
    }
    size_t ab = ((size_t)n * APX + (y + 7) * APITCH + (x + 7)) * 4;
#pragma unroll
    for (int j = 0; j < 4; j++)
        g_hg[ab + j] = make_uint4(rh[4*j], rh[4*j+1], rh[4*j+2], rh[4*j+3]);
}

// ---------------------------------------------------------------------------
// ns1
// ---------------------------------------------------------------------------
__global__ void k_ns1(int t, const float* __restrict__ alpha, const float* __restrict__ mu,
                      const float* __restrict__ bn1w, const float* __restrict__ bn1b) {
    __shared__ float smn[25], srs[25], sa[25], smu[25], s1w[25], s1b[25];
    if (threadIdx.x < 25) {
        int c = threadIdx.x;
        bn_finalize_c(0, c, &smn[c], &srs[c]);
        sa[c] = alpha[c]; smu[c] = mu[c]; s1w[c] = bn1w[c]; s1b[c] = bn1b[c];
    }
    __syncthreads();

    const int gid = blockIdx.x * 256 + threadIdx.x;
    const int n = gid >> 14, p = gid & 16383;
    const int y = p >> 7, x = p & 127;

    unsigned rh[16];
#pragma unroll
    for (int i = 0; i < 16; i++) rh[i] = 0u;

#pragma unroll
    for (int c = 0; c < 25; c++) {
        size_t a = (size_t)(n * 25 + c) * HW + p;
        float c1 = (g_c1[a] - smn[c]) * srs[c] * s1w[c] + s1b[c];
        float h = g_h[a];
        float yv = g_y[(size_t)t * (2 * 25 * HW) + a];
        float ns = softplusf(yv - softplusf(c1 * fmaf(sa[c], h, smu[c])));
        g_ns1[a] = ns;
        rh[c >> 1] |= (unsigned)hbits(ns) << ((c & 1) * 16);
    }
    size_t ab = ((size_t)n * APX + (y + 7) * APITCH + (x + 7)) * 4;
#pragma unroll
    for (int j = 0; j < 4; j++)
        g_ns[ab + j] = make_uint4(rh[4*j], rh[4*j+1], rh[4*j+2], rh[4*j+3]);
}

// ---------------------------------------------------------------------------
// h update, fused with NEXT step's g1 gate
// ---------------------------------------------------------------------------
__global__ void k_hnew(const float* __restrict__ u2w, const float* __restrict__ u2b,
                       const float* __restrict__ kappa, const float* __restrict__ gammap,
                       const float* __restrict__ wmix,
                       const float* __restrict__ bn3w, const float* __restrict__ bn3b,
                       const float* __restrict__ u1w, const float* __restrict__ u1b) {
    __shared__ float sw2[625], sw1[625];
    __shared__ float sb[25], sk[25], sg[25], sm_[25], s3w[25], s3b[25], s1b[25];
    __shared__ float smn[25], srs[25];
    for (int t = threadIdx.x; t < 625; t += 256) { sw2[t] = u2w[t]; sw1[t] = u1w[t]; }
    if (threadIdx.x < 25) {
        int c = threadIdx.x;
        sb[c]  = u2b[c];
        sk[c]  = kappa[c];
        sg[c]  = gammap[c];
        sm_[c] = wmix[c];
        s3w[c] = bn3w[c];
        s3b[c] = bn3b[c];
        s1b[c] = u1b[c];
        bn_finalize_c(1, c, &smn[c], &srs[c]);
    }
    __syncthreads();

    const int gid = blockIdx.x * 256 + threadIdx.x;
    const int n = gid >> 14, p = gid & 16383;
    const int y = p >> 7, x = p & 127;
    float nv[25], hn[25];
#pragma unroll
    for (int i = 0; i < 25; i++) nv[i] = g_ns1[(size_t)(n * 25 + i) * HW + p];
#pragma unroll
    for (int c = 0; c < 25; c++) {
        float dot = sb[c];
#pragma unroll
        for (int i = 0; i < 25; i++) dot = fmaf(sw2[c * 25 + i], nv[i], dot);
        float g2 = sigmoidf_(dot);
        size_t a = (size_t)(n * 25 + c) * HW + p;
        float c2n = (g_c2[a] - smn[c]) * srs[c] * s3w[c] + s3b[c];
        float h2 = softplusf(sk[c] * nv[c] + sg[c] * c2n + sm_[c] * nv[c] * c2n);
        float hold = g_h[a];
        float hnw = softplusf((1.f - g2) * hold + g2 * h2);
        hn[c] = hnw;
        g_h[a] = hnw;
    }
    unsigned rh[16];
#pragma unroll
    for (int i = 0; i < 16; i++) rh[i] = 0u;
#pragma unroll
    for (int c = 0; c < 25; c++) {
        float dot = s1b[c];
#pragma unroll
        for (int i = 0; i < 25; i++) dot = fmaf(sw1[c * 25 + i], hn[i], dot);
        float v = hn[c] * sigmoidf_(dot);
        rh[c >> 1] |= (unsigned)hbits(v) << ((c & 1) * 16);
    }
    size_t ab = ((size_t)n * APX + (y + 7) * APITCH + (x + 7)) * 4;
#pragma unroll
    for (int j = 0; j < 4; j++)
        g_hg[ab + j] = make_uint4(rh[4*j], rh[4*j+1], rh[4*j+2], rh[4*j+3]);
}

// ---------------------------------------------------------------------------
__global__ void k_zero() {
    int idx = blockIdx.x * 256 + threadIdx.x;
    if (idx < 2 * 25 * HW) g_h[idx] = 0.f;
    if (idx < 2 * APX * 4) {
        const uint4 z = make_uint4(0u, 0u, 0u, 0u);
        g_hg[idx] = z;
        g_ns[idx] = z;
    }
}

// ---------------------------------------------------------------------------
// Epilogue
// ---------------------------------------------------------------------------
__global__ void k_pool(const float* __restrict__ bnow, const float* __restrict__ bnob,
                       const float* __restrict__ fcw) {
    __shared__ float smn[25], srs[25];
    if (threadIdx.x < 25) bn_finalize(2, threadIdx.x, &smn[threadIdx.x], &srs[threadIdx.x]);
    __syncthreads();
    const int gid = blockIdx.x * 256 + threadIdx.x;
    float p0 = 0.f, p1 = 0.f;
    for (int m = gid; m < 204800; m += 32768) {
        int n = m / 102400;
        int r = m % 102400;
        int c = r >> 12;
        int q = r & 4095;
        int i = q >> 6, j = q & 63;
        size_t base = (size_t)(n * 25 + c) * HW + (size_t)(i * 2) * 128 + j * 2;
        float s4 = g_h[base] + g_h[base + 1] + g_h[base + 128] + g_h[base + 129];
        float val = (0.25f * s4 - smn[c]) * srs[c] * bnow[c] + bnob[c];
        p0 = fmaf(val, fcw[m], p0);
        p1 = fmaf(val, fcw[204800 + m], p1);
    }
    __shared__ float s0[256], s1[256];
    s0[threadIdx.x] = p0; s1[threadIdx.x] = p1;
    __syncthreads();
    for (int o = 128; o > 0; o >>= 1) {
        if (threadIdx.x < o) {
            s0[threadIdx.x] += s0[threadIdx.x + o];
            s1[threadIdx.x] += s1[threadIdx.x + o];
        }
        __syncthreads();
    }
    if (threadIdx.x == 0) {
        g_part[blockIdx.x * 2]     = s0[0];
        g_part[blockIdx.x * 2 + 1] = s1[0];
    }
}

__global__ void k_final(const float* __restrict__ fcb, float* __restrict__ out) {
    __shared__ float s0[128], s1[128];
    s0[threadIdx.x] = g_part[threadIdx.x * 2];
    s1[threadIdx.x] = g_part[threadIdx.x * 2 + 1];
    __syncthreads();
    for (int o = 64; o > 0; o >>= 1) {
        if (threadIdx.x < o) {
            s0[threadIdx.x] += s0[threadIdx.x + o];
            s1[threadIdx.x] += s1[threadIdx.x + o];
        }
        __syncthreads();
    }
    if (threadIdx.x == 0) {
        out[0] = sigmoidf_(s0[0] + fcb[0]);
        out[1] = sigmoidf_(s1[0] + fcb[1]);
    }
}

// ---------------------------------------------------------------------------
extern "C" void kernel_launch(void* const* d_in, const int* in_sizes, int n_in,
                              void* d_out, int out_size) {
    const float* x        = (const float*)d_in[0];
    const float* conv00_w = (const float*)d_in[1];
    const float* conv0_w  = (const float*)d_in[2];
    const float* conv1_w  = (const float*)d_in[3];
    const float* conv1_b  = (const float*)d_in[4];
    const float* u1_w     = (const float*)d_in[5];
    const float* u1_b     = (const float*)d_in[6];
    const float* u2_w     = (const float*)d_in[7];
    const float* u2_b     = (const float*)d_in[8];
    const float* w_inh    = (const float*)d_in[9];
    const float* w_exc    = (const float*)d_in[10];
    const float* alpha    = (const float*)d_in[11];
    const float* mu       = (const float*)d_in[12];
    const float* gamma_p  = (const float*)d_in[13];
    const float* kappa    = (const float*)d_in[14];
    const float* w_mix    = (const float*)d_in[15];
    const float* bn1_w    = (const float*)d_in[16];
    const float* bn1_b    = (const float*)d_in[17];
    const float* bn3_w    = (const float*)d_in[18];
    const float* bn3_b    = (const float*)d_in[19];
    const float* bn_out_w = (const float*)d_in[20];
    const float* bn_out_b = (const float*)d_in[21];
    const float* fc4_w    = (const float*)d_in[22];
    const float* fc4_b    = (const float*)d_in[23];
    float* out = (float*)d_out;

    cudaFuncSetAttribute(k_conv15, cudaFuncAttributeMaxDynamicSharedMemorySize, CONV15_SMEM);
    cudaFuncSetAttribute(k_conv00t, cudaFuncAttributeMaxDynamicSharedMemorySize, CONV00_SMEM);

    // ---- 3D conv front-end (4th launch = k_conv0t -> PROFILED) ----
    k_prep<<<4624, 256>>>(x);
    k_wfront<<<dim3(49, 9), 256>>>(conv00_w, conv0_w);
    k_conv00t<<<dim3(4, 16, 16), 256, CONV00_SMEM>>>();
    k_conv0t<<<dim3(4, 16, 2), 256, CONV0_SMEM>>>();      // PROFILED
    k_zrec<<<1124, 256>>>();
    k_wconv1<<<49, 128>>>(conv1_w);
    k_conv1t<<<dim3(4, 16, 16), 256, CONV1_SMEM>>>(conv1_b);

    // ---- recurrent prep ----
    k_zero<<<3200, 256>>>();
    k_wconv<<<dim3(225, 2), 256>>>(w_inh, w_exc);
    k_g1<<<128, 256>>>(u1_w, u1_b);                       // h=0 -> hg records

    // ---- recurrent scan, T = 8 (g1 fused into k_hnew) ----
    for (int t = 0; t < 8; t++) {
        k_conv15<<<dim3(4, 16, 2), 256, CONV15_SMEM>>>(0);
        k_ns1<<<128, 256>>>(t, alpha, mu, bn1_w, bn1_b);
        k_conv15<<<dim3(4, 16, 2), 256, CONV15_SMEM>>>(1);
        k_hnew<<<128, 256>>>(u2_w, u2_b, kappa, gamma_p, w_mix, bn3_w, bn3_b, u1_w, u1_b);
    }

    // ---- epilogue ----
    k_bnpart<<<dim3(25, 8), 256>>>(2);
    k_pool<<<128, 256>>>(bn_out_w, bn_out_b, fc4_w);
    k_final<<<1, 128>>>(fc4_b, out);
}

// round 17
// speedup vs baseline: 1.4556x; 1.0180x over previous
#include <cuda_runtime.h>
#include <cuda_fp16.h>
#include <math.h>

#define HW 16384   // 128*128
#define APITCH 144
#define APX (144*144)
#define XP 136
#define XPX (136*136)

// ---------------- scratch (device globals; no allocation allowed) ----------
static __device__ float g_z [2*8*HW];
static __device__ float g_z2[2*8*HW];
static __device__ float g_y[8*2*25*HW];
static __device__ float g_h  [2*25*HW];
static __device__ float g_ns1[2*25*HW];
static __device__ float g_c1 [2*25*HW];
static __device__ float g_c2 [2*25*HW];
static __device__ float g_bpart[3][25][8][2];
static __device__ float g_cpart[2][25][128][2];
static __device__ float g_part[128*2];

// fp16 activation records (conv15): [n][apix] * 4 uint4
static __device__ uint4 g_hg[2*APX*4];
static __device__ uint4 g_ns[2*APX*4];
// fp16 weights, plane-packed B-fragment layout (conv15)
static __device__ uint4 g_wb[2][28800];
// conv00 records: [n][d][136*136] * 4 uint4, K slots = kd*3+ci (21 used)
static __device__ uint4 g_xr[16*XPX*4];
// conv00 weights: 49 taps x 128 uint4
static __device__ uint4 g_wb00[49*128];
// conv0 records (written by conv00t): [n][id][136*136] * 4 uint4, K = ci
static __device__ uint4 g_or[16*XPX*4];
// conv0 weights, d-as-N: [id][tap][s][lane] uint2
static __device__ uint2 g_wb0b[8*49*64];
// conv1 records: [n][d][136*136] * 2 uint4, K slots = kd (7 used of 16)
static __device__ uint4 g_zr[16*XPX*2];
// conv1 weights: 49 taps x 64 uint4
static __device__ uint4 g_wb1[49*64];

// ---------------- transcendentals (MUFU fast math — best measured) ---------
__device__ __forceinline__ float softplusf(float x) {
    return fmaxf(x, 0.f) + __logf(1.f + __expf(-fabsf(x)));
}
__device__ __forceinline__ float sigmoidf_(float x) {
    return 1.f / (1.f + __expf(-x));
}
__device__ __forceinline__ unsigned s2u(const void* p) {
    return (unsigned)__cvta_generic_to_shared(p);
}
__device__ __forceinline__ void ldm4(unsigned* r, unsigned addr) {
    asm volatile("ldmatrix.sync.aligned.m8n8.x4.shared.b16 {%0,%1,%2,%3}, [%4];"
                 : "=r"(r[0]), "=r"(r[1]), "=r"(r[2]), "=r"(r[3]) : "r"(addr));
}
__device__ __forceinline__ void mma16816(float* d, const unsigned* a, unsigned b0, unsigned b1) {
    asm volatile("mma.sync.aligned.m16n8k16.row.col.f32.f16.f16.f32 "
                 "{%0,%1,%2,%3}, {%4,%5,%6,%7}, {%8,%9}, {%0,%1,%2,%3};"
                 : "+f"(d[0]), "+f"(d[1]), "+f"(d[2]), "+f"(d[3])
                 : "r"(a[0]), "r"(a[1]), "r"(a[2]), "r"(a[3]), "r"(b0), "r"(b1));
}
__device__ __forceinline__ void cpa16(uint4* dst_smem, const uint4* src) {
    asm volatile("cp.async.cg.shared.global [%0], [%1], 16;"
                 :: "r"(s2u(dst_smem)), "l"(src));
}
#define CP_COMMIT() asm volatile("cp.async.commit_group;" ::: "memory")
#define CP_WAIT0()  asm volatile("cp.async.wait_group 0;" ::: "memory")
__device__ __forceinline__ unsigned short hbits(float v) {
    __half h = __float2half(v);
    return *reinterpret_cast<unsigned short*>(&h);
}

__device__ __forceinline__ void bn_finalize(int phase, int c, float* m_out, float* rs_out) {
    float s = 0.f, q = 0.f;
#pragma unroll
    for (int i = 0; i < 8; i++) {
        s += g_bpart[phase][c][i][0];
        q += g_bpart[phase][c][i][1];
    }
    float m = s * (1.f / 32768.f);
    *m_out = m;
    *rs_out = rsqrtf(q * (1.f / 32768.f) - m * m + 1e-3f);
}

__device__ __forceinline__ void bn_finalize_c(int phase, int c, float* m_out, float* rs_out) {
    float s = 0.f, q = 0.f;
#pragma unroll 8
    for (int i = 0; i < 128; i++) {
        s += g_cpart[phase][c][i][0];
        q += g_cpart[phase][c][i][1];
    }
    float m = s * (1.f / 32768.f);
    *m_out = m;
    *rs_out = rsqrtf(q * (1.f / 32768.f) - m * m + 1e-3f);
}

// ---------------------------------------------------------------------------
// prep: conv00 record builder + zero g_or halo + zero h / hg / ns.
// grid 4624 x 256 (1.18M threads).
// ---------------------------------------------------------------------------
__global__ void k_prep(const float* __restrict__ x) {
    int idx = blockIdx.x * 256 + threadIdx.x;
    const uint4 z4 = make_uint4(0u, 0u, 0u, 0u);
    if (idx < 16 * XPX * 4) g_or[idx] = z4;
    if (idx < 2 * APX * 4) { g_hg[idx] = z4; g_ns[idx] = z4; }
    if (idx < 2 * 25 * HW / 4) ((uint4*)g_h)[idx] = z4;
    if (idx >= 2 * 8 * 134 * 134) return;
    int rx = idx % 134; int t = idx / 134;
    int ry = t % 134; t /= 134;
    int d = t & 7, n = t >> 3;
    int py = ry - 3, px = rx - 3;
    bool inb = ((unsigned)py < 128u) && ((unsigned)px < 128u);

    unsigned rh[16];
#pragma unroll
    for (int i = 0; i < 16; i++) rh[i] = 0u;
    if (inb) {
#pragma unroll
        for (int kd = 0; kd < 7; kd++) {
            int dd = d + kd - 3;
            if ((unsigned)dd < 8u) {
#pragma unroll
                for (int ci = 0; ci < 3; ci++) {
                    float v = x[(size_t)((n * 3 + ci) * 8 + dd) * HW + py * 128 + px];
                    int slot = kd * 3 + ci;
                    rh[slot >> 1] |= (unsigned)hbits(v) << ((slot & 1) * 16);
                }
            }
        }
    }
    size_t ab = ((size_t)(n * 8 + d) * XPX + ry * XP + rx) * 4;
#pragma unroll
    for (int j = 0; j < 4; j++)
        g_xr[ab + j] = make_uint4(rh[4*j], rh[4*j+1], rh[4*j+2], rh[4*j+3]);
}

// ---------------------------------------------------------------------------
// front-end weight preconvert: y=0 -> conv00 (K=(kd,ci), N=oc);
// y=1..8 -> conv0 d-as-N (id = y-1): B[ci][d] = w0[ci][id-d+3][tap]
// ---------------------------------------------------------------------------
__global__ void k_wfront(const float* __restrict__ w00, const float* __restrict__ w0) {
    const int tap = blockIdx.x;
    if (blockIdx.y == 0) {
        const int tid = threadIdx.x;
        const int s = tid >> 7, lane = (tid >> 2) & 31, nt = tid & 3;
        const int oc = nt * 8 + (lane >> 2);
        const int cb = s * 16 + 2 * (lane & 3);
        const int slots[4] = {cb, cb + 1, cb + 8, cb + 9};
        ushort4 hrec;
        unsigned short* hp = (unsigned short*)&hrec;
#pragma unroll
        for (int j = 0; j < 4; j++) {
            float v = 0.f;
            int slot = slots[j];
            if (oc < 25 && slot < 21) {
                int kd = slot / 3, ci = slot % 3;
                v = w00[((oc * 3 + ci) * 7 + kd) * 49 + tap];
            }
            hp[j] = hbits(v);
        }
        size_t rec = (((size_t)(tap * 2 + s) * 2 + (nt >> 1)) * 32 + lane) * 2 + (nt & 1);
        ((ushort4*)g_wb00)[rec] = hrec;
    } else {
        if (threadIdx.x >= 64) return;
        const int id = blockIdx.y - 1;
        const int s = threadIdx.x >> 5, lane = threadIdx.x & 31;
        const int d = lane >> 2;
        const int cb = s * 16 + 2 * (lane & 3);
        const int slots[4] = {cb, cb + 1, cb + 8, cb + 9};
        const int kd = id - d + 3;
        ushort4 hrec;
        unsigned short* hp = (unsigned short*)&hrec;
#pragma unroll
        for (int j = 0; j < 4; j++) {
            float v = 0.f;
            int ci = slots[j];
            if (ci < 25 && kd >= 0 && kd <= 6) v = w0[ci * 343 + kd * 49 + tap];
            hp[j] = hbits(v);
        }
        ((ushort4*)g_wb0b)[((size_t)(id * 49 + tap) * 2 + s) * 32 + lane] = hrec;
    }
}

// ---------------------------------------------------------------------------
// conv00 via mma.sync fp16, epilogue writes g_or fp16 records directly.
// grid (4,16,16), 256 thr. PROFILED (4th launch)
// ---------------------------------------------------------------------------
#define CONV00_SMEM 50560
__global__ __launch_bounds__(256) void k_conv00t() {
    extern __shared__ __align__(128) char smem[];
    uint4* sA = (uint4*)smem;
    uint4* sW = (uint4*)(smem + 21888);

    const int n = blockIdx.z >> 3, d = blockIdx.z & 7;
    const int x0 = blockIdx.x * 32, y0 = blockIdx.y * 8;
    const int tid = threadIdx.x, warp = tid >> 5, lane = tid & 31;

    const uint4* __restrict__ ga = g_xr + (size_t)(n * 8 + d) * XPX * 4;
    const uint4* __restrict__ gw = g_wb00;

    float acc[2][4][4];
#pragma unroll
    for (int h = 0; h < 2; h++)
#pragma unroll
        for (int nt = 0; nt < 4; nt++)
#pragma unroll
            for (int j = 0; j < 4; j++) acc[h][nt][j] = 0.f;

    const int lm = lane & 15, lk = lane >> 4;
    const unsigned aB = s2u(sA);

    for (int i = tid; i < 8 * 152; i += 256) {
        int r = i / 152, j = i % 152;
        int px = j >> 2, part = j & 3;
        int rec = r * 38 + px;
        int pos = (part + (rec >> 1)) & 3;
        cpa16(sA + rec * 4 + pos, ga + ((size_t)(y0 + r) * XP + x0 + px) * 4 + part);
    }
    for (int i = tid; i < 896; i += 256) cpa16(sW + i, gw + i);
    CP_COMMIT();

    for (int ky = 0; ky < 7; ky++) {
        CP_WAIT0();
        __syncthreads();
        if (ky < 6) {
            const int rel = ky + 8, slot = rel % 9;
            for (int i = tid; i < 152; i += 256) {
                int px = i >> 2, part = i & 3;
                int rec = slot * 38 + px;
                int pos = (part + (rec >> 1)) & 3;
                cpa16(sA + rec * 4 + pos, ga + ((size_t)(y0 + rel) * XP + x0 + px) * 4 + part);
            }
            uint4* wd = sW + ((ky + 1) & 1) * 896;
            for (int i = tid; i < 896; i += 256)
                cpa16(wd + i, gw + (ky + 1) * 896 + i);
            CP_COMMIT();
        }

        const uint4* sWb = sW + (ky & 1) * 896;
        const int rs = ((warp + ky) % 9) * 38;
#pragma unroll 1
        for (int kx = 0; kx < 7; kx++) {
            const int rec0 = rs + lm + kx, rec1 = rec0 + 16;
#pragma unroll
            for (int s = 0; s < 2; s++) {
                const int qbase = s * 2 + lk;
                unsigned a0 = aB + rec0 * 64 + (((qbase + (rec0 >> 1)) & 3) << 4);
                unsigned a1 = aB + rec1 * 64 + (((qbase + (rec1 >> 1)) & 3) << 4);
                unsigned f0[4], f1[4];
                ldm4(f0, a0);
                ldm4(f1, a1);
                const int wi = (kx * 2 + s) * 64 + lane;
                uint4 h01 = sWb[wi], h23 = sWb[wi + 32];
                mma16816(acc[0][0], f0, h01.x, h01.y);
                mma16816(acc[0][1], f0, h01.z, h01.w);
                mma16816(acc[0][2], f0, h23.x, h23.y);
                mma16816(acc[0][3], f0, h23.z, h23.w);
                mma16816(acc[1][0], f1, h01.x, h01.y);
                mma16816(acc[1][1], f1, h01.z, h01.w);
                mma16816(acc[1][2], f1, h23.x, h23.y);
                mma16816(acc[1][3], f1, h23.z, h23.w);
            }
        }
    }

    // epilogue: write fp16 records (oc pairs; oc=25 acc is exact 0 -> pad ok)
    const int y = y0 + warp;
    unsigned short* go = (unsigned short*)g_or;
#pragma unroll
    for (int h = 0; h < 2; h++) {
#pragma unroll
        for (int nt = 0; nt < 4; nt++) {
            int oc = nt * 8 + (lane & 3) * 2;
            if (oc < 25) {
                int xb = x0 + h * 16 + (lane >> 2);
                size_t rb0 = ((size_t)(n * 8 + d) * XPX + (size_t)(y + 3) * XP + (xb + 3)) * 32;
                __half2 v0 = __floats2half2_rn(acc[h][nt][0], acc[h][nt][1]);
                __half2 v2 = __floats2half2_rn(acc[h][nt][2], acc[h][nt][3]);
                *(__half2*)(go + rb0 + oc) = v0;
                *(__half2*)(go + rb0 + 8 * 32 + oc) = v2;
            }
        }
    }
}

// ---------------------------------------------------------------------------
// conv0 via mma.sync fp16, d-as-N, split over id halves (4 ids per CTA).
// grid (4,16,4): z = n*2 + half. half 0 -> g_z, half 1 -> g_z2.
// W slab per ky = 448 uint2 = 224 uint4.
// ---------------------------------------------------------------------------
#define CONV0_SMEM 29056
__global__ __launch_bounds__(256) void k_conv0t() {
    extern __shared__ __align__(128) char smem[];
    uint4* sA = (uint4*)smem;                  // 9*38*4 uint4 = 21888 B
    uint2* sW = (uint2*)(smem + 21888);        // 2 bufs x 448 uint2 = 7168 B

    const int n = blockIdx.z >> 1, half = blockIdx.z & 1;
    const int x0 = blockIdx.x * 32, y0 = blockIdx.y * 8;
    const int tid = threadIdx.x, warp = tid >> 5, lane = tid & 31;

    float acc[2][4];
#pragma unroll
    for (int h = 0; h < 2; h++)
#pragma unroll
        for (int j = 0; j < 4; j++) acc[h][j] = 0.f;

    const int lm = lane & 15, lk = lane >> 4;
    const unsigned aB = s2u(sA);

#pragma unroll 1
    for (int id = half * 4; id < half * 4 + 4; id++) {
        const uint4* __restrict__ ga = g_or + (size_t)(n * 8 + id) * XPX * 4;
        const uint4* __restrict__ gw = (const uint4*)g_wb0b + (size_t)(id * 49) * 32;

        __syncthreads();   // previous id reads complete before restaging
        for (int i = tid; i < 8 * 152; i += 256) {
            int r = i / 152, j = i % 152;
            int px = j >> 2, part = j & 3;
            int rec = r * 38 + px;
            int pos = (part + (rec >> 1)) & 3;
            cpa16(sA + rec * 4 + pos, ga + ((size_t)(y0 + r) * XP + x0 + px) * 4 + part);
        }
        for (int i = tid; i < 224; i += 256) cpa16((uint4*)sW + i, gw + i);
        CP_COMMIT();

        for (int ky = 0; ky < 7; ky++) {
            CP_WAIT0();
            __syncthreads();
            if (ky < 6) {
                const int rel = ky + 8, slot = rel % 9;
                for (int i = tid; i < 152; i += 256) {
                    int px = i >> 2, part = i & 3;
                    int rec = slot * 38 + px;
                    int pos = (part + (rec >> 1)) & 3;
                    cpa16(sA + rec * 4 + pos, ga + ((size_t)(y0 + rel) * XP + x0 + px) * 4 + part);
                }
                uint4* wd = (uint4*)sW + ((ky + 1) & 1) * 224;
                for (int i = tid; i < 224; i += 256)
                    cpa16(wd + i, gw + (ky + 1) * 224 + i);
                CP_COMMIT();
            }

            const uint2* sWb = sW + (ky & 1) * 448;
            const int rs = ((warp + ky) % 9) * 38;
#pragma unroll 1
            for (int kx = 0; kx < 7; kx++) {
                const int rec0 = rs + lm + kx, rec1 = rec0 + 16;
#pragma unroll
                for (int s = 0; s < 2; s++) {
                    const int qbase = s * 2 + lk;
                    unsigned a0 = aB + rec0 * 64 + (((qbase + (rec0 >> 1)) & 3) << 4);
                    unsigned a1 = aB + rec1 * 64 + (((qbase + (rec1 >> 1)) & 3) << 4);
                    unsigned f0[4], f1[4];
                    ldm4(f0, a0);
                    ldm4(f1, a1);
                    uint2 b = sWb[(kx * 2 + s) * 32 + lane];
                    mma16816(acc[0], f0, b.x, b.y);
                    mma16816(acc[1], f1, b.x, b.y);
                }
            }
        }
    }

    // epilogue: c0=(px, d0) c1=(px, d0+1) c2=(px+8, d0) c3=(px+8, d0+1)
    float* zo = half ? g_z2 : g_z;
    const int y = y0 + warp;
    const int d0 = (lane & 3) * 2;
#pragma unroll
    for (int h = 0; h < 2; h++) {
        int px = x0 + h * 16 + (lane >> 2);
        size_t b0 = (size_t)(n * 8 + d0) * HW + y * 128;
        zo[b0 + px]          = acc[h][0];
        zo[b0 + HW + px]     = acc[h][1];
        zo[b0 + px + 8]      = acc[h][2];
        zo[b0 + HW + px + 8] = acc[h][3];
    }
}

// ---------------------------------------------------------------------------
// conv1 record builder: g_z + g_z2 -> g_zr (16 fp16 slots: kd 0..6, pad)
// ---------------------------------------------------------------------------
__global__ void k_zrec() {
    int idx = blockIdx.x * 256 + threadIdx.x;
    if (idx >= 2 * 8 * 134 * 134) return;
    int rx = idx % 134; int t = idx / 134;
    int ry = t % 134; t /= 134;
    int d = t & 7, n = t >> 3;
    int py = ry - 3, px = rx - 3;
    bool inb = ((unsigned)py < 128u) && ((unsigned)px < 128u);

    unsigned rh[8];
#pragma unroll
    for (int i = 0; i < 8; i++) rh[i] = 0u;
    if (inb) {
#pragma unroll
        for (int kd = 0; kd < 7; kd++) {
            int dd = d + kd - 3;
            if ((unsigned)dd < 8u) {
                size_t a = (size_t)(n * 8 + dd) * HW + py * 128 + px;
                float v = g_z[a] + g_z2[a];
                rh[kd >> 1] |= (unsigned)hbits(v) << ((kd & 1) * 16);
            }
        }
    }
    size_t ab = ((size_t)(n * 8 + d) * XPX + ry * XP + rx) * 2;
    g_zr[ab]     = make_uint4(rh[0], rh[1], rh[2], rh[3]);
    g_zr[ab + 1] = make_uint4(rh[4], rh[5], rh[6], rh[7]);
}

// ---------------------------------------------------------------------------
// conv1 weight preconvert
// ---------------------------------------------------------------------------
__global__ void k_wconv1(const float* __restrict__ w) {
    const int tap = blockIdx.x;
    const int tid = threadIdx.x;
    const int lane = (tid >> 2) & 31, nt = tid & 3;
    const int oc = nt * 8 + (lane >> 2);
    const int cb = 2 * (lane & 3);
    const int slots[4] = {cb, cb + 1, cb + 8, cb + 9};
    ushort4 hrec;
    unsigned short* hp = (unsigned short*)&hrec;
#pragma unroll
    for (int j = 0; j < 4; j++) {
        float v = 0.f;
        int slot = slots[j];
        if (oc < 25 && slot < 7) v = w[oc * 343 + slot * 49 + tap];
        hp[j] = hbits(v);
    }
    size_t rec = (((size_t)(tap * 2 + (nt >> 1)) * 32) + lane) * 2 + (nt & 1);
    ((ushort4*)g_wb1)[rec] = hrec;
}

// ---------------------------------------------------------------------------
// conv1 + bias + square via mma.sync fp16 (K=16). grid (4,16,16), 256 thr.
// ---------------------------------------------------------------------------
#define CONV1_SMEM 25408
__global__ __launch_bounds__(256) void k_conv1t(const float* __restrict__ bias) {
    extern __shared__ __align__(128) char smem[];
    uint4* sA = (uint4*)smem;
    uint4* sW = (uint4*)(smem + 10944);
    float* sBias = (float*)(smem + 25280);

    const int n = blockIdx.z >> 3, d = blockIdx.z & 7;
    const int x0 = blockIdx.x * 32, y0 = blockIdx.y * 8;
    const int tid = threadIdx.x, warp = tid >> 5, lane = tid & 31;

    const uint4* __restrict__ ga = g_zr + (size_t)(n * 8 + d) * XPX * 2;
    const uint4* __restrict__ gw = g_wb1;

    if (tid < 25) sBias[tid] = bias[tid];

    float acc[2][4][4];
#pragma unroll
    for (int h = 0; h < 2; h++)
#pragma unroll
        for (int nt = 0; nt < 4; nt++)
#pragma unroll
            for (int j = 0; j < 4; j++) acc[h][nt][j] = 0.f;

    const int lm = lane & 15, lk = lane >> 4;
    const unsigned aB = s2u(sA);

    for (int i = tid; i < 8 * 76; i += 256) {
        int r = i / 76, j = i % 76;
        int px = j >> 1, part = j & 1;
        int rec = r * 38 + px;
        int pos = (part + (rec >> 2)) & 1;
        cpa16(sA + rec * 2 + pos, ga + ((size_t)(y0 + r) * XP + x0 + px) * 2 + part);
    }
    for (int i = tid; i < 448; i += 256) cpa16(sW + i, gw + i);
    CP_COMMIT();

    for (int ky = 0; ky < 7; ky++) {
        CP_WAIT0();
        __syncthreads();
        if (ky < 6) {
            const int rel = ky + 8, slot = rel % 9;
            for (int i = tid; i < 76; i += 256) {
                int px = i >> 1, part = i & 1;
                int rec = slot * 38 + px;
                int pos = (part + (rec >> 2)) & 1;
                cpa16(sA + rec * 2 + pos, ga + ((size_t)(y0 + rel) * XP + x0 + px) * 2 + part);
            }
            uint4* wd = sW + ((ky + 1) & 1) * 448;
            for (int i = tid; i < 448; i += 256)
                cpa16(wd + i, gw + (ky + 1) * 448 + i);
            CP_COMMIT();
        }

        const uint4* sWb = sW + (ky & 1) * 448;
        const int rs = ((warp + ky) % 9) * 38;
#pragma unroll 1
        for (int kx = 0; kx < 7; kx++) {
            const int rec0 = rs + lm + kx, rec1 = rec0 + 16;
            unsigned a0 = aB + rec0 * 32 + (((lk + (rec0 >> 2)) & 1) << 4);
            unsigned a1 = aB + rec1 * 32 + (((lk + (rec1 >> 2)) & 1) << 4);
            unsigned f0[4], f1[4];
            ldm4(f0, a0);
            ldm4(f1, a1);
            const int wi = kx * 64 + lane;
            uint4 h01 = sWb[wi], h23 = sWb[wi + 32];
            mma16816(acc[0][0], f0, h01.x, h01.y);
            mma16816(acc[0][1], f0, h01.z, h01.w);
            mma16816(acc[0][2], f0, h23.x, h23.y);
            mma16816(acc[0][3], f0, h23.z, h23.w);
            mma16816(acc[1][0], f1, h01.x, h01.y);
            mma16816(acc[1][1], f1, h01.z, h01.w);
            mma16816(acc[1][2], f1, h23.x, h23.y);
            mma16816(acc[1][3], f1, h23.z, h23.w);
        }
    }

    const int y = y0 + warp;
#pragma unroll
    for (int h = 0; h < 2; h++) {
#pragma unroll
        for (int nt = 0; nt < 4; nt++) {
            int oc = nt * 8 + (lane & 3) * 2;
            int xb = x0 + h * 16 + (lane >> 2);
            if (oc < 25) {
                float b = sBias[oc];
                size_t ob = (size_t)((d * 2 + n) * 25 + oc) * HW + y * 128;
                float v0 = acc[h][nt][0] + b;
                float v2 = acc[h][nt][2] + b;
                g_y[ob + xb]     = v0 * v0;
                g_y[ob + xb + 8] = v2 * v2;
            }
            if (oc + 1 < 25) {
                float b = sBias[oc + 1];
                size_t ob = (size_t)((d * 2 + n) * 25 + oc + 1) * HW + y * 128;
                float v1 = acc[h][nt][1] + b;
                float v3 = acc[h][nt][3] + b;
                g_y[ob + xb]     = v1 * v1;
                g_y[ob + xb + 8] = v3 * v3;
            }
        }
    }
}

// ---------------------------------------------------------------------------
// conv15 weight preconvert
// ---------------------------------------------------------------------------
__global__ void k_wconv(const float* __restrict__ w_inh, const float* __restrict__ w_exc) {
    const int tap = blockIdx.x, pair = blockIdx.y;
    const float* w = pair ? w_exc : w_inh;
    const int tid = threadIdx.x;
    const int s = tid >> 7, lane = (tid >> 2) & 31, nt = tid & 3;
    const int oc = nt * 8 + (lane >> 2);
    const int cb = s * 16 + 2 * (lane & 3);
    const int cis[4] = {cb, cb + 1, cb + 8, cb + 9};
    ushort4 hrec;
    unsigned short* hp = (unsigned short*)&hrec;
#pragma unroll
    for (int j = 0; j < 4; j++) {
        float v = 0.f;
        int ci = cis[j];
        if (oc < 25 && ci < 25) v = w[(oc * 25 + ci) * 225 + tap];
        hp[j] = hbits(v);
    }
    size_t rec = (((size_t)(tap * 2 + s) * 2 + (nt >> 1)) * 32 + lane) * 2 + (nt & 1);
    ((ushort4*)g_wb[pair])[rec] = hrec;
}

// ---------------------------------------------------------------------------
// conv15 via mma.sync fp16, cp.async pipelined. grid (4,16,2), 256 thr.
// ---------------------------------------------------------------------------
#define CONV15_SMEM 87936
__global__ __launch_bounds__(256) void k_conv15(int phase) {
    extern __shared__ __align__(128) char smem[];
    uint4* sA = (uint4*)smem;
    uint4* sW = (uint4*)(smem + 26496);

    const int n = blockIdx.z;
    const int x0 = blockIdx.x * 32, y0 = blockIdx.y * 8;
    const int tid = threadIdx.x, warp = tid >> 5, lane = tid & 31;

    const uint4* __restrict__ ga = (phase ? g_ns : g_hg) + (size_t)n * APX * 4;
    const uint4* __restrict__ gw = g_wb[phase];
    float* __restrict__ out = phase ? g_c2 : g_c1;

    float acc[2][4][4];
#pragma unroll
    for (int h = 0; h < 2; h++)
#pragma unroll
        for (int nt = 0; nt < 4; nt++)
#pragma unroll
            for (int j = 0; j < 4; j++) acc[h][nt][j] = 0.f;

    const int lm = lane & 15, lk = lane >> 4;
    const unsigned aB = s2u(sA);

    for (int i = tid; i < 8 * 184; i += 256) {
        int r = i / 184, j = i % 184;
        int px = j >> 2, part = j & 3;
        int rec = r * 46 + px;
        int pos = (part + (rec >> 1)) & 3;
        cpa16(sA + rec * 4 + pos, ga + ((size_t)(y0 + r) * APITCH + x0 + px) * 4 + part);
    }
    for (int i = tid; i < 1920; i += 256) cpa16(sW + i, gw + i);
    CP_COMMIT();

    for (int ky = 0; ky < 15; ky++) {
        CP_WAIT0();
        __syncthreads();

        if (ky < 14) {
            const int rel = ky + 8, slot = rel % 9;
            for (int i = tid; i < 184; i += 256) {
                int px = i >> 2, part = i & 3;
                int rec = slot * 46 + px;
                int pos = (part + (rec >> 1)) & 3;
                cpa16(sA + rec * 4 + pos, ga + ((size_t)(y0 + rel) * APITCH + x0 + px) * 4 + part);
            }
            uint4* wd = sW + ((ky + 1) & 1) * 1920;
            for (int i = tid; i < 1920; i += 256)
                cpa16(wd + i, gw + (ky + 1) * 1920 + i);
            CP_COMMIT();
        }

        const uint4* sWb = sW + (ky & 1) * 1920;
        const int rs = ((warp + ky) % 9) * 46;
#pragma unroll 3
        for (int kx = 0; kx < 15; kx++) {
            const int rec0 = rs + lm + kx, rec1 = rec0 + 16;
#pragma unroll
            for (int s = 0; s < 2; s++) {
                const int qbase = s * 2 + lk;
                unsigned a0 = aB + rec0 * 64 + (((qbase + (rec0 >> 1)) & 3) << 4);
                unsigned a1 = aB + rec1 * 64 + (((qbase + (rec1 >> 1)) & 3) << 4);
                unsigned f0[4], f1[4];
                ldm4(f0, a0);
                ldm4(f1, a1);
                const int wi = (kx * 2 + s) * 64 + lane;
                uint4 h01 = sWb[wi], h23 = sWb[wi + 32];
                mma16816(acc[0][0], f0, h01.x, h01.y);
                mma16816(acc[0][1], f0, h01.z, h01.w);
                mma16816(acc[0][2], f0, h23.x, h23.y);
                mma16816(acc[0][3], f0, h23.z, h23.w);
                mma16816(acc[1][0], f1, h01.x, h01.y);
                mma16816(acc[1][1], f1, h01.z, h01.w);
                mma16816(acc[1][2], f1, h23.x, h23.y);
                mma16816(acc[1][3], f1, h23.z, h23.w);
            }
        }
    }

    const int y = y0 + warp;
#pragma unroll
    for (int h = 0; h < 2; h++) {
#pragma unroll
        for (int nt = 0; nt < 4; nt++) {
            int oc = nt * 8 + (lane & 3) * 2;
            int xb = x0 + h * 16 + (lane >> 2);
            if (oc < 25) {
                size_t ob = (size_t)(n * 25 + oc) * HW + y * 128;
                out[ob + xb]     = acc[h][nt][0];
                out[ob + xb + 8] = acc[h][nt][2];
            }
            if (oc + 1 < 25) {
                size_t ob = (size_t)(n * 25 + oc + 1) * HW + y * 128;
                out[ob + xb]     = acc[h][nt][1];
                out[ob + xb + 8] = acc[h][nt][3];
            }
        }
    }

    __syncthreads();
    float* sred = (float*)smem;
#pragma unroll
    for (int nt = 0; nt < 4; nt++) {
        float s0 = 0.f, q0 = 0.f, s1 = 0.f, q1 = 0.f;
#pragma unroll
        for (int h = 0; h < 2; h++) {
            float v;
            v = acc[h][nt][0]; s0 += v; q0 = fmaf(v, v, q0);
            v = acc[h][nt][2]; s0 += v; q0 = fmaf(v, v, q0);
            v = acc[h][nt][1]; s1 += v; q1 = fmaf(v, v, q1);
            v = acc[h][nt][3]; s1 += v; q1 = fmaf(v, v, q1);
        }
#pragma unroll
        for (int m = 4; m <= 16; m <<= 1) {
            s0 += __shfl_xor_sync(~0u, s0, m);
            q0 += __shfl_xor_sync(~0u, q0, m);
            s1 += __shfl_xor_sync(~0u, s1, m);
            q1 += __shfl_xor_sync(~0u, q1, m);
        }
        if (lane < 4) {
            int base = ((warp * 4 + nt) * 4 + lane) * 4;
            sred[base + 0] = s0;
            sred[base + 1] = q0;
            sred[base + 2] = s1;
            sred[base + 3] = q1;
        }
    }
    __syncthreads();
    if (tid < 25) {
        int nt = tid >> 3, rem = tid & 7, q = rem >> 1, par = rem & 1;
        float s = 0.f, qq = 0.f;
#pragma unroll
        for (int w = 0; w < 8; w++) {
            int base = ((w * 4 + nt) * 4 + q) * 4 + par * 2;
            s  += sred[base];
            qq += sred[base + 1];
        }
        int cta = (blockIdx.z * 16 + blockIdx.y) * 4 + blockIdx.x;
        g_cpart[phase][tid][cta][0] = s;
        g_cpart[phase][tid][cta][1] = qq;
    }
}

// ---------------------------------------------------------------------------
// BN partial statistics for final h
// ---------------------------------------------------------------------------
__global__ void k_bnpart(int phase) {
    const float* src = g_h;
    const int c = blockIdx.x, sl = blockIdx.y;
    float s = 0.f, q = 0.f;
#pragma unroll
    for (int k = 0; k < 16; k++) {
        int j = sl * 4096 + k * 256 + threadIdx.x;
        int nn = j >> 14, p = j & 16383;
        float v = src[(size_t)(nn * 25 + c) * HW + p];
        s += v;
        q = fmaf(v, v, q);
    }
    __shared__ float ss[256], sq[256];
    ss[threadIdx.x] = s; sq[threadIdx.x] = q;
    __syncthreads();
    for (int o = 128; o > 0; o >>= 1) {
        if (threadIdx.x < o) {
            ss[threadIdx.x] += ss[threadIdx.x + o];
            sq[threadIdx.x] += sq[threadIdx.x + o];
        }
        __syncthreads();
    }
    if (threadIdx.x == 0) {
        g_bpart[phase][c][sl][0] = ss[0];
        g_bpart[phase][c][sl][1] = sq[0];
    }
}

// ---------------------------------------------------------------------------
// ns1
// ---------------------------------------------------------------------------
__global__ void k_ns1(int t, const float* __restrict__ alpha, const float* __restrict__ mu,
                      const float* __restrict__ bn1w, const float* __restrict__ bn1b) {
    __shared__ float smn[25], srs[25], sa[25], smu[25], s1w[25], s1b[25];
    if (threadIdx.x < 25) {
        int c = threadIdx.x;
        bn_finalize_c(0, c, &smn[c], &srs[c]);
        sa[c] = alpha[c]; smu[c] = mu[c]; s1w[c] = bn1w[c]; s1b[c] = bn1b[c];
    }
    __syncthreads();

    const int gid = blockIdx.x * 256 + threadIdx.x;
    const int n = gid >> 14, p = gid & 16383;
    const int y = p >> 7, x = p & 127;

    unsigned rh[16];
#pragma unroll
    for (int i = 0; i < 16; i++) rh[i] = 0u;

#pragma unroll
    for (int c = 0; c < 25; c++) {
        size_t a = (size_t)(n * 25 + c) * HW + p;
        float c1 = (g_c1[a] - smn[c]) * srs[c] * s1w[c] + s1b[c];
        float h = g_h[a];
        float yv = g_y[(size_t)t * (2 * 25 * HW) + a];
        float ns = softplusf(yv - softplusf(c1 * fmaf(sa[c], h, smu[c])));
        g_ns1[a] = ns;
        rh[c >> 1] |= (unsigned)hbits(ns) << ((c & 1) * 16);
    }
    size_t ab = ((size_t)n * APX + (y + 7) * APITCH + (x + 7)) * 4;
#pragma unroll
    for (int j = 0; j < 4; j++)
        g_ns[ab + j] = make_uint4(rh[4*j], rh[4*j+1], rh[4*j+2], rh[4*j+3]);
}

// ---------------------------------------------------------------------------
// h update, fused with NEXT step's g1 gate
// ---------------------------------------------------------------------------
__global__ void k_hnew(const float* __restrict__ u2w, const float* __restrict__ u2b,
                       const float* __restrict__ kappa, const float* __restrict__ gammap,
                       const float* __restrict__ wmix,
                       const float* __restrict__ bn3w, const float* __restrict__ bn3b,
                       const float* __restrict__ u1w, const float* __restrict__ u1b) {
    __shared__ float sw2[625], sw1[625];
    __shared__ float sb[25], sk[25], sg[25], sm_[25], s3w[25], s3b[25], s1b[25];
    __shared__ float smn[25], srs[25];
    for (int t = threadIdx.x; t < 625; t += 256) { sw2[t] = u2w[t]; sw1[t] = u1w[t]; }
    if (threadIdx.x < 25) {
        int c = threadIdx.x;
        sb[c]  = u2b[c];
        sk[c]  = kappa[c];
        sg[c]  = gammap[c];
        sm_[c] = wmix[c];
        s3w[c] = bn3w[c];
        s3b[c] = bn3b[c];
        s1b[c] = u1b[c];
        bn_finalize_c(1, c, &smn[c], &srs[c]);
    }
    __syncthreads();

    const int gid = blockIdx.x * 256 + threadIdx.x;
    const int n = gid >> 14, p = gid & 16383;
    const int y = p >> 7, x = p & 127;
    float nv[25], hn[25];
#pragma unroll
    for (int i = 0; i < 25; i++) nv[i] = g_ns1[(size_t)(n * 25 + i) * HW + p];
#pragma unroll
    for (int c = 0; c < 25; c++) {
        float dot = sb[c];
#pragma unroll
        for (int i = 0; i < 25; i++) dot = fmaf(sw2[c * 25 + i], nv[i], dot);
        float g2 = sigmoidf_(dot);
        size_t a = (size_t)(n * 25 + c) * HW + p;
        float c2n = (g_c2[a] - smn[c]) * srs[c] * s3w[c] + s3b[c];
        float h2 = softplusf(sk[c] * nv[c] + sg[c] * c2n + sm_[c] * nv[c] * c2n);
        float hold = g_h[a];
        float hnw = softplusf((1.f - g2) * hold + g2 * h2);
        hn[c] = hnw;
        g_h[a] = hnw;
    }
    unsigned rh[16];
#pragma unroll
    for (int i = 0; i < 16; i++) rh[i] = 0u;
#pragma unroll
    for (int c = 0; c < 25; c++) {
        float dot = s1b[c];
#pragma unroll
        for (int i = 0; i < 25; i++) dot = fmaf(sw1[c * 25 + i], hn[i], dot);
        float v = hn[c] * sigmoidf_(dot);
        rh[c >> 1] |= (unsigned)hbits(v) << ((c & 1) * 16);
    }
    size_t ab = ((size_t)n * APX + (y + 7) * APITCH + (x + 7)) * 4;
#pragma unroll
    for (int j = 0; j < 4; j++)
        g_hg[ab + j] = make_uint4(rh[4*j], rh[4*j+1], rh[4*j+2], rh[4*j+3]);
}

// ---------------------------------------------------------------------------
// Epilogue
// ---------------------------------------------------------------------------
__global__ void k_pool(const float* __restrict__ bnow, const float* __restrict__ bnob,
                       const float* __restrict__ fcw) {
    __shared__ float smn[25], srs[25];
    if (threadIdx.x < 25) bn_finalize(2, threadIdx.x, &smn[threadIdx.x], &srs[threadIdx.x]);
    __syncthreads();
    const int gid = blockIdx.x * 256 + threadIdx.x;
    float p0 = 0.f, p1 = 0.f;
    for (int m = gid; m < 204800; m += 32768) {
        int n = m / 102400;
        int r = m % 102400;
        int c = r >> 12;
        int q = r & 4095;
        int i = q >> 6, j = q & 63;
        size_t base = (size_t)(n * 25 + c) * HW + (size_t)(i * 2) * 128 + j * 2;
        float s4 = g_h[base] + g_h[base + 1] + g_h[base + 128] + g_h[base + 129];
        float val = (0.25f * s4 - smn[c]) * srs[c] * bnow[c] + bnob[c];
        p0 = fmaf(val, fcw[m], p0);
        p1 = fmaf(val, fcw[204800 + m], p1);
    }
    __shared__ float s0[256], s1[256];
    s0[threadIdx.x] = p0; s1[threadIdx.x] = p1;
    __syncthreads();
    for (int o = 128; o > 0; o >>= 1) {
        if (threadIdx.x < o) {
            s0[threadIdx.x] += s0[threadIdx.x + o];
            s1[threadIdx.x] += s1[threadIdx.x + o];
        }
        __syncthreads();
    }
    if (threadIdx.x == 0) {
        g_part[blockIdx.x * 2]     = s0[0];
        g_part[blockIdx.x * 2 + 1] = s1[0];
    }
}

__global__ void k_final(const float* __restrict__ fcb, float* __restrict__ out) {
    __shared__ float s0[128], s1[128];
    s0[threadIdx.x] = g_part[threadIdx.x * 2];
    s1[threadIdx.x] = g_part[threadIdx.x * 2 + 1];
    __syncthreads();
    for (int o = 64; o > 0; o >>= 1) {
        if (threadIdx.x < o) {
            s0[threadIdx.x] += s0[threadIdx.x + o];
            s1[threadIdx.x] += s1[threadIdx.x + o];
        }
        __syncthreads();
    }
    if (threadIdx.x == 0) {
        out[0] = sigmoidf_(s0[0] + fcb[0]);
        out[1] = sigmoidf_(s1[0] + fcb[1]);
    }
}

// ---------------------------------------------------------------------------
extern "C" void kernel_launch(void* const* d_in, const int* in_sizes, int n_in,
                              void* d_out, int out_size) {
    const float* x        = (const float*)d_in[0];
    const float* conv00_w = (const float*)d_in[1];
    const float* conv0_w  = (const float*)d_in[2];
    const float* conv1_w  = (const float*)d_in[3];
    const float* conv1_b  = (const float*)d_in[4];
    const float* u1_w     = (const float*)d_in[5];
    const float* u1_b     = (const float*)d_in[6];
    const float* u2_w     = (const float*)d_in[7];
    const float* u2_b     = (const float*)d_in[8];
    const float* w_inh    = (const float*)d_in[9];
    const float* w_exc    = (const float*)d_in[10];
    const float* alpha    = (const float*)d_in[11];
    const float* mu       = (const float*)d_in[12];
    const float* gamma_p  = (const float*)d_in[13];
    const float* kappa    = (const float*)d_in[14];
    const float* w_mix    = (const float*)d_in[15];
    const float* bn1_w    = (const float*)d_in[16];
    const float* bn1_b    = (const float*)d_in[17];
    const float* bn3_w    = (const float*)d_in[18];
    const float* bn3_b    = (const float*)d_in[19];
    const float* bn_out_w = (const float*)d_in[20];
    const float* bn_out_b = (const float*)d_in[21];
    const float* fc4_w    = (const float*)d_in[22];
    const float* fc4_b    = (const float*)d_in[23];
    float* out = (float*)d_out;

    cudaFuncSetAttribute(k_conv15, cudaFuncAttributeMaxDynamicSharedMemorySize, CONV15_SMEM);
    cudaFuncSetAttribute(k_conv00t, cudaFuncAttributeMaxDynamicSharedMemorySize, CONV00_SMEM);

    // ---- 3D conv front-end (4th launch = k_conv00t -> PROFILED) ----
    k_prep<<<4624, 256>>>(x);          // records + zero h/hg/ns/or-halo
    k_wfront<<<dim3(49, 9), 256>>>(conv00_w, conv0_w);
    k_wconv1<<<49, 128>>>(conv1_w);
    k_conv00t<<<dim3(4, 16, 16), 256, CONV00_SMEM>>>();   // PROFILED
    k_conv0t<<<dim3(4, 16, 4), 256, CONV0_SMEM>>>();
    k_zrec<<<1124, 256>>>();
    k_conv1t<<<dim3(4, 16, 16), 256, CONV1_SMEM>>>(conv1_b);

    // ---- recurrent prep ----
    k_wconv<<<dim3(225, 2), 256>>>(w_inh, w_exc);
    // t=0: h = 0 -> hg records are all zero; g_hg already zeroed by k_prep.

    // ---- recurrent scan, T = 8 (g1 fused into k_hnew) ----
    for (int t = 0; t < 8; t++) {
        k_conv15<<<dim3(4, 16, 2), 256, CONV15_SMEM>>>(0);
        k_ns1<<<128, 256>>>(t, alpha, mu, bn1_w, bn1_b);
        k_conv15<<<dim3(4, 16, 2), 256, CONV15_SMEM>>>(1);
        k_hnew<<<128, 256>>>(u2_w, u2_b, kappa, gamma_p, w_mix, bn3_w, bn3_b, u1_w, u1_b);
    }

    // ---- epilogue ----
    k_bnpart<<<dim3(25, 8), 256>>>(2);
    k_pool<<<128, 256>>>(bn_out_w, bn_out_b, fc4_w);
    k_final<<<1, 128>>>(fc4_b, out);
}